// round 1
// baseline (speedup 1.0000x reference)
#include <cuda_runtime.h>
#include <math.h>

#define IMG 192
#define HWC (192*192)           // 36864
#define NWSIDE 24
#define NWPB 576                // windows per batch
#define NWTOT 1152              // total windows (B=2)

// ---------------- scratch (device globals; no allocation allowed) ----------------
static __device__ float g_a512[(size_t)2*512*HWC];          // 512-ch intermediate
static __device__ float g_g256[(size_t)2*256*HWC];          // gated 256-ch
static __device__ float g_x1  [(size_t)2*128*HWC];          // after conv block
static __device__ float g_x2  [(size_t)2*128*HWC];          // after attention
static __device__ float g_qkv [(size_t)NWTOT*3*4*64*32];    // (win,3,head,T,hd)
static __device__ float g_ao  [(size_t)NWTOT*128*64];       // (win, c, T)

__device__ __forceinline__ float gelu_erf(float v) {
    return 0.5f * v * (1.0f + erff(v * 0.70710678118654752f));
}

// =====================================================================
// Generic 1x1-conv GEMM: out[b,o,p] = sum_c W[o,c]*in[b,c,p] + bias[o]
// tile: 64 pixels x 64 out-channels, 4x4 register micro-tile, 256 threads.
// RMS: apply RMSNorm(s,b) over channels to the input tile before GEMM.
// RES: out = res + (*scale_ptr) * (gemm + bias)
// =====================================================================
template<int K, int OC, bool RMS, bool RES>
__global__ void __launch_bounds__(256)
gemm1x1_kernel(const float* __restrict__ in, const float* __restrict__ W,
               const float* __restrict__ bias,
               const float* __restrict__ rs, const float* __restrict__ rb,
               const float* __restrict__ res, const float* __restrict__ scale_ptr,
               float* __restrict__ out)
{
    extern __shared__ float smem[];
    float* xs = smem;            // [K][64]
    float* wt = smem + K * 64;   // [128][64]
    const int tid = threadIdx.x;
    int gp = blockIdx.x * 64;
    const int b  = gp / HWC;
    const int p0 = gp - b * HWC;
    const float* inb = in + (size_t)b * K * HWC + p0;

    for (int i = tid; i < K * 64; i += 256) {
        int c = i >> 6, p = i & 63;
        xs[i] = inb[(size_t)c * HWC + p];
    }
    __syncthreads();

    if (RMS) {
        const int pix = tid & 63, part = tid >> 6;
        float ss = 0.f;
        #pragma unroll 8
        for (int c = part * (K / 4); c < (part + 1) * (K / 4); ++c) {
            float v = xs[c * 64 + pix];
            ss += v * v;
        }
        wt[part * 64 + pix] = ss;
        __syncthreads();
        if (tid < 64) {
            float tot = wt[tid] + wt[64 + tid] + wt[128 + tid] + wt[192 + tid];
            wt[256 + tid] = rsqrtf(tot * (1.0f / K) + 1e-6f);
        }
        __syncthreads();
        for (int i = tid; i < K * 64; i += 256) {
            int c = i >> 6, p = i & 63;
            xs[i] = rs[c] * xs[i] * wt[256 + p] + rb[c];
        }
    }

    float scl = 1.0f;
    if (RES) scl = *scale_ptr;
    const int px4 = tid & 15, oc4 = tid >> 4;

    for (int ot = 0; ot < OC / 64; ++ot) {
        float acc[4][4];
        #pragma unroll
        for (int a = 0; a < 4; a++)
            #pragma unroll
            for (int c = 0; c < 4; c++) acc[a][c] = 0.f;

        #pragma unroll
        for (int kt = 0; kt < K / 128; ++kt) {
            __syncthreads();
            {   // load weight tile [128 c][64 oc] (oc contiguous for float4 reads)
                int ol = tid >> 2, cpart = tid & 3;
                const float* wrow = W + (size_t)(ot * 64 + ol) * K + kt * 128 + cpart * 32;
                #pragma unroll
                for (int j = 0; j < 32; j += 4) {
                    float4 wv = *(const float4*)(wrow + j);
                    int c = cpart * 32 + j;
                    wt[(c + 0) * 64 + ol] = wv.x;
                    wt[(c + 1) * 64 + ol] = wv.y;
                    wt[(c + 2) * 64 + ol] = wv.z;
                    wt[(c + 3) * 64 + ol] = wv.w;
                }
            }
            __syncthreads();
            const float* xk = xs + kt * 128 * 64;
            #pragma unroll 8
            for (int c = 0; c < 128; ++c) {
                float4 xv = *(const float4*)(xk + c * 64 + px4 * 4);
                float4 wv = *(const float4*)(wt + c * 64 + oc4 * 4);
                acc[0][0] = fmaf(wv.x, xv.x, acc[0][0]);
                acc[0][1] = fmaf(wv.x, xv.y, acc[0][1]);
                acc[0][2] = fmaf(wv.x, xv.z, acc[0][2]);
                acc[0][3] = fmaf(wv.x, xv.w, acc[0][3]);
                acc[1][0] = fmaf(wv.y, xv.x, acc[1][0]);
                acc[1][1] = fmaf(wv.y, xv.y, acc[1][1]);
                acc[1][2] = fmaf(wv.y, xv.z, acc[1][2]);
                acc[1][3] = fmaf(wv.y, xv.w, acc[1][3]);
                acc[2][0] = fmaf(wv.z, xv.x, acc[2][0]);
                acc[2][1] = fmaf(wv.z, xv.y, acc[2][1]);
                acc[2][2] = fmaf(wv.z, xv.z, acc[2][2]);
                acc[2][3] = fmaf(wv.z, xv.w, acc[2][3]);
                acc[3][0] = fmaf(wv.w, xv.x, acc[3][0]);
                acc[3][1] = fmaf(wv.w, xv.y, acc[3][1]);
                acc[3][2] = fmaf(wv.w, xv.z, acc[3][2]);
                acc[3][3] = fmaf(wv.w, xv.w, acc[3][3]);
            }
        }
        #pragma unroll
        for (int io = 0; io < 4; ++io) {
            int o = ot * 64 + oc4 * 4 + io;
            float bv = bias[o];
            size_t oidx = (size_t)b * OC * HWC + (size_t)o * HWC + p0 + px4 * 4;
            float4 r;
            r.x = acc[io][0] + bv; r.y = acc[io][1] + bv;
            r.z = acc[io][2] + bv; r.w = acc[io][3] + bv;
            if (RES) {
                float4 rr = *(const float4*)(res + oidx);
                r.x = rr.x + scl * r.x; r.y = rr.y + scl * r.y;
                r.z = rr.z + scl * r.z; r.w = rr.w + scl * r.w;
            }
            *(float4*)(out + oidx) = r;
        }
    }
}

// =====================================================================
// Depthwise 3x3 + bias + gated GELU.  in: g_a512 (B,512,H,W)
// out[b,c,p] = dw(a[c]) * gelu(dw(a[c+256])) for c in [0,256)
// =====================================================================
__global__ void __launch_bounds__(256)
dwgate_kernel(const float* __restrict__ a, const float* __restrict__ dw,
              const float* __restrict__ db, float* __restrict__ out)
{
    __shared__ float su[18 * 18], sv[18 * 18];
    int blk  = blockIdx.x;
    int tile = blk % 144;
    int cp   = (blk / 144) & 255;
    int b    = blk / (144 * 256);
    int ty = (tile / 12) * 16, tx = (tile % 12) * 16;
    const float* ua = a + ((size_t)b * 512 + cp) * HWC;
    const float* va = a + ((size_t)b * 512 + cp + 256) * HWC;

    for (int i = threadIdx.x; i < 324; i += 256) {
        int ly = i / 18, lx = i - ly * 18;
        int gy = ty + ly - 1, gx = tx + lx - 1;
        bool ok = ((unsigned)gy < (unsigned)IMG) && ((unsigned)gx < (unsigned)IMG);
        int gi = gy * IMG + gx;
        su[i] = ok ? ua[gi] : 0.f;
        sv[i] = ok ? va[gi] : 0.f;
    }
    __syncthreads();
    int y = threadIdx.x >> 4, x = threadIdx.x & 15;
    float u = db[cp], v = db[cp + 256];
    #pragma unroll
    for (int i = 0; i < 3; ++i)
        #pragma unroll
        for (int j = 0; j < 3; ++j) {
            float wu = dw[cp * 9 + i * 3 + j];
            float wv = dw[(cp + 256) * 9 + i * 3 + j];
            u = fmaf(su[(y + i) * 18 + x + j], wu, u);
            v = fmaf(sv[(y + i) * 18 + x + j], wv, v);
        }
    out[((size_t)b * 256 + cp) * HWC + (ty + y) * IMG + tx + x] = u * gelu_erf(v);
}

// =====================================================================
// Elementwise gate for FFN: g[b,c,p] = u * gelu(v)
// =====================================================================
__global__ void gate_kernel(const float* __restrict__ a, float* __restrict__ out)
{
    size_t idx = (size_t)blockIdx.x * blockDim.x + threadIdx.x;
    if (idx >= (size_t)2 * 256 * HWC) return;
    size_t b = idx / ((size_t)256 * HWC);
    size_t rem = idx - b * 256 * HWC;
    size_t c = rem / HWC, p = rem - c * HWC;
    float u = a[(b * 512 + c) * HWC + p];
    float v = a[(b * 512 + c + 256) * HWC + p];
    out[idx] = u * gelu_erf(v);
}

// =====================================================================
// QKV: block = one 8x8 window. Fuses roll(-SS), RMSNorm, qkv conv,
// 1/sqrt(hd) on q, scatter to (win,3,head,T,hd).
// =====================================================================
__global__ void __launch_bounds__(256)
qkv_kernel(const float* __restrict__ x, const float* __restrict__ rs,
           const float* __restrict__ rb, const float* __restrict__ W,
           const float* __restrict__ bias, float* __restrict__ out)
{
    extern __shared__ float smem[];
    float* xs = smem;            // [128][64]
    float* wt = smem + 128 * 64; // [128][64]
    const int tid = threadIdx.x;
    int w = blockIdx.x;
    int b = w / NWPB, wrem = w - b * NWPB;
    int wy = wrem / NWSIDE, wx = wrem - wy * NWSIDE;

    for (int i = tid; i < 128 * 64; i += 256) {
        int c = i >> 6, t = i & 63;
        int r = t >> 3, cc = t & 7;
        int gh = wy * 8 + r + 4;  if (gh >= IMG) gh -= IMG;
        int gw = wx * 8 + cc + 4; if (gw >= IMG) gw -= IMG;
        xs[i] = x[(size_t)b * 128 * HWC + (size_t)c * HWC + gh * IMG + gw];
    }
    __syncthreads();
    {   // RMSNorm over 128 channels per token
        const int pix = tid & 63, part = tid >> 6;
        float ss = 0.f;
        #pragma unroll 8
        for (int c = part * 32; c < part * 32 + 32; ++c) {
            float v = xs[c * 64 + pix]; ss += v * v;
        }
        wt[part * 64 + pix] = ss;
        __syncthreads();
        if (tid < 64) {
            float tot = wt[tid] + wt[64 + tid] + wt[128 + tid] + wt[192 + tid];
            wt[256 + tid] = rsqrtf(tot * (1.0f / 128.0f) + 1e-6f);
        }
        __syncthreads();
        for (int i = tid; i < 128 * 64; i += 256) {
            int c = i >> 6, p = i & 63;
            xs[i] = rs[c] * xs[i] * wt[256 + p] + rb[c];
        }
    }

    const int px4 = tid & 15, oc4 = tid >> 4;
    for (int ot = 0; ot < 6; ++ot) {            // OC = 384
        float acc[4][4];
        #pragma unroll
        for (int a = 0; a < 4; a++)
            #pragma unroll
            for (int c = 0; c < 4; c++) acc[a][c] = 0.f;
        __syncthreads();
        {
            int ol = tid >> 2, cpart = tid & 3;
            const float* wrow = W + (size_t)(ot * 64 + ol) * 128 + cpart * 32;
            #pragma unroll
            for (int j = 0; j < 32; j += 4) {
                float4 wv = *(const float4*)(wrow + j);
                int c = cpart * 32 + j;
                wt[(c + 0) * 64 + ol] = wv.x;
                wt[(c + 1) * 64 + ol] = wv.y;
                wt[(c + 2) * 64 + ol] = wv.z;
                wt[(c + 3) * 64 + ol] = wv.w;
            }
        }
        __syncthreads();
        #pragma unroll 8
        for (int c = 0; c < 128; ++c) {
            float4 xv = *(const float4*)(xs + c * 64 + px4 * 4);
            float4 wv = *(const float4*)(wt + c * 64 + oc4 * 4);
            acc[0][0] = fmaf(wv.x, xv.x, acc[0][0]);
            acc[0][1] = fmaf(wv.x, xv.y, acc[0][1]);
            acc[0][2] = fmaf(wv.x, xv.z, acc[0][2]);
            acc[0][3] = fmaf(wv.x, xv.w, acc[0][3]);
            acc[1][0] = fmaf(wv.y, xv.x, acc[1][0]);
            acc[1][1] = fmaf(wv.y, xv.y, acc[1][1]);
            acc[1][2] = fmaf(wv.y, xv.z, acc[1][2]);
            acc[1][3] = fmaf(wv.y, xv.w, acc[1][3]);
            acc[2][0] = fmaf(wv.z, xv.x, acc[2][0]);
            acc[2][1] = fmaf(wv.z, xv.y, acc[2][1]);
            acc[2][2] = fmaf(wv.z, xv.z, acc[2][2]);
            acc[2][3] = fmaf(wv.z, xv.w, acc[2][3]);
            acc[3][0] = fmaf(wv.w, xv.x, acc[3][0]);
            acc[3][1] = fmaf(wv.w, xv.y, acc[3][1]);
            acc[3][2] = fmaf(wv.w, xv.z, acc[3][2]);
            acc[3][3] = fmaf(wv.w, xv.w, acc[3][3]);
        }
        #pragma unroll
        for (int io = 0; io < 4; ++io) {
            int o = ot * 64 + oc4 * 4 + io;
            int part = o >> 7, ch = o & 127, head = ch >> 5, d = ch & 31;
            float bv = bias[o];
            float qs = (part == 0) ? 0.17677669529663687f : 1.0f;
            size_t basep = (((size_t)(w * 3 + part)) * 4 + head) * 2048 + d;
            #pragma unroll
            for (int j = 0; j < 4; ++j) {
                int t = px4 * 4 + j;
                out[basep + (size_t)t * 32] = (acc[io][j] + bv) * qs;
            }
        }
    }
}

// =====================================================================
// Attention: block per (window, head). 64 threads, one query row each.
// RPE gathered into smem; shift-mask computed inline from region labels.
// Output transposed via padded smem into (win, c, T) channel-major.
// =====================================================================
__global__ void __launch_bounds__(64)
attn_kernel(const float* __restrict__ qkv, const float* __restrict__ rpe,
            float* __restrict__ ao)
{
    __shared__ float Ks[2048], Vs[2048], rpe_s[225], outs[64 * 33];
    __shared__ int lk[64];
    int w = blockIdx.x >> 2, head = blockIdx.x & 3;
    int tid = threadIdx.x;
    size_t qb = ((size_t)(w * 3 + 0) * 4 + head) * 2048;
    size_t kb = ((size_t)(w * 3 + 1) * 4 + head) * 2048;
    size_t vb = ((size_t)(w * 3 + 2) * 4 + head) * 2048;
    for (int i = tid; i < 2048; i += 64) { Ks[i] = qkv[kb + i]; Vs[i] = qkv[vb + i]; }
    for (int i = tid; i < 225; i += 64) rpe_s[i] = rpe[i * 4 + head];

    int wrem = w % NWPB;
    int wy = wrem / NWSIDE, wx = wrem - (wrem / NWSIDE) * NWSIDE;
    int qy = tid >> 3, qx = tid & 7;
    int gh = wy * 8 + qy, gw = wx * 8 + qx;
    int lh = gh < 184 ? 0 : (gh < 188 ? 1 : 2);
    int lw = gw < 184 ? 0 : (gw < 188 ? 1 : 2);
    int lab = lh * 3 + lw;
    lk[tid] = lab;
    __syncthreads();

    float q[32];
    #pragma unroll
    for (int d4 = 0; d4 < 8; ++d4) {
        float4 t4 = *(const float4*)(qkv + qb + (size_t)tid * 32 + d4 * 4);
        q[d4 * 4 + 0] = t4.x; q[d4 * 4 + 1] = t4.y;
        q[d4 * 4 + 2] = t4.z; q[d4 * 4 + 3] = t4.w;
    }
    float sc[64];
    float mx = -1e30f;
    #pragma unroll
    for (int kk = 0; kk < 64; ++kk) {
        const float4* kp = (const float4*)(Ks + kk * 32);
        float dot = 0.f;
        #pragma unroll
        for (int d4 = 0; d4 < 8; ++d4) {
            float4 kv = kp[d4];
            dot = fmaf(q[d4 * 4 + 0], kv.x, dot);
            dot = fmaf(q[d4 * 4 + 1], kv.y, dot);
            dot = fmaf(q[d4 * 4 + 2], kv.z, dot);
            dot = fmaf(q[d4 * 4 + 3], kv.w, dot);
        }
        int ky = kk >> 3, kx = kk & 7;
        dot += rpe_s[(qy - ky + 7) * 15 + (qx - kx + 7)];
        if (lab != lk[kk]) dot = -1e30f;
        sc[kk] = dot;
        mx = fmaxf(mx, dot);
    }
    float sum = 0.f;
    #pragma unroll
    for (int kk = 0; kk < 64; ++kk) {
        float e = __expf(sc[kk] - mx);
        sc[kk] = e; sum += e;
    }
    float inv = 1.0f / sum;
    float acc[32];
    #pragma unroll
    for (int d = 0; d < 32; ++d) acc[d] = 0.f;
    #pragma unroll
    for (int kk = 0; kk < 64; ++kk) {
        float p = sc[kk];
        const float4* vp = (const float4*)(Vs + kk * 32);
        #pragma unroll
        for (int d4 = 0; d4 < 8; ++d4) {
            float4 vv = vp[d4];
            acc[d4 * 4 + 0] = fmaf(p, vv.x, acc[d4 * 4 + 0]);
            acc[d4 * 4 + 1] = fmaf(p, vv.y, acc[d4 * 4 + 1]);
            acc[d4 * 4 + 2] = fmaf(p, vv.z, acc[d4 * 4 + 2]);
            acc[d4 * 4 + 3] = fmaf(p, vv.w, acc[d4 * 4 + 3]);
        }
    }
    #pragma unroll
    for (int d = 0; d < 32; ++d) outs[tid * 33 + d] = acc[d] * inv;
    __syncthreads();
    size_t ab = ((size_t)w << 13) + (size_t)head * 2048;  // (win, c=head*32+d, t)
    for (int i = tid; i < 2048; i += 64) {
        int d = i >> 6, t = i & 63;
        ao[ab + i] = outs[t * 33 + d];
    }
}

// =====================================================================
// Proj: block = one window. GEMM 128x128 over the window's attention
// output, fuses un-window + roll(+SS) + residual (x1 + alpha*proj).
// =====================================================================
__global__ void __launch_bounds__(256)
proj_kernel(const float* __restrict__ ao, const float* __restrict__ W,
            const float* __restrict__ bias, const float* __restrict__ x1,
            const float* __restrict__ alpha_ptr, float* __restrict__ out)
{
    extern __shared__ float smem[];
    float* xs = smem;            // [128][64]
    float* wt = smem + 128 * 64; // [128][64]
    const int tid = threadIdx.x;
    int w = blockIdx.x;
    int b = w / NWPB, wrem = w - b * NWPB;
    int wy = wrem / NWSIDE, wx = wrem - wy * NWSIDE;

    const float* aow = ao + ((size_t)w << 13);
    for (int i = tid; i < 128 * 64; i += 256) xs[i] = aow[i];
    float al = *alpha_ptr;

    const int px4 = tid & 15, oc4 = tid >> 4;
    for (int ot = 0; ot < 2; ++ot) {
        float acc[4][4];
        #pragma unroll
        for (int a = 0; a < 4; a++)
            #pragma unroll
            for (int c = 0; c < 4; c++) acc[a][c] = 0.f;
        __syncthreads();
        {
            int ol = tid >> 2, cpart = tid & 3;
            const float* wrow = W + (size_t)(ot * 64 + ol) * 128 + cpart * 32;
            #pragma unroll
            for (int j = 0; j < 32; j += 4) {
                float4 wv = *(const float4*)(wrow + j);
                int c = cpart * 32 + j;
                wt[(c + 0) * 64 + ol] = wv.x;
                wt[(c + 1) * 64 + ol] = wv.y;
                wt[(c + 2) * 64 + ol] = wv.z;
                wt[(c + 3) * 64 + ol] = wv.w;
            }
        }
        __syncthreads();
        #pragma unroll 8
        for (int c = 0; c < 128; ++c) {
            float4 xv = *(const float4*)(xs + c * 64 + px4 * 4);
            float4 wv = *(const float4*)(wt + c * 64 + oc4 * 4);
            acc[0][0] = fmaf(wv.x, xv.x, acc[0][0]);
            acc[0][1] = fmaf(wv.x, xv.y, acc[0][1]);
            acc[0][2] = fmaf(wv.x, xv.z, acc[0][2]);
            acc[0][3] = fmaf(wv.x, xv.w, acc[0][3]);
            acc[1][0] = fmaf(wv.y, xv.x, acc[1][0]);
            acc[1][1] = fmaf(wv.y, xv.y, acc[1][1]);
            acc[1][2] = fmaf(wv.y, xv.z, acc[1][2]);
            acc[1][3] = fmaf(wv.y, xv.w, acc[1][3]);
            acc[2][0] = fmaf(wv.z, xv.x, acc[2][0]);
            acc[2][1] = fmaf(wv.z, xv.y, acc[2][1]);
            acc[2][2] = fmaf(wv.z, xv.z, acc[2][2]);
            acc[2][3] = fmaf(wv.z, xv.w, acc[2][3]);
            acc[3][0] = fmaf(wv.w, xv.x, acc[3][0]);
            acc[3][1] = fmaf(wv.w, xv.y, acc[3][1]);
            acc[3][2] = fmaf(wv.w, xv.z, acc[3][2]);
            acc[3][3] = fmaf(wv.w, xv.w, acc[3][3]);
        }
        #pragma unroll
        for (int io = 0; io < 4; ++io) {
            int o = ot * 64 + oc4 * 4 + io;
            float bv = bias[o];
            #pragma unroll
            for (int j = 0; j < 4; ++j) {
                int t = px4 * 4 + j;
                int r = t >> 3, cc = t & 7;
                int fh = wy * 8 + r + 4;  if (fh >= IMG) fh -= IMG;
                int fw = wx * 8 + cc + 4; if (fw >= IMG) fw -= IMG;
                size_t idx = (size_t)b * 128 * HWC + (size_t)o * HWC + fh * IMG + fw;
                out[idx] = x1[idx] + al * (acc[io][j] + bv);
            }
        }
    }
}

// =====================================================================
extern "C" void kernel_launch(void* const* d_in, const int* in_sizes, int n_in,
                              void* d_out, int out_size)
{
    const float* x      = (const float*)d_in[0];
    const float* cg_s   = (const float*)d_in[1];
    const float* cg_b   = (const float*)d_in[2];
    const float* pw1_w  = (const float*)d_in[3];
    const float* pw1_b  = (const float*)d_in[4];
    const float* dw_w   = (const float*)d_in[5];
    const float* dw_b   = (const float*)d_in[6];
    const float* pw2_w  = (const float*)d_in[7];
    const float* pw2_b  = (const float*)d_in[8];
    const float* beta   = (const float*)d_in[9];
    const float* at_s   = (const float*)d_in[10];
    const float* at_b   = (const float*)d_in[11];
    const float* qkv_w  = (const float*)d_in[12];
    const float* qkv_b  = (const float*)d_in[13];
    const float* rpe    = (const float*)d_in[14];
    const float* proj_w = (const float*)d_in[15];
    const float* proj_b = (const float*)d_in[16];
    const float* alpha  = (const float*)d_in[17];
    const float* ff_s   = (const float*)d_in[18];
    const float* ff_b   = (const float*)d_in[19];
    const float* fc1_w  = (const float*)d_in[20];
    const float* fc1_b  = (const float*)d_in[21];
    const float* fc2_w  = (const float*)d_in[22];
    const float* fc2_b  = (const float*)d_in[23];
    const float* gamma  = (const float*)d_in[24];
    float* out = (float*)d_out;

    float *a512, *g256, *x1, *x2, *qkvb, *aob;
    cudaGetSymbolAddress((void**)&a512, g_a512);
    cudaGetSymbolAddress((void**)&g256, g_g256);
    cudaGetSymbolAddress((void**)&x1,   g_x1);
    cudaGetSymbolAddress((void**)&x2,   g_x2);
    cudaGetSymbolAddress((void**)&qkvb, g_qkv);
    cudaGetSymbolAddress((void**)&aob,  g_ao);

    const int SM128 = (128 * 64 + 128 * 64) * 4;   // 64 KB
    const int SM256 = (256 * 64 + 128 * 64) * 4;   // 96 KB
    cudaFuncSetAttribute(gemm1x1_kernel<128, 512, true,  false>,
                         cudaFuncAttributeMaxDynamicSharedMemorySize, SM128);
    cudaFuncSetAttribute(gemm1x1_kernel<256, 128, false, true>,
                         cudaFuncAttributeMaxDynamicSharedMemorySize, SM256);
    cudaFuncSetAttribute(qkv_kernel,
                         cudaFuncAttributeMaxDynamicSharedMemorySize, SM128);
    cudaFuncSetAttribute(proj_kernel,
                         cudaFuncAttributeMaxDynamicSharedMemorySize, SM128);

    const int NPIXBLK = (2 * HWC) / 64;   // 1152

    // ---- conv gated block ----
    gemm1x1_kernel<128, 512, true, false><<<NPIXBLK, 256, SM128>>>(
        x, pw1_w, pw1_b, cg_s, cg_b, nullptr, nullptr, a512);
    dwgate_kernel<<<2 * 256 * 144, 256>>>(a512, dw_w, dw_b, g256);
    gemm1x1_kernel<256, 128, false, true><<<NPIXBLK, 256, SM256>>>(
        g256, pw2_w, pw2_b, nullptr, nullptr, x, beta, x1);

    // ---- window attention ----
    qkv_kernel<<<NWTOT, 256, SM128>>>(x1, at_s, at_b, qkv_w, qkv_b, qkvb);
    attn_kernel<<<NWTOT * 4, 64>>>(qkvb, rpe, aob);
    proj_kernel<<<NWTOT, 256, SM128>>>(aob, proj_w, proj_b, x1, alpha, x2);

    // ---- gated FFN ----
    gemm1x1_kernel<128, 512, true, false><<<NPIXBLK, 256, SM128>>>(
        x2, fc1_w, fc1_b, ff_s, ff_b, nullptr, nullptr, a512);
    {
        size_t n = (size_t)2 * 256 * HWC;
        gate_kernel<<<(int)((n + 255) / 256), 256>>>(a512, g256);
    }
    gemm1x1_kernel<256, 128, false, true><<<NPIXBLK, 256, SM256>>>(
        g256, fc2_w, fc2_b, nullptr, nullptr, x2, gamma, out);
}

// round 3
// speedup vs baseline: 1.7650x; 1.7650x over previous
#include <cuda_runtime.h>
#include <math.h>
#include <stdint.h>

#define IMG 192
#define HWC (192*192)           // 36864 pixels per batch
#define NWSIDE 24
#define NWPB 576
#define NWTOT 1152

// ---------------- scratch (device globals) ----------------
static __device__ float g_a512[(size_t)2*512*HWC];   // 512-ch intermediate / qkv (384ch)
static __device__ float g_g256[(size_t)2*256*HWC];   // gated 256-ch / attn-out 128ch
static __device__ float g_x1  [(size_t)2*128*HWC];
static __device__ float g_x2  [(size_t)2*128*HWC];

__device__ __forceinline__ float gelu_erf(float v) {
    return 0.5f * v * (1.0f + erff(v * 0.70710678118654752f));
}
__device__ __forceinline__ uint32_t to_tf32(float f) {
    uint32_t r;
    asm("cvt.rna.tf32.f32 %0, %1;" : "=r"(r) : "f"(f));
    return r;
}
__device__ __forceinline__ void mma8(float* c, const uint32_t* a, const uint32_t* b) {
    asm volatile("mma.sync.aligned.m16n8k8.row.col.f32.tf32.tf32.f32 "
        "{%0,%1,%2,%3}, {%4,%5,%6,%7}, {%8,%9}, {%0,%1,%2,%3};"
        : "+f"(c[0]), "+f"(c[1]), "+f"(c[2]), "+f"(c[3])
        : "r"(a[0]), "r"(a[1]), "r"(a[2]), "r"(a[3]), "r"(b[0]), "r"(b[1]));
}

// smem layout (floats)
#define SA 132               // A stride (132 % 32 == 4)
#define SB 136               // B stride (136 % 32 == 8)
#define AS_OFF   0
#define BS_OFF   16896       // 128*132
#define RB_OFF   34304       // + 128*136
#define BIAS_OFF 34560
#define SM_FLOATS 35072
#define SMB (SM_FLOATS * 4)  // 140288 bytes

// =====================================================================
// mma.sync tf32 GEMM: out[b,o,p] = sum_c W[o,c]*in[b,c,p] (+ epilogue)
// KT = K/128 chunks, MT = OC/128 tiles.
// RMS: rmsnorm(s,b) over channels on input (requires KT==1)
// RES: out = res + (*scale_ptr)*(acc + bias); else out = acc + bias
// =====================================================================
template<int KT, int MT, bool RMS, bool RES>
__global__ void __launch_bounds__(256)
tc_gemm(const float* __restrict__ in, const float* __restrict__ W,
        const float* __restrict__ bias,
        const float* __restrict__ rs, const float* __restrict__ rb,
        const float* __restrict__ res, const float* __restrict__ scale_ptr,
        float* __restrict__ out)
{
    extern __shared__ float sm[];
    float* As   = sm + AS_OFF;
    float* Bs   = sm + BS_OFF;
    float* rbuf = sm + RB_OFF;
    float* bs   = sm + BIAS_OFF;
    uint32_t* Au = (uint32_t*)As;
    uint32_t* Bu = (uint32_t*)Bs;

    const int tid = threadIdx.x, lane = tid & 31, wid = tid >> 5;
    const int wm = wid & 3, wn = wid >> 2;
    const int gp = blockIdx.x * 128;
    const int b  = gp / HWC;
    const int p0 = gp - b * HWC;
    const float* inb = in + (size_t)b * (KT * 128) * HWC + p0;

    for (int i = tid; i < MT * 128; i += 256) bs[i] = bias[i];

    const int arow = wm * 32 + (lane >> 2);
    const int acol = lane & 3;
    const int brow = lane & 3;
    const int bcol = wn * 64 + (lane >> 2);

    for (int mt = 0; mt < MT; ++mt) {
        float acc[2][8][4];
        #pragma unroll
        for (int mi = 0; mi < 2; ++mi)
            #pragma unroll
            for (int j = 0; j < 8; ++j)
                #pragma unroll
                for (int q = 0; q < 4; ++q) acc[mi][j][q] = 0.f;

        for (int kc = 0; kc < KT; ++kc) {
            if (mt == 0 || KT > 1) {
                __syncthreads();
                // ---- load B chunk [128 c][128 px] ----
                for (int i = tid; i < 4096; i += 256) {
                    int c = i >> 5, p4 = (i & 31) * 4;
                    float4 v = *(const float4*)(inb + (size_t)(kc * 128 + c) * HWC + p4);
                    if (!RMS) {
                        uint4 u;
                        u.x = to_tf32(v.x); u.y = to_tf32(v.y);
                        u.z = to_tf32(v.z); u.w = to_tf32(v.w);
                        *(uint4*)&Bu[c * SB + p4] = u;
                    } else {
                        *(float4*)&Bs[c * SB + p4] = v;
                    }
                }
                if (RMS) {
                    __syncthreads();
                    int p = tid & 127, half = tid >> 7;
                    float s = 0.f;
                    #pragma unroll 8
                    for (int c = half * 64; c < half * 64 + 64; ++c) {
                        float v = Bs[c * SB + p];
                        s += v * v;
                    }
                    rbuf[half * 128 + p] = s;
                    __syncthreads();
                    if (tid < 128)
                        rbuf[tid] = rsqrtf((rbuf[tid] + rbuf[128 + tid]) * (1.0f / 128.0f) + 1e-6f);
                    __syncthreads();
                    for (int i = tid; i < 16384; i += 256) {
                        int c = i >> 7, p2 = i & 127;
                        float v = rs[c] * Bs[c * SB + p2] * rbuf[p2] + rb[c];
                        Bu[c * SB + p2] = to_tf32(v);
                    }
                }
            }
            __syncthreads();
            // ---- load A chunk [128 oc][128 c] ----
            {
                const float* wt = W + (size_t)(mt * 128) * (KT * 128) + kc * 128;
                for (int i = tid; i < 4096; i += 256) {
                    int o = i >> 5, c4 = (i & 31) * 4;
                    float4 v = *(const float4*)(wt + (size_t)o * (KT * 128) + c4);
                    uint4 u;
                    u.x = to_tf32(v.x); u.y = to_tf32(v.y);
                    u.z = to_tf32(v.z); u.w = to_tf32(v.w);
                    *(uint4*)&Au[o * SA + c4] = u;
                }
            }
            __syncthreads();
            // ---- mma mainloop: 16 k-steps of 8 ----
            #pragma unroll 4
            for (int k8 = 0; k8 < 16; ++k8) {
                uint32_t bb[8][2];
                #pragma unroll
                for (int j = 0; j < 8; ++j) {
                    bb[j][0] = Bu[(k8 * 8 + brow) * SB + bcol + j * 8];
                    bb[j][1] = Bu[(k8 * 8 + brow + 4) * SB + bcol + j * 8];
                }
                #pragma unroll
                for (int mi = 0; mi < 2; ++mi) {
                    uint32_t aa[4];
                    int r0 = arow + mi * 16;
                    aa[0] = Au[r0 * SA + k8 * 8 + acol];
                    aa[1] = Au[(r0 + 8) * SA + k8 * 8 + acol];
                    aa[2] = Au[r0 * SA + k8 * 8 + acol + 4];
                    aa[3] = Au[(r0 + 8) * SA + k8 * 8 + acol + 4];
                    #pragma unroll
                    for (int j = 0; j < 8; ++j) mma8(acc[mi][j], aa, bb[j]);
                }
            }
        }

        // ---- epilogue: stage (acc + bias) into As, then coalesced write ----
        __syncthreads();
        {
            int r0 = wm * 32 + (lane >> 2);
            int c0 = wn * 64 + (lane & 3) * 2;
            #pragma unroll
            for (int mi = 0; mi < 2; ++mi) {
                int o = r0 + mi * 16;
                float bv1 = bs[mt * 128 + o];
                float bv2 = bs[mt * 128 + o + 8];
                #pragma unroll
                for (int j = 0; j < 8; ++j) {
                    float2 v01 = make_float2(acc[mi][j][0] + bv1, acc[mi][j][1] + bv1);
                    float2 v23 = make_float2(acc[mi][j][2] + bv2, acc[mi][j][3] + bv2);
                    *(float2*)&As[o * SA + c0 + j * 8]       = v01;
                    *(float2*)&As[(o + 8) * SA + c0 + j * 8] = v23;
                }
            }
        }
        __syncthreads();
        {
            float scl = RES ? *scale_ptr : 0.f;
            for (int i = tid; i < 4096; i += 256) {
                int o = i >> 5, p4 = (i & 31) * 4;
                float4 v = *(float4*)&As[o * SA + p4];
                size_t oidx = (size_t)b * (MT * 128) * HWC + (size_t)(mt * 128 + o) * HWC + p0 + p4;
                if (RES) {
                    float4 rr = *(const float4*)(res + oidx);
                    v.x = rr.x + scl * v.x; v.y = rr.y + scl * v.y;
                    v.z = rr.z + scl * v.z; v.w = rr.w + scl * v.w;
                }
                *(float4*)(out + oidx) = v;
            }
        }
    }
}

// =====================================================================
// Depthwise 3x3 + bias + gated GELU
// =====================================================================
__global__ void __launch_bounds__(256)
dwgate_kernel(const float* __restrict__ a, const float* __restrict__ dw,
              const float* __restrict__ db, float* __restrict__ out)
{
    __shared__ float su[18 * 18], sv[18 * 18];
    int blk  = blockIdx.x;
    int tile = blk % 144;
    int cp   = (blk / 144) & 255;
    int b    = blk / (144 * 256);
    int ty = (tile / 12) * 16, tx = (tile % 12) * 16;
    const float* ua = a + ((size_t)b * 512 + cp) * HWC;
    const float* va = a + ((size_t)b * 512 + cp + 256) * HWC;

    for (int i = threadIdx.x; i < 324; i += 256) {
        int ly = i / 18, lx = i - ly * 18;
        int gy = ty + ly - 1, gx = tx + lx - 1;
        bool ok = ((unsigned)gy < (unsigned)IMG) && ((unsigned)gx < (unsigned)IMG);
        int gi = gy * IMG + gx;
        su[i] = ok ? ua[gi] : 0.f;
        sv[i] = ok ? va[gi] : 0.f;
    }
    __syncthreads();
    int y = threadIdx.x >> 4, x = threadIdx.x & 15;
    float u = db[cp], v = db[cp + 256];
    #pragma unroll
    for (int i = 0; i < 3; ++i)
        #pragma unroll
        for (int j = 0; j < 3; ++j) {
            float wu = dw[cp * 9 + i * 3 + j];
            float wv = dw[(cp + 256) * 9 + i * 3 + j];
            u = fmaf(su[(y + i) * 18 + x + j], wu, u);
            v = fmaf(sv[(y + i) * 18 + x + j], wv, v);
        }
    out[((size_t)b * 256 + cp) * HWC + (ty + y) * IMG + tx + x] = u * gelu_erf(v);
}

// =====================================================================
// Elementwise gate for FFN: g[b,c,p] = u * gelu(v)
// =====================================================================
__global__ void gate_kernel(const float* __restrict__ a, float* __restrict__ out)
{
    size_t idx = (size_t)blockIdx.x * blockDim.x + threadIdx.x;
    if (idx >= (size_t)2 * 256 * HWC) return;
    size_t b = idx / ((size_t)256 * HWC);
    size_t rem = idx - b * 256 * HWC;
    size_t c = rem / HWC, p = rem - c * HWC;
    float u = a[(b * 512 + c) * HWC + p];
    float v = a[(b * 512 + c + 256) * HWC + p];
    out[idx] = u * gelu_erf(v);
}

// =====================================================================
// Attention: qkv in standard layout [b][384][p]. Gathers rolled window,
// q-scale, RPE, shift mask, softmax, AV; scatters result back to
// standard image layout [b][128][p] at the FINAL (un-rolled) positions.
// =====================================================================
__global__ void __launch_bounds__(64)
attn2_kernel(const float* __restrict__ qkv, const float* __restrict__ rpe,
             float* __restrict__ aog)
{
    __shared__ float Ks[64 * 36], Vs[64 * 36], rpe_s[225], outs[64 * 33];
    __shared__ int pix[64], lk[64];
    int w = blockIdx.x >> 2, head = blockIdx.x & 3;
    int tid = threadIdx.x;
    int b = w / NWPB, wrem = w - b * NWPB;
    int wy = wrem / NWSIDE, wx = wrem - wy * NWSIDE;
    int qy = tid >> 3, qx = tid & 7;
    {
        int gh = wy * 8 + qy + 4; if (gh >= IMG) gh -= IMG;
        int gw = wx * 8 + qx + 4; if (gw >= IMG) gw -= IMG;
        pix[tid] = gh * IMG + gw;
    }
    {
        int gh = wy * 8 + qy, gw = wx * 8 + qx;
        int lh = gh < 184 ? 0 : (gh < 188 ? 1 : 2);
        int lw = gw < 184 ? 0 : (gw < 188 ? 1 : 2);
        lk[tid] = lh * 3 + lw;
    }
    for (int i = tid; i < 225; i += 64) rpe_s[i] = rpe[i * 4 + head];
    __syncthreads();

    const float* qb = qkv + (size_t)b * 384 * HWC + (size_t)(head * 32) * HWC;
    const float* kb = qb + (size_t)128 * HWC;
    const float* vb = qb + (size_t)256 * HWC;
    int myp = pix[tid];
    float q[32];
    #pragma unroll
    for (int d = 0; d < 32; ++d) {
        q[d] = qb[(size_t)d * HWC + myp] * 0.17677669529663687f;
        Ks[tid * 36 + d] = kb[(size_t)d * HWC + myp];
        Vs[tid * 36 + d] = vb[(size_t)d * HWC + myp];
    }
    int lab = lk[tid];
    __syncthreads();

    float sc[64];
    float mx = -1e30f;
    #pragma unroll
    for (int kk = 0; kk < 64; ++kk) {
        const float4* kp = (const float4*)(Ks + kk * 36);
        float dot = 0.f;
        #pragma unroll
        for (int d4 = 0; d4 < 8; ++d4) {
            float4 kv = kp[d4];
            dot = fmaf(q[d4 * 4 + 0], kv.x, dot);
            dot = fmaf(q[d4 * 4 + 1], kv.y, dot);
            dot = fmaf(q[d4 * 4 + 2], kv.z, dot);
            dot = fmaf(q[d4 * 4 + 3], kv.w, dot);
        }
        int ky = kk >> 3, kx = kk & 7;
        dot += rpe_s[(qy - ky + 7) * 15 + (qx - kx + 7)];
        if (lab != lk[kk]) dot = -1e30f;
        sc[kk] = dot;
        mx = fmaxf(mx, dot);
    }
    float sum = 0.f;
    #pragma unroll
    for (int kk = 0; kk < 64; ++kk) {
        float e = __expf(sc[kk] - mx);
        sc[kk] = e; sum += e;
    }
    float inv = 1.0f / sum;
    float acc[32];
    #pragma unroll
    for (int d = 0; d < 32; ++d) acc[d] = 0.f;
    #pragma unroll
    for (int kk = 0; kk < 64; ++kk) {
        float p = sc[kk];
        const float4* vp = (const float4*)(Vs + kk * 36);
        #pragma unroll
        for (int d4 = 0; d4 < 8; ++d4) {
            float4 vv = vp[d4];
            acc[d4 * 4 + 0] = fmaf(p, vv.x, acc[d4 * 4 + 0]);
            acc[d4 * 4 + 1] = fmaf(p, vv.y, acc[d4 * 4 + 1]);
            acc[d4 * 4 + 2] = fmaf(p, vv.z, acc[d4 * 4 + 2]);
            acc[d4 * 4 + 3] = fmaf(p, vv.w, acc[d4 * 4 + 3]);
        }
    }
    #pragma unroll
    for (int d = 0; d < 32; ++d) outs[tid * 33 + d] = acc[d] * inv;
    __syncthreads();
    // scatter back to standard image layout at final (un-rolled) position
    size_t cb = (size_t)b * 128 * HWC + (size_t)(head * 32) * HWC;
    #pragma unroll
    for (int d = 0; d < 32; ++d)
        aog[cb + (size_t)d * HWC + myp] = outs[tid * 33 + d];
}

// =====================================================================
extern "C" void kernel_launch(void* const* d_in, const int* in_sizes, int n_in,
                              void* d_out, int out_size)
{
    const float* x      = (const float*)d_in[0];
    const float* cg_s   = (const float*)d_in[1];
    const float* cg_b   = (const float*)d_in[2];
    const float* pw1_w  = (const float*)d_in[3];
    const float* pw1_b  = (const float*)d_in[4];
    const float* dw_w   = (const float*)d_in[5];
    const float* dw_b   = (const float*)d_in[6];
    const float* pw2_w  = (const float*)d_in[7];
    const float* pw2_b  = (const float*)d_in[8];
    const float* beta   = (const float*)d_in[9];
    const float* at_s   = (const float*)d_in[10];
    const float* at_b   = (const float*)d_in[11];
    const float* qkv_w  = (const float*)d_in[12];
    const float* qkv_b  = (const float*)d_in[13];
    const float* rpe    = (const float*)d_in[14];
    const float* proj_w = (const float*)d_in[15];
    const float* proj_b = (const float*)d_in[16];
    const float* alpha  = (const float*)d_in[17];
    const float* ff_s   = (const float*)d_in[18];
    const float* ff_b   = (const float*)d_in[19];
    const float* fc1_w  = (const float*)d_in[20];
    const float* fc1_b  = (const float*)d_in[21];
    const float* fc2_w  = (const float*)d_in[22];
    const float* fc2_b  = (const float*)d_in[23];
    const float* gamma  = (const float*)d_in[24];
    float* out = (float*)d_out;

    float *a512, *g256, *x1, *x2;
    cudaGetSymbolAddress((void**)&a512, g_a512);
    cudaGetSymbolAddress((void**)&g256, g_g256);
    cudaGetSymbolAddress((void**)&x1,   g_x1);
    cudaGetSymbolAddress((void**)&x2,   g_x2);

    cudaFuncSetAttribute(tc_gemm<1, 4, true,  false>, cudaFuncAttributeMaxDynamicSharedMemorySize, SMB);
    cudaFuncSetAttribute(tc_gemm<1, 3, true,  false>, cudaFuncAttributeMaxDynamicSharedMemorySize, SMB);
    cudaFuncSetAttribute(tc_gemm<2, 1, false, true >, cudaFuncAttributeMaxDynamicSharedMemorySize, SMB);
    cudaFuncSetAttribute(tc_gemm<1, 1, false, true >, cudaFuncAttributeMaxDynamicSharedMemorySize, SMB);

    // ---- conv gated block ----
    tc_gemm<1, 4, true, false><<<576, 256, SMB>>>(
        x, pw1_w, pw1_b, cg_s, cg_b, nullptr, nullptr, a512);
    dwgate_kernel<<<2 * 256 * 144, 256>>>(a512, dw_w, dw_b, g256);
    tc_gemm<2, 1, false, true><<<576, 256, SMB>>>(
        g256, pw2_w, pw2_b, nullptr, nullptr, x, beta, x1);

    // ---- window attention ----
    tc_gemm<1, 3, true, false><<<576, 256, SMB>>>(
        x1, qkv_w, qkv_b, at_s, at_b, nullptr, nullptr, a512);
    attn2_kernel<<<NWTOT * 4, 64>>>(a512, rpe, g256);
    tc_gemm<1, 1, false, true><<<576, 256, SMB>>>(
        g256, proj_w, proj_b, nullptr, nullptr, x1, alpha, x2);

    // ---- gated FFN ----
    tc_gemm<1, 4, true, false><<<576, 256, SMB>>>(
        x2, fc1_w, fc1_b, ff_s, ff_b, nullptr, nullptr, a512);
    {
        size_t n = (size_t)2 * 256 * HWC;
        gate_kernel<<<(int)((n + 255) / 256), 256>>>(a512, g256);
    }
    tc_gemm<2, 1, false, true><<<576, 256, SMB>>>(
        g256, fc2_w, fc2_b, nullptr, nullptr, x2, gamma, out);
}

// round 4
// speedup vs baseline: 2.4831x; 1.4069x over previous
#include <cuda_runtime.h>
#include <math.h>
#include <stdint.h>

#define IMG 192
#define HWC (192*192)           // 36864 pixels per batch
#define NWSIDE 24
#define NWPB 576
#define NWTOT 1152

// ---------------- scratch (device globals) ----------------
static __device__ float g_a512[(size_t)2*512*HWC];   // qkv (384ch) etc.
static __device__ float g_g256[(size_t)2*256*HWC];   // gated 256-ch / attn-out 128ch
static __device__ float g_x1  [(size_t)2*128*HWC];
static __device__ float g_x2  [(size_t)2*128*HWC];

__device__ __forceinline__ float gelu_erf(float v) {
    return 0.5f * v * (1.0f + erff(v * 0.70710678118654752f));
}
__device__ __forceinline__ uint32_t smem_u32(const void* p) {
    uint32_t a;
    asm("{ .reg .u64 t; cvta.to.shared.u64 t, %1; cvt.u32.u64 %0, t; }" : "=r"(a) : "l"(p));
    return a;
}
__device__ __forceinline__ void cpa16(void* dst, const void* src) {
    uint32_t d = smem_u32(dst);
    asm volatile("cp.async.cg.shared.global [%0], [%1], 16;" :: "r"(d), "l"(src) : "memory");
}
#define CP_COMMIT() asm volatile("cp.async.commit_group;" ::: "memory")
#define CP_WAIT(n)  asm volatile("cp.async.wait_group %0;" :: "n"(n) : "memory")

// mma consumes raw fp32 bits as tf32 (HW reads top 19 bits; truncation rounding)
__device__ __forceinline__ void mma8(float* c, const uint32_t* a, const uint32_t* b) {
    asm volatile("mma.sync.aligned.m16n8k8.row.col.f32.tf32.tf32.f32 "
        "{%0,%1,%2,%3}, {%4,%5,%6,%7}, {%8,%9}, {%0,%1,%2,%3};"
        : "+f"(c[0]), "+f"(c[1]), "+f"(c[2]), "+f"(c[3])
        : "r"(a[0]), "r"(a[1]), "r"(a[2]), "r"(a[3]), "r"(b[0]), "r"(b[1]));
}

// smem layout (floats)
#define SA 132               // A stride (132 % 32 == 4)
#define SB 136               // B stride (136 % 32 == 8)
#define AS_OFF   0
#define BS_OFF   16896       // 128*132
#define RB_OFF   34304       // + 128*136
#define BIAS_OFF 34816       // rbuf 512
#define SM_FLOATS 35328
#define SMB (SM_FLOATS * 4)  // 141312 bytes

// =====================================================================
// mma.sync tf32 GEMM: out[b,o,p] = sum_c W[o,c]*in[b,c,p] (+ epilogue)
// 512 threads, 16 warps (4x4), warp tile 32oc x 32px, block 128oc x 128px.
// KT = K/128 chunks. MODE 0: plain (MT tiles). MODE 1: gated fc1
// (MT=2 pairs, out = (u+bu)*gelu(v+bv), 256 out ch). MODE 2: residual.
// RMS: rmsnorm over channels on input (KT==1 only).
// =====================================================================
template<int KT, int MT, bool RMS, int MODE>
__global__ void __launch_bounds__(512, 1)
tc_gemm(const float* __restrict__ in, const float* __restrict__ W,
        const float* __restrict__ bias,
        const float* __restrict__ rs, const float* __restrict__ rb,
        const float* __restrict__ res, const float* __restrict__ scale_ptr,
        float* __restrict__ out)
{
    constexpr int NSUB  = (MODE == 1) ? 2 : 1;
    constexpr int OCOUT = (MODE == 1) ? 256 : ((MODE == 2) ? 128 : MT * 128);
    constexpr int NBIAS = (MODE == 1) ? 512 : MT * 128;

    extern __shared__ float sm[];
    float* As   = sm + AS_OFF;
    float* Bs   = sm + BS_OFF;
    float* rbuf = sm + RB_OFF;
    float* bs   = sm + BIAS_OFF;
    uint32_t* Au = (uint32_t*)As;
    uint32_t* Bu = (uint32_t*)Bs;

    const int tid = threadIdx.x, lane = tid & 31, wid = tid >> 5;
    const int wm = wid & 3, wn = wid >> 2;
    const int gp = blockIdx.x * 128;
    const int b  = gp / HWC;
    const int p0 = gp - b * HWC;
    const float* inb = in + (size_t)b * (KT * 128) * HWC + p0;

    for (int i = tid; i < NBIAS; i += 512) bs[i] = bias[i];

    const int arow = wm * 32 + (lane >> 2);
    const int acol = lane & 3;
    const int brow = lane & 3;
    const int bcol = wn * 32 + (lane >> 2);

    for (int mt = 0; mt < MT; ++mt) {
        float acc[NSUB][2][4][4];
        #pragma unroll
        for (int s = 0; s < NSUB; ++s)
            #pragma unroll
            for (int mi = 0; mi < 2; ++mi)
                #pragma unroll
                for (int j = 0; j < 4; ++j)
                    #pragma unroll
                    for (int q = 0; q < 4; ++q) acc[s][mi][j][q] = 0.f;

        for (int kc = 0; kc < KT; ++kc) {
            const bool loadB = (mt == 0 || KT > 1);
            #pragma unroll
            for (int sub = 0; sub < NSUB; ++sub) {
                __syncthreads();   // protect As/Bs from previous mma readers
                if (sub == 0 && loadB) {
                    #pragma unroll
                    for (int i = tid; i < 4096; i += 512) {
                        int c = i >> 5, p4 = (i & 31) * 4;
                        cpa16(&Bs[c * SB + p4], inb + (size_t)(kc * 128 + c) * HWC + p4);
                    }
                    CP_COMMIT();
                }
                const int ocb = (MODE == 1) ? (mt + 2 * sub) * 128 : mt * 128;
                const float* wt = W + (size_t)ocb * (KT * 128) + kc * 128;
                #pragma unroll
                for (int i = tid; i < 4096; i += 512) {
                    int o = i >> 5, c4 = (i & 31) * 4;
                    cpa16(&As[o * SA + c4], wt + (size_t)o * (KT * 128) + c4);
                }
                CP_COMMIT();

                if (RMS && sub == 0 && loadB) {
                    CP_WAIT(1);          // B ready; A still in flight
                    __syncthreads();
                    int p = tid & 127, qq = tid >> 7;
                    float s = 0.f;
                    #pragma unroll 8
                    for (int c = qq * 32; c < qq * 32 + 32; ++c) {
                        float v = Bs[c * SB + p];
                        s += v * v;
                    }
                    rbuf[qq * 128 + p] = s;
                    __syncthreads();
                    if (tid < 128)
                        rbuf[tid] = rsqrtf((rbuf[tid] + rbuf[128 + tid] + rbuf[256 + tid]
                                          + rbuf[384 + tid]) * (1.0f / 128.0f) + 1e-6f);
                    __syncthreads();
                    for (int i = tid; i < 16384; i += 512) {
                        int c = i >> 7, p2 = i & 127;
                        Bs[c * SB + p2] = rs[c] * Bs[c * SB + p2] * rbuf[p2] + rb[c];
                    }
                }
                CP_WAIT(0);
                __syncthreads();

                // ---- mma mainloop: 16 k-steps of 8 ----
                #pragma unroll 4
                for (int k8 = 0; k8 < 16; ++k8) {
                    uint32_t bb[4][2];
                    #pragma unroll
                    for (int j = 0; j < 4; ++j) {
                        bb[j][0] = Bu[(k8 * 8 + brow) * SB + bcol + j * 8];
                        bb[j][1] = Bu[(k8 * 8 + brow + 4) * SB + bcol + j * 8];
                    }
                    #pragma unroll
                    for (int mi = 0; mi < 2; ++mi) {
                        uint32_t aa[4];
                        int r0 = arow + mi * 16;
                        aa[0] = Au[r0 * SA + k8 * 8 + acol];
                        aa[1] = Au[(r0 + 8) * SA + k8 * 8 + acol];
                        aa[2] = Au[r0 * SA + k8 * 8 + acol + 4];
                        aa[3] = Au[(r0 + 8) * SA + k8 * 8 + acol + 4];
                        #pragma unroll
                        for (int j = 0; j < 4; ++j) mma8(acc[sub][mi][j], aa, bb[j]);
                    }
                }
            }
        }

        // ---- epilogue: stage into As, then coalesced float4 write ----
        __syncthreads();
        {
            int r0e = wm * 32 + (lane >> 2), c0e = wn * 32 + (lane & 3) * 2;
            #pragma unroll
            for (int mi = 0; mi < 2; ++mi) {
                int o = r0e + mi * 16;
                if (MODE == 1) {
                    float bu1 = bs[mt * 128 + o],     bv1 = bs[mt * 128 + o + 256];
                    float bu2 = bs[mt * 128 + o + 8], bv2 = bs[mt * 128 + o + 264];
                    #pragma unroll
                    for (int j = 0; j < 4; ++j) {
                        float2 v01, v23;
                        v01.x = (acc[0][mi][j][0] + bu1) * gelu_erf(acc[1][mi][j][0] + bv1);
                        v01.y = (acc[0][mi][j][1] + bu1) * gelu_erf(acc[1][mi][j][1] + bv1);
                        v23.x = (acc[0][mi][j][2] + bu2) * gelu_erf(acc[1][mi][j][2] + bv2);
                        v23.y = (acc[0][mi][j][3] + bu2) * gelu_erf(acc[1][mi][j][3] + bv2);
                        *(float2*)&As[o * SA + c0e + j * 8]       = v01;
                        *(float2*)&As[(o + 8) * SA + c0e + j * 8] = v23;
                    }
                } else {
                    float b1 = bs[mt * 128 + o], b2 = bs[mt * 128 + o + 8];
                    #pragma unroll
                    for (int j = 0; j < 4; ++j) {
                        float2 v01 = make_float2(acc[0][mi][j][0] + b1, acc[0][mi][j][1] + b1);
                        float2 v23 = make_float2(acc[0][mi][j][2] + b2, acc[0][mi][j][3] + b2);
                        *(float2*)&As[o * SA + c0e + j * 8]       = v01;
                        *(float2*)&As[(o + 8) * SA + c0e + j * 8] = v23;
                    }
                }
            }
        }
        __syncthreads();
        {
            float scl = (MODE == 2) ? *scale_ptr : 0.f;
            for (int i = tid; i < 4096; i += 512) {
                int o = i >> 5, p4 = (i & 31) * 4;
                float4 v = *(float4*)&As[o * SA + p4];
                size_t oidx = (size_t)b * OCOUT * HWC + (size_t)(mt * 128 + o) * HWC + p0 + p4;
                if (MODE == 2) {
                    float4 rr = *(const float4*)(res + oidx);
                    v.x = rr.x + scl * v.x; v.y = rr.y + scl * v.y;
                    v.z = rr.z + scl * v.z; v.w = rr.w + scl * v.w;
                }
                *(float4*)(out + oidx) = v;
            }
        }
    }
}

// =====================================================================
// Depthwise 3x3 + bias + gated GELU
// =====================================================================
__global__ void __launch_bounds__(256)
dwgate_kernel(const float* __restrict__ a, const float* __restrict__ dw,
              const float* __restrict__ db, float* __restrict__ out)
{
    __shared__ float su[18 * 18], sv[18 * 18];
    int blk  = blockIdx.x;
    int tile = blk % 144;
    int cp   = (blk / 144) & 255;
    int b    = blk / (144 * 256);
    int ty = (tile / 12) * 16, tx = (tile % 12) * 16;
    const float* ua = a + ((size_t)b * 512 + cp) * HWC;
    const float* va = a + ((size_t)b * 512 + cp + 256) * HWC;

    for (int i = threadIdx.x; i < 324; i += 256) {
        int ly = i / 18, lx = i - ly * 18;
        int gy = ty + ly - 1, gx = tx + lx - 1;
        bool ok = ((unsigned)gy < (unsigned)IMG) && ((unsigned)gx < (unsigned)IMG);
        int gi = gy * IMG + gx;
        su[i] = ok ? ua[gi] : 0.f;
        sv[i] = ok ? va[gi] : 0.f;
    }
    __syncthreads();
    int y = threadIdx.x >> 4, x = threadIdx.x & 15;
    float u = db[cp], v = db[cp + 256];
    #pragma unroll
    for (int i = 0; i < 3; ++i)
        #pragma unroll
        for (int j = 0; j < 3; ++j) {
            float wu = dw[cp * 9 + i * 3 + j];
            float wv = dw[(cp + 256) * 9 + i * 3 + j];
            u = fmaf(su[(y + i) * 18 + x + j], wu, u);
            v = fmaf(sv[(y + i) * 18 + x + j], wv, v);
        }
    out[((size_t)b * 256 + cp) * HWC + (ty + y) * IMG + tx + x] = u * gelu_erf(v);
}

// =====================================================================
// Attention: qkv in standard layout [b][384][p]; rolled window gather,
// q-scale, RPE, shift mask, softmax, AV; scatter to un-rolled layout.
// =====================================================================
__global__ void __launch_bounds__(64)
attn2_kernel(const float* __restrict__ qkv, const float* __restrict__ rpe,
             float* __restrict__ aog)
{
    __shared__ float Ks[64 * 36], Vs[64 * 36], rpe_s[225], outs[64 * 33];
    __shared__ int pix[64], lk[64];
    int w = blockIdx.x >> 2, head = blockIdx.x & 3;
    int tid = threadIdx.x;
    int b = w / NWPB, wrem = w - b * NWPB;
    int wy = wrem / NWSIDE, wx = wrem - wy * NWSIDE;
    int qy = tid >> 3, qx = tid & 7;
    {
        int gh = wy * 8 + qy + 4; if (gh >= IMG) gh -= IMG;
        int gw = wx * 8 + qx + 4; if (gw >= IMG) gw -= IMG;
        pix[tid] = gh * IMG + gw;
    }
    {
        int gh = wy * 8 + qy, gw = wx * 8 + qx;
        int lh = gh < 184 ? 0 : (gh < 188 ? 1 : 2);
        int lw = gw < 184 ? 0 : (gw < 188 ? 1 : 2);
        lk[tid] = lh * 3 + lw;
    }
    for (int i = tid; i < 225; i += 64) rpe_s[i] = rpe[i * 4 + head];
    __syncthreads();

    const float* qb = qkv + (size_t)b * 384 * HWC + (size_t)(head * 32) * HWC;
    const float* kb = qb + (size_t)128 * HWC;
    const float* vb = qb + (size_t)256 * HWC;
    int myp = pix[tid];
    float q[32];
    #pragma unroll
    for (int d = 0; d < 32; ++d) {
        q[d] = qb[(size_t)d * HWC + myp] * 0.17677669529663687f;
        Ks[tid * 36 + d] = kb[(size_t)d * HWC + myp];
        Vs[tid * 36 + d] = vb[(size_t)d * HWC + myp];
    }
    int lab = lk[tid];
    __syncthreads();

    float sc[64];
    float mx = -1e30f;
    #pragma unroll
    for (int kk = 0; kk < 64; ++kk) {
        const float4* kp = (const float4*)(Ks + kk * 36);
        float dot = 0.f;
        #pragma unroll
        for (int d4 = 0; d4 < 8; ++d4) {
            float4 kv = kp[d4];
            dot = fmaf(q[d4 * 4 + 0], kv.x, dot);
            dot = fmaf(q[d4 * 4 + 1], kv.y, dot);
            dot = fmaf(q[d4 * 4 + 2], kv.z, dot);
            dot = fmaf(q[d4 * 4 + 3], kv.w, dot);
        }
        int ky = kk >> 3, kx = kk & 7;
        dot += rpe_s[(qy - ky + 7) * 15 + (qx - kx + 7)];
        if (lab != lk[kk]) dot = -1e30f;
        sc[kk] = dot;
        mx = fmaxf(mx, dot);
    }
    float sum = 0.f;
    #pragma unroll
    for (int kk = 0; kk < 64; ++kk) {
        float e = __expf(sc[kk] - mx);
        sc[kk] = e; sum += e;
    }
    float inv = 1.0f / sum;
    float acc[32];
    #pragma unroll
    for (int d = 0; d < 32; ++d) acc[d] = 0.f;
    #pragma unroll
    for (int kk = 0; kk < 64; ++kk) {
        float p = sc[kk];
        const float4* vp = (const float4*)(Vs + kk * 36);
        #pragma unroll
        for (int d4 = 0; d4 < 8; ++d4) {
            float4 vv = vp[d4];
            acc[d4 * 4 + 0] = fmaf(p, vv.x, acc[d4 * 4 + 0]);
            acc[d4 * 4 + 1] = fmaf(p, vv.y, acc[d4 * 4 + 1]);
            acc[d4 * 4 + 2] = fmaf(p, vv.z, acc[d4 * 4 + 2]);
            acc[d4 * 4 + 3] = fmaf(p, vv.w, acc[d4 * 4 + 3]);
        }
    }
    #pragma unroll
    for (int d = 0; d < 32; ++d) outs[tid * 33 + d] = acc[d] * inv;
    __syncthreads();
    size_t cb = (size_t)b * 128 * HWC + (size_t)(head * 32) * HWC;
    #pragma unroll
    for (int d = 0; d < 32; ++d)
        aog[cb + (size_t)d * HWC + myp] = outs[tid * 33 + d];
}

// =====================================================================
extern "C" void kernel_launch(void* const* d_in, const int* in_sizes, int n_in,
                              void* d_out, int out_size)
{
    const float* x      = (const float*)d_in[0];
    const float* cg_s   = (const float*)d_in[1];
    const float* cg_b   = (const float*)d_in[2];
    const float* pw1_w  = (const float*)d_in[3];
    const float* pw1_b  = (const float*)d_in[4];
    const float* dw_w   = (const float*)d_in[5];
    const float* dw_b   = (const float*)d_in[6];
    const float* pw2_w  = (const float*)d_in[7];
    const float* pw2_b  = (const float*)d_in[8];
    const float* beta   = (const float*)d_in[9];
    const float* at_s   = (const float*)d_in[10];
    const float* at_b   = (const float*)d_in[11];
    const float* qkv_w  = (const float*)d_in[12];
    const float* qkv_b  = (const float*)d_in[13];
    const float* rpe    = (const float*)d_in[14];
    const float* proj_w = (const float*)d_in[15];
    const float* proj_b = (const float*)d_in[16];
    const float* alpha  = (const float*)d_in[17];
    const float* ff_s   = (const float*)d_in[18];
    const float* ff_b   = (const float*)d_in[19];
    const float* fc1_w  = (const float*)d_in[20];
    const float* fc1_b  = (const float*)d_in[21];
    const float* fc2_w  = (const float*)d_in[22];
    const float* fc2_b  = (const float*)d_in[23];
    const float* gamma  = (const float*)d_in[24];
    float* out = (float*)d_out;

    float *a512, *g256, *x1, *x2;
    cudaGetSymbolAddress((void**)&a512, g_a512);
    cudaGetSymbolAddress((void**)&g256, g_g256);
    cudaGetSymbolAddress((void**)&x1,   g_x1);
    cudaGetSymbolAddress((void**)&x2,   g_x2);

    cudaFuncSetAttribute(tc_gemm<1, 4, true,  0>, cudaFuncAttributeMaxDynamicSharedMemorySize, SMB);
    cudaFuncSetAttribute(tc_gemm<1, 3, true,  0>, cudaFuncAttributeMaxDynamicSharedMemorySize, SMB);
    cudaFuncSetAttribute(tc_gemm<2, 1, false, 2>, cudaFuncAttributeMaxDynamicSharedMemorySize, SMB);
    cudaFuncSetAttribute(tc_gemm<1, 1, false, 2>, cudaFuncAttributeMaxDynamicSharedMemorySize, SMB);
    cudaFuncSetAttribute(tc_gemm<1, 2, true,  1>, cudaFuncAttributeMaxDynamicSharedMemorySize, SMB);

    // ---- conv gated block ----
    tc_gemm<1, 4, true, 0><<<576, 512, SMB>>>(
        x, pw1_w, pw1_b, cg_s, cg_b, nullptr, nullptr, a512);
    dwgate_kernel<<<2 * 256 * 144, 256>>>(a512, dw_w, dw_b, g256);
    tc_gemm<2, 1, false, 2><<<576, 512, SMB>>>(
        g256, pw2_w, pw2_b, nullptr, nullptr, x, beta, x1);

    // ---- window attention ----
    tc_gemm<1, 3, true, 0><<<576, 512, SMB>>>(
        x1, qkv_w, qkv_b, at_s, at_b, nullptr, nullptr, a512);
    attn2_kernel<<<NWTOT * 4, 64>>>(a512, rpe, g256);
    tc_gemm<1, 1, false, 2><<<576, 512, SMB>>>(
        g256, proj_w, proj_b, nullptr, nullptr, x1, alpha, x2);

    // ---- gated FFN (gate fused into fc1 epilogue) ----
    tc_gemm<1, 2, true, 1><<<576, 512, SMB>>>(
        x2, fc1_w, fc1_b, ff_s, ff_b, nullptr, nullptr, g256);
    tc_gemm<2, 1, false, 2><<<576, 512, SMB>>>(
        g256, fc2_w, fc2_b, nullptr, nullptr, x2, gamma, out);
}

// round 5
// speedup vs baseline: 3.5221x; 1.4184x over previous
#include <cuda_runtime.h>
#include <cuda_bf16.h>
#include <math.h>
#include <stdint.h>

#define IMG 192
#define HWC (192*192)
#define NWSIDE 24
#define NWPB 576
#define NWTOT 1152
typedef __nv_bfloat16 bf16;

// ---------------- scratch (device globals) ----------------
static __device__ bf16  g_wbf [262144];               // all weights bf16
static __device__ bf16  g_xn  [(size_t)2*128*HWC];    // rmsnorm(x)
static __device__ bf16  g_a512[(size_t)2*512*HWC];    // pw1 out
static __device__ bf16  g_g256[(size_t)2*256*HWC];    // dwgate out / fc1 out
static __device__ bf16  g_qkv [(size_t)2*384*HWC];    // qkv out
static __device__ bf16  g_ao  [(size_t)2*128*HWC];    // attn out
static __device__ bf16  g_x1n [(size_t)2*128*HWC];    // rmsnorm(x1)
static __device__ bf16  g_x2n [(size_t)2*128*HWC];    // rmsnorm(x2)
static __device__ float g_x1  [(size_t)2*128*HWC];
static __device__ float g_x2  [(size_t)2*128*HWC];

__device__ __forceinline__ float gelu_erf(float v) {
    return 0.5f * v * (1.0f + erff(v * 0.70710678118654752f));
}
__device__ __forceinline__ uint32_t smem_u32(const void* p) {
    uint32_t a;
    asm("{ .reg .u64 t; cvta.to.shared.u64 t, %1; cvt.u32.u64 %0, t; }" : "=r"(a) : "l"(p));
    return a;
}
__device__ __forceinline__ void cpa16(void* dst, const void* src) {
    uint32_t d = smem_u32(dst);
    asm volatile("cp.async.cg.shared.global [%0], [%1], 16;" :: "r"(d), "l"(src) : "memory");
}
#define CP_COMMIT() asm volatile("cp.async.commit_group;" ::: "memory")
#define CP_WAIT(n)  asm volatile("cp.async.wait_group %0;" :: "n"(n) : "memory")

__device__ __forceinline__ void ldsm4(uint32_t* r, uint32_t addr) {
    asm volatile("ldmatrix.sync.aligned.m8n8.x4.shared.b16 {%0,%1,%2,%3}, [%4];"
        : "=r"(r[0]), "=r"(r[1]), "=r"(r[2]), "=r"(r[3]) : "r"(addr));
}
__device__ __forceinline__ void ldsm4t(uint32_t* r, uint32_t addr) {
    asm volatile("ldmatrix.sync.aligned.m8n8.x4.trans.shared.b16 {%0,%1,%2,%3}, [%4];"
        : "=r"(r[0]), "=r"(r[1]), "=r"(r[2]), "=r"(r[3]) : "r"(addr));
}
__device__ __forceinline__ void mma16(float* c, const uint32_t* a, const uint32_t* b) {
    asm volatile("mma.sync.aligned.m16n8k16.row.col.f32.bf16.bf16.f32 "
        "{%0,%1,%2,%3}, {%4,%5,%6,%7}, {%8,%9}, {%0,%1,%2,%3};"
        : "+f"(c[0]), "+f"(c[1]), "+f"(c[2]), "+f"(c[3])
        : "r"(a[0]), "r"(a[1]), "r"(a[2]), "r"(a[3]), "r"(b[0]), "r"(b[1]));
}

// smem byte offsets
#define SH 136                // tile stride in halves (272B rows -> ldmatrix conflict-free)
#define OFF_A0   0
#define OFF_A1   34816
#define OFF_B0   69632
#define OFF_B1   104448
#define OFF_BIAS 139264       // 512 floats
#define OFF_RS   141312       // 128 floats
#define OFF_RB   141824       // 128 floats
#define OFF_RBUF 142336       // 512 floats
#define SMB      144384

// =====================================================================
// bf16 mma GEMM, 512 thr (16 warps 4x4), block 128oc x 128px, double-
// buffered A/B cp.async pipeline.
// MODE 0: out bf16 = acc+bias (MT tiles).  MODE 1: fc1 gated, out bf16 =
// (u+bu)*gelu(v+bv) (256 ch). MODE 2: out fp32 = res + scl*(acc+bias),
// KT chunks; RMSOUT adds normalized bf16 dual write (rs2/rb2).
// =====================================================================
template<int KT, int MT, int MODE, bool RMSOUT>
__global__ void __launch_bounds__(512, 1)
tc_gemm(const bf16* __restrict__ in, const bf16* __restrict__ W,
        const float* __restrict__ bias,
        const float* __restrict__ res, const float* __restrict__ scale_ptr,
        float* __restrict__ out, bf16* __restrict__ outb,
        bf16* __restrict__ outn,
        const float* __restrict__ rs2, const float* __restrict__ rb2)
{
    constexpr int NSUB  = (MODE == 1) ? 2 : 1;
    constexpr int NS    = KT * MT * NSUB;
    constexpr int KTOT  = KT * 128;
    constexpr int OCOUT = (MODE == 1) ? 256 : MT * 128;
    constexpr int NBIAS = (MODE == 1) ? 512 : MT * 128;
    constexpr int NACC  = (MODE == 1) ? 2 : 1;

    extern __shared__ char sm[];
    float* bs   = (float*)(sm + OFF_BIAS);
    float* rsv  = (float*)(sm + OFF_RS);
    float* rbv  = (float*)(sm + OFF_RB);
    float* rbuf = (float*)(sm + OFF_RBUF);
    const uint32_t smb = smem_u32(sm);

    const int tid = threadIdx.x, lane = tid & 31, wid = tid >> 5;
    const int wm = wid & 3, wn = wid >> 2;
    const int gp = blockIdx.x * 128;
    const int b  = gp / HWC;
    const int p0 = gp - b * HWC;
    const bf16* inb = in + (size_t)b * KTOT * HWC + p0;

    for (int i = tid; i < NBIAS; i += 512) bs[i] = bias[i];
    if (RMSOUT) for (int i = tid; i < 128; i += 512) { rsv[i] = rs2[i]; rbv[i] = rb2[i]; }

    // ldmatrix lane addressing
    const int a_m = (lane & 7) + ((lane >> 3) & 1) * 8;     // + wm*32 + mi*16
    const int a_k = (lane >> 4) * 8;
    const int b_k = (lane & 7) + ((lane >> 3) & 1) * 8;
    const int b_n = wn * 32 + (lane >> 4) * 8;

    float acc[NACC][2][4][4];

    // ---- prefetch step 0 ----
    {
        for (int i = tid; i < 2048; i += 512) {        // B(kc=0)
            int c = i >> 4, p8 = (i & 15) * 8;
            cpa16(sm + OFF_B0 + (c * SH + p8) * 2, inb + (size_t)c * HWC + p8);
        }
        const int ocb0 = (MODE == 1) ? 0 : 0;
        const bf16* wt = W + (size_t)ocb0 * KTOT;
        for (int i = tid; i < 2048; i += 512) {        // A(step 0)
            int o = i >> 4, k8 = (i & 15) * 8;
            cpa16(sm + OFF_A0 + (o * SH + k8) * 2, wt + (size_t)o * KTOT + k8);
        }
        CP_COMMIT();
    }

    #pragma unroll
    for (int s = 0; s < NS; ++s) {
        const int kc = (KT == 2) ? s : 0;
        __syncthreads();
        if (s + 1 < NS) {
            const int kcn = (KT == 2) ? (s + 1) : 0;
            if (kcn != kc) {
                char* bd = sm + ((kcn & 1) ? OFF_B1 : OFF_B0);
                for (int i = tid; i < 2048; i += 512) {
                    int c = i >> 4, p8 = (i & 15) * 8;
                    cpa16(bd + (c * SH + p8) * 2, inb + (size_t)(kcn * 128 + c) * HWC + p8);
                }
            }
            const int sn = s + 1;
            const int ocb = (MODE == 1) ? ((sn & 1) * 256 + (sn >> 1) * 128)
                          : ((MODE == 0) ? sn * 128 : 0);
            const bf16* wt = W + (size_t)ocb * KTOT + kcn * 128;
            char* ad = sm + ((sn & 1) ? OFF_A1 : OFF_A0);
            for (int i = tid; i < 2048; i += 512) {
                int o = i >> 4, k8 = (i & 15) * 8;
                cpa16(ad + (o * SH + k8) * 2, wt + (size_t)o * KTOT + k8);
            }
            CP_COMMIT();
            CP_WAIT(1);
        } else {
            CP_WAIT(0);
        }
        __syncthreads();

        // zero accumulators for fresh tiles
        const int sel = (MODE == 1) ? (s & 1) : 0;
        if (MODE != 2 || s == 0) {
            #pragma unroll
            for (int mi = 0; mi < 2; ++mi)
                #pragma unroll
                for (int j = 0; j < 4; ++j)
                    #pragma unroll
                    for (int q = 0; q < 4; ++q) acc[sel][mi][j][q] = 0.f;
        }

        // ---- mma over k=128 ----
        {
            const uint32_t Ab = smb + ((s & 1) ? OFF_A1 : OFF_A0);
            const uint32_t Bb = smb + ((kc & 1) ? OFF_B1 : OFF_B0);
            const uint32_t aaddr = Ab + ((wm * 32 + a_m) * SH + a_k) * 2;
            const uint32_t baddr = Bb + (b_k * SH + b_n) * 2;
            #pragma unroll
            for (int k0 = 0; k0 < 128; k0 += 16) {
                uint32_t a0[4], a1[4], b0[4], b1[4];
                ldsm4 (a0, aaddr + k0 * 2);
                ldsm4 (a1, aaddr + (16 * SH + k0) * 2);
                ldsm4t(b0, baddr + k0 * SH * 2);
                ldsm4t(b1, baddr + (k0 * SH + 16) * 2);
                mma16(acc[sel][0][0], a0, b0 + 0);
                mma16(acc[sel][0][1], a0, b0 + 2);
                mma16(acc[sel][0][2], a0, b1 + 0);
                mma16(acc[sel][0][3], a0, b1 + 2);
                mma16(acc[sel][1][0], a1, b0 + 0);
                mma16(acc[sel][1][1], a1, b0 + 2);
                mma16(acc[sel][1][2], a1, b1 + 0);
                mma16(acc[sel][1][3], a1, b1 + 2);
            }
        }

        // ---- epilogues ----
        const int r0e = wm * 32 + (lane >> 2);
        const int c0e = wn * 32 + (lane & 3) * 2;

        if (MODE == 0 || (MODE == 1 && (s & 1))) {
            const int mt = (MODE == 1) ? (s >> 1) : s;
            __syncthreads();      // all warps done reading A[s&1]
            bf16* st = (bf16*)(sm + ((s & 1) ? OFF_A1 : OFF_A0));
            #pragma unroll
            for (int mi = 0; mi < 2; ++mi) {
                int o = r0e + mi * 16;
                if (MODE == 1) {
                    float bu1 = bs[mt * 128 + o],     bv1 = bs[256 + mt * 128 + o];
                    float bu2 = bs[mt * 128 + o + 8], bv2 = bs[256 + mt * 128 + o + 8];
                    #pragma unroll
                    for (int j = 0; j < 4; ++j) {
                        int c = c0e + j * 8;
                        float u0 = (acc[0][mi][j][0] + bu1) * gelu_erf(acc[1][mi][j][0] + bv1);
                        float u1 = (acc[0][mi][j][1] + bu1) * gelu_erf(acc[1][mi][j][1] + bv1);
                        float u2 = (acc[0][mi][j][2] + bu2) * gelu_erf(acc[1][mi][j][2] + bv2);
                        float u3 = (acc[0][mi][j][3] + bu2) * gelu_erf(acc[1][mi][j][3] + bv2);
                        *(__nv_bfloat162*)&st[o * SH + c] =
                            __halves2bfloat162(__float2bfloat16(u0), __float2bfloat16(u1));
                        *(__nv_bfloat162*)&st[(o + 8) * SH + c] =
                            __halves2bfloat162(__float2bfloat16(u2), __float2bfloat16(u3));
                    }
                } else {
                    float b1v = bs[mt * 128 + o], b2v = bs[mt * 128 + o + 8];
                    #pragma unroll
                    for (int j = 0; j < 4; ++j) {
                        int c = c0e + j * 8;
                        *(__nv_bfloat162*)&st[o * SH + c] =
                            __halves2bfloat162(__float2bfloat16(acc[0][mi][j][0] + b1v),
                                               __float2bfloat16(acc[0][mi][j][1] + b1v));
                        *(__nv_bfloat162*)&st[(o + 8) * SH + c] =
                            __halves2bfloat162(__float2bfloat16(acc[0][mi][j][2] + b2v),
                                               __float2bfloat16(acc[0][mi][j][3] + b2v));
                    }
                }
            }
            __syncthreads();
            for (int i = tid; i < 2048; i += 512) {
                int o = i >> 4, p8 = (i & 15) * 8;
                uint4 v = *(uint4*)&st[o * SH + p8];
                *(uint4*)(outb + (size_t)b * OCOUT * HWC
                          + (size_t)(mt * 128 + o) * HWC + p0 + p8) = v;
            }
        } else if (MODE == 2 && s == NS - 1) {
            __syncthreads();      // B buffers free now
            float* st = (float*)(sm + OFF_B0);   // fp32 stage [128][132]
            #pragma unroll
            for (int mi = 0; mi < 2; ++mi) {
                int o = r0e + mi * 16;
                float b1v = bs[o], b2v = bs[o + 8];
                #pragma unroll
                for (int j = 0; j < 4; ++j) {
                    int c = c0e + j * 8;
                    st[o * 132 + c]           = acc[0][mi][j][0] + b1v;
                    st[o * 132 + c + 1]       = acc[0][mi][j][1] + b1v;
                    st[(o + 8) * 132 + c]     = acc[0][mi][j][2] + b2v;
                    st[(o + 8) * 132 + c + 1] = acc[0][mi][j][3] + b2v;
                }
            }
            __syncthreads();
            float scl = *scale_ptr;
            for (int i = tid; i < 4096; i += 512) {
                int o = i >> 5, p4 = (i & 31) * 4;
                float4 v = *(float4*)&st[o * 132 + p4];
                size_t oidx = (size_t)b * 128 * HWC + (size_t)o * HWC + p0 + p4;
                float4 rr = *(const float4*)(res + oidx);
                v.x = rr.x + scl * v.x; v.y = rr.y + scl * v.y;
                v.z = rr.z + scl * v.z; v.w = rr.w + scl * v.w;
                *(float4*)(out + oidx) = v;
                if (RMSOUT) *(float4*)&st[o * 132 + p4] = v;
            }
            if (RMSOUT) {
                __syncthreads();
                int px = tid & 127, part = tid >> 7;
                float ss = 0.f;
                #pragma unroll 8
                for (int c = part * 32; c < part * 32 + 32; ++c) {
                    float v = st[c * 132 + px]; ss += v * v;
                }
                rbuf[part * 128 + px] = ss;
                __syncthreads();
                if (tid < 128)
                    rbuf[tid] = rsqrtf((rbuf[tid] + rbuf[128 + tid] + rbuf[256 + tid]
                                      + rbuf[384 + tid]) * (1.0f / 128.0f) + 1e-6f);
                __syncthreads();
                for (int i = tid; i < 4096; i += 512) {
                    int o = i >> 5, p4 = (i & 31) * 4;
                    float sc = rsv[o], bb = rbv[o];
                    float4 v = *(float4*)&st[o * 132 + p4];
                    float n0 = rbuf[p4], n1 = rbuf[p4 + 1], n2 = rbuf[p4 + 2], n3 = rbuf[p4 + 3];
                    bf16* ob = outn + (size_t)b * 128 * HWC + (size_t)o * HWC + p0 + p4;
                    *(__nv_bfloat162*)ob =
                        __halves2bfloat162(__float2bfloat16(sc * v.x * n0 + bb),
                                           __float2bfloat16(sc * v.y * n1 + bb));
                    *(__nv_bfloat162*)(ob + 2) =
                        __halves2bfloat162(__float2bfloat16(sc * v.z * n2 + bb),
                                           __float2bfloat16(sc * v.w * n3 + bb));
                }
            }
        }
    }
}

// =====================================================================
// weight fp32 -> bf16 (segments: pw1|pw2|qkv|proj|fc1|fc2)
// =====================================================================
__global__ void wcvt_kernel(const float* p1, const float* p2, const float* p3,
                            const float* p4, const float* p5, const float* p6,
                            bf16* o)
{
    int i = blockIdx.x * 1024 + threadIdx.x * 4;
    const float* src; int base;
    if      (i < 65536)  { src = p1; base = 0; }
    else if (i < 98304)  { src = p2; base = 65536; }
    else if (i < 147456) { src = p3; base = 98304; }
    else if (i < 163840) { src = p4; base = 147456; }
    else if (i < 229376) { src = p5; base = 163840; }
    else                 { src = p6; base = 229376; }
    float4 v = *(const float4*)(src + (i - base));
    *(__nv_bfloat162*)(o + i)     = __halves2bfloat162(__float2bfloat16(v.x), __float2bfloat16(v.y));
    *(__nv_bfloat162*)(o + i + 2) = __halves2bfloat162(__float2bfloat16(v.z), __float2bfloat16(v.w));
}

// =====================================================================
// rmsnorm(x) -> bf16
// =====================================================================
__global__ void __launch_bounds__(512)
rms_prep(const float* __restrict__ x, const float* __restrict__ s,
         const float* __restrict__ bsh, bf16* __restrict__ xn)
{
    extern __shared__ float smf[];
    float* st = smf;               // [128][132]
    float* rbuf = smf + 128 * 132;
    int tid = threadIdx.x;
    int gp = blockIdx.x * 128;
    int b = gp / HWC, p0 = gp - b * HWC;
    const float* xb = x + (size_t)b * 128 * HWC + p0;
    for (int i = tid; i < 4096; i += 512) {
        int c = i >> 5, p4 = (i & 31) * 4;
        *(float4*)&st[c * 132 + p4] = *(const float4*)(xb + (size_t)c * HWC + p4);
    }
    __syncthreads();
    int px = tid & 127, part = tid >> 7;
    float ss = 0.f;
    #pragma unroll 8
    for (int c = part * 32; c < part * 32 + 32; ++c) { float v = st[c * 132 + px]; ss += v * v; }
    rbuf[part * 128 + px] = ss;
    __syncthreads();
    if (tid < 128)
        rbuf[tid] = rsqrtf((rbuf[tid] + rbuf[128 + tid] + rbuf[256 + tid] + rbuf[384 + tid])
                           * (1.0f / 128.0f) + 1e-6f);
    __syncthreads();
    bf16* ob = xn + (size_t)b * 128 * HWC + p0;
    for (int i = tid; i < 4096; i += 512) {
        int c = i >> 5, p4 = (i & 31) * 4;
        float sc = s[c], bb = bsh[c];
        float4 v = *(float4*)&st[c * 132 + p4];
        float n0 = rbuf[p4], n1 = rbuf[p4 + 1], n2 = rbuf[p4 + 2], n3 = rbuf[p4 + 3];
        *(__nv_bfloat162*)(ob + (size_t)c * HWC + p4) =
            __halves2bfloat162(__float2bfloat16(sc * v.x * n0 + bb),
                               __float2bfloat16(sc * v.y * n1 + bb));
        *(__nv_bfloat162*)(ob + (size_t)c * HWC + p4 + 2) =
            __halves2bfloat162(__float2bfloat16(sc * v.z * n2 + bb),
                               __float2bfloat16(sc * v.w * n3 + bb));
    }
}

// =====================================================================
// Depthwise 3x3 + bias + gated GELU (bf16 in/out, fp32 math)
// =====================================================================
__global__ void __launch_bounds__(256)
dwgate_kernel(const bf16* __restrict__ a, const float* __restrict__ dw,
              const float* __restrict__ db, bf16* __restrict__ out)
{
    __shared__ float su[18 * 18], sv[18 * 18];
    int blk  = blockIdx.x;
    int tile = blk % 144;
    int cp   = (blk / 144) & 255;
    int b    = blk / (144 * 256);
    int ty = (tile / 12) * 16, tx = (tile % 12) * 16;
    const bf16* ua = a + ((size_t)b * 512 + cp) * HWC;
    const bf16* va = a + ((size_t)b * 512 + cp + 256) * HWC;

    for (int i = threadIdx.x; i < 324; i += 256) {
        int ly = i / 18, lx = i - ly * 18;
        int gy = ty + ly - 1, gx = tx + lx - 1;
        bool ok = ((unsigned)gy < (unsigned)IMG) && ((unsigned)gx < (unsigned)IMG);
        int gi = gy * IMG + gx;
        su[i] = ok ? __bfloat162float(ua[gi]) : 0.f;
        sv[i] = ok ? __bfloat162float(va[gi]) : 0.f;
    }
    __syncthreads();
    int y = threadIdx.x >> 4, x = threadIdx.x & 15;
    float u = db[cp], v = db[cp + 256];
    #pragma unroll
    for (int i = 0; i < 3; ++i)
        #pragma unroll
        for (int j = 0; j < 3; ++j) {
            float wu = dw[cp * 9 + i * 3 + j];
            float wv = dw[(cp + 256) * 9 + i * 3 + j];
            u = fmaf(su[(y + i) * 18 + x + j], wu, u);
            v = fmaf(sv[(y + i) * 18 + x + j], wv, v);
        }
    out[((size_t)b * 256 + cp) * HWC + (ty + y) * IMG + tx + x] =
        __float2bfloat16(u * gelu_erf(v));
}

// =====================================================================
// Attention (bf16 qkv in, bf16 out; fp32 math)
// =====================================================================
__global__ void __launch_bounds__(64)
attn2_kernel(const bf16* __restrict__ qkv, const float* __restrict__ rpe,
             bf16* __restrict__ aog)
{
    __shared__ float Ks[64 * 36], Vs[64 * 36], rpe_s[225], outs[64 * 33];
    __shared__ int pix[64], lk[64];
    int w = blockIdx.x >> 2, head = blockIdx.x & 3;
    int tid = threadIdx.x;
    int b = w / NWPB, wrem = w - b * NWPB;
    int wy = wrem / NWSIDE, wx = wrem - wy * NWSIDE;
    int qy = tid >> 3, qx = tid & 7;
    {
        int gh = wy * 8 + qy + 4; if (gh >= IMG) gh -= IMG;
        int gw = wx * 8 + qx + 4; if (gw >= IMG) gw -= IMG;
        pix[tid] = gh * IMG + gw;
    }
    {
        int gh = wy * 8 + qy, gw = wx * 8 + qx;
        int lh = gh < 184 ? 0 : (gh < 188 ? 1 : 2);
        int lw = gw < 184 ? 0 : (gw < 188 ? 1 : 2);
        lk[tid] = lh * 3 + lw;
    }
    for (int i = tid; i < 225; i += 64) rpe_s[i] = rpe[i * 4 + head];
    __syncthreads();

    const bf16* qb = qkv + (size_t)b * 384 * HWC + (size_t)(head * 32) * HWC;
    const bf16* kb = qb + (size_t)128 * HWC;
    const bf16* vb = qb + (size_t)256 * HWC;
    int myp = pix[tid];
    float q[32];
    #pragma unroll
    for (int d = 0; d < 32; ++d) {
        q[d] = __bfloat162float(qb[(size_t)d * HWC + myp]) * 0.17677669529663687f;
        Ks[tid * 36 + d] = __bfloat162float(kb[(size_t)d * HWC + myp]);
        Vs[tid * 36 + d] = __bfloat162float(vb[(size_t)d * HWC + myp]);
    }
    int lab = lk[tid];
    __syncthreads();

    float sc[64];
    float mx = -1e30f;
    #pragma unroll
    for (int kk = 0; kk < 64; ++kk) {
        const float4* kp = (const float4*)(Ks + kk * 36);
        float dot = 0.f;
        #pragma unroll
        for (int d4 = 0; d4 < 8; ++d4) {
            float4 kv = kp[d4];
            dot = fmaf(q[d4 * 4 + 0], kv.x, dot);
            dot = fmaf(q[d4 * 4 + 1], kv.y, dot);
            dot = fmaf(q[d4 * 4 + 2], kv.z, dot);
            dot = fmaf(q[d4 * 4 + 3], kv.w, dot);
        }
        int ky = kk >> 3, kx = kk & 7;
        dot += rpe_s[(qy - ky + 7) * 15 + (qx - kx + 7)];
        if (lab != lk[kk]) dot = -1e30f;
        sc[kk] = dot;
        mx = fmaxf(mx, dot);
    }
    float sum = 0.f;
    #pragma unroll
    for (int kk = 0; kk < 64; ++kk) {
        float e = __expf(sc[kk] - mx);
        sc[kk] = e; sum += e;
    }
    float inv = 1.0f / sum;
    float acc[32];
    #pragma unroll
    for (int d = 0; d < 32; ++d) acc[d] = 0.f;
    #pragma unroll
    for (int kk = 0; kk < 64; ++kk) {
        float p = sc[kk];
        const float4* vp = (const float4*)(Vs + kk * 36);
        #pragma unroll
        for (int d4 = 0; d4 < 8; ++d4) {
            float4 vv = vp[d4];
            acc[d4 * 4 + 0] = fmaf(p, vv.x, acc[d4 * 4 + 0]);
            acc[d4 * 4 + 1] = fmaf(p, vv.y, acc[d4 * 4 + 1]);
            acc[d4 * 4 + 2] = fmaf(p, vv.z, acc[d4 * 4 + 2]);
            acc[d4 * 4 + 3] = fmaf(p, vv.w, acc[d4 * 4 + 3]);
        }
    }
    #pragma unroll
    for (int d = 0; d < 32; ++d) outs[tid * 33 + d] = acc[d] * inv;
    __syncthreads();
    size_t cb = (size_t)b * 128 * HWC + (size_t)(head * 32) * HWC;
    #pragma unroll
    for (int d = 0; d < 32; ++d)
        aog[cb + (size_t)d * HWC + myp] = __float2bfloat16(outs[tid * 33 + d]);
}

// =====================================================================
extern "C" void kernel_launch(void* const* d_in, const int* in_sizes, int n_in,
                              void* d_out, int out_size)
{
    const float* x      = (const float*)d_in[0];
    const float* cg_s   = (const float*)d_in[1];
    const float* cg_b   = (const float*)d_in[2];
    const float* pw1_w  = (const float*)d_in[3];
    const float* pw1_b  = (const float*)d_in[4];
    const float* dw_w   = (const float*)d_in[5];
    const float* dw_b   = (const float*)d_in[6];
    const float* pw2_w  = (const float*)d_in[7];
    const float* pw2_b  = (const float*)d_in[8];
    const float* beta   = (const float*)d_in[9];
    const float* at_s   = (const float*)d_in[10];
    const float* at_b   = (const float*)d_in[11];
    const float* qkv_w  = (const float*)d_in[12];
    const float* qkv_b  = (const float*)d_in[13];
    const float* rpe    = (const float*)d_in[14];
    const float* proj_w = (const float*)d_in[15];
    const float* proj_b = (const float*)d_in[16];
    const float* alpha  = (const float*)d_in[17];
    const float* ff_s   = (const float*)d_in[18];
    const float* ff_b   = (const float*)d_in[19];
    const float* fc1_w  = (const float*)d_in[20];
    const float* fc1_b  = (const float*)d_in[21];
    const float* fc2_w  = (const float*)d_in[22];
    const float* fc2_b  = (const float*)d_in[23];
    const float* gamma  = (const float*)d_in[24];
    float* out = (float*)d_out;

    bf16 *wbf, *xn, *a512, *g256, *qkvb, *aob, *x1n, *x2n;
    float *x1, *x2;
    cudaGetSymbolAddress((void**)&wbf,  g_wbf);
    cudaGetSymbolAddress((void**)&xn,   g_xn);
    cudaGetSymbolAddress((void**)&a512, g_a512);
    cudaGetSymbolAddress((void**)&g256, g_g256);
    cudaGetSymbolAddress((void**)&qkvb, g_qkv);
    cudaGetSymbolAddress((void**)&aob,  g_ao);
    cudaGetSymbolAddress((void**)&x1n,  g_x1n);
    cudaGetSymbolAddress((void**)&x2n,  g_x2n);
    cudaGetSymbolAddress((void**)&x1,   g_x1);
    cudaGetSymbolAddress((void**)&x2,   g_x2);

    cudaFuncSetAttribute(tc_gemm<1, 4, 0, false>, cudaFuncAttributeMaxDynamicSharedMemorySize, SMB);
    cudaFuncSetAttribute(tc_gemm<1, 3, 0, false>, cudaFuncAttributeMaxDynamicSharedMemorySize, SMB);
    cudaFuncSetAttribute(tc_gemm<2, 1, 2, true >, cudaFuncAttributeMaxDynamicSharedMemorySize, SMB);
    cudaFuncSetAttribute(tc_gemm<1, 1, 2, true >, cudaFuncAttributeMaxDynamicSharedMemorySize, SMB);
    cudaFuncSetAttribute(tc_gemm<1, 2, 1, false>, cudaFuncAttributeMaxDynamicSharedMemorySize, SMB);
    cudaFuncSetAttribute(tc_gemm<2, 1, 2, false>, cudaFuncAttributeMaxDynamicSharedMemorySize, SMB);
    cudaFuncSetAttribute(rms_prep, cudaFuncAttributeMaxDynamicSharedMemorySize, 69632);

    // ---- prep ----
    wcvt_kernel<<<256, 256>>>(pw1_w, pw2_w, qkv_w, proj_w, fc1_w, fc2_w, wbf);
    rms_prep<<<576, 512, 69632>>>(x, cg_s, cg_b, xn);

    // ---- conv gated block ----
    tc_gemm<1, 4, 0, false><<<576, 512, SMB>>>(
        xn, wbf + 0, pw1_b, nullptr, nullptr, nullptr, a512, nullptr, nullptr, nullptr);
    dwgate_kernel<<<2 * 256 * 144, 256>>>(a512, dw_w, dw_b, g256);
    tc_gemm<2, 1, 2, true><<<576, 512, SMB>>>(
        g256, wbf + 65536, pw2_b, x, beta, x1, nullptr, x1n, at_s, at_b);

    // ---- window attention ----
    tc_gemm<1, 3, 0, false><<<576, 512, SMB>>>(
        x1n, wbf + 98304, qkv_b, nullptr, nullptr, nullptr, qkvb, nullptr, nullptr, nullptr);
    attn2_kernel<<<NWTOT * 4, 64>>>(qkvb, rpe, aob);
    tc_gemm<1, 1, 2, true><<<576, 512, SMB>>>(
        aob, wbf + 147456, proj_b, x1, alpha, x2, nullptr, x2n, ff_s, ff_b);

    // ---- gated FFN ----
    tc_gemm<1, 2, 1, false><<<576, 512, SMB>>>(
        x2n, wbf + 163840, fc1_b, nullptr, nullptr, nullptr, g256, nullptr, nullptr, nullptr);
    tc_gemm<2, 1, 2, false><<<576, 512, SMB>>>(
        g256, wbf + 229376, fc2_b, x2, gamma, out, nullptr, nullptr, nullptr, nullptr);
}

// round 6
// speedup vs baseline: 3.9307x; 1.1160x over previous
#include <cuda_runtime.h>
#include <cuda_bf16.h>
#include <math.h>
#include <stdint.h>

#define IMG 192
#define HWC (192*192)
#define NWSIDE 24
#define NWPB 576
#define NWTOT 1152
typedef __nv_bfloat16 bf16;

// ---------------- scratch (device globals) ----------------
static __device__ bf16  g_wbf [262144];               // all weights bf16
static __device__ bf16  g_xn  [(size_t)2*128*HWC];    // rmsnorm(x)
static __device__ bf16  g_a512[(size_t)2*512*HWC];    // pw1 out
static __device__ bf16  g_g256[(size_t)2*256*HWC];    // dwgate out / fc1 out
static __device__ bf16  g_qkv [(size_t)2*384*HWC];    // qkv out
static __device__ bf16  g_ao  [(size_t)2*128*HWC];    // attn out
static __device__ bf16  g_x1n [(size_t)2*128*HWC];    // rmsnorm(x1)
static __device__ bf16  g_x2n [(size_t)2*128*HWC];    // rmsnorm(x2)
static __device__ float g_x1  [(size_t)2*128*HWC];
static __device__ float g_x2  [(size_t)2*128*HWC];

__device__ __forceinline__ float gelu_erf(float v) {
    return 0.5f * v * (1.0f + erff(v * 0.70710678118654752f));
}
__device__ __forceinline__ uint32_t smem_u32(const void* p) {
    uint32_t a;
    asm("{ .reg .u64 t; cvta.to.shared.u64 t, %1; cvt.u32.u64 %0, t; }" : "=r"(a) : "l"(p));
    return a;
}
__device__ __forceinline__ void cpa16(void* dst, const void* src) {
    uint32_t d = smem_u32(dst);
    asm volatile("cp.async.cg.shared.global [%0], [%1], 16;" :: "r"(d), "l"(src) : "memory");
}
#define CP_COMMIT() asm volatile("cp.async.commit_group;" ::: "memory")
#define CP_WAIT(n)  asm volatile("cp.async.wait_group %0;" :: "n"(n) : "memory")

__device__ __forceinline__ void ldsm4(uint32_t* r, uint32_t addr) {
    asm volatile("ldmatrix.sync.aligned.m8n8.x4.shared.b16 {%0,%1,%2,%3}, [%4];"
        : "=r"(r[0]), "=r"(r[1]), "=r"(r[2]), "=r"(r[3]) : "r"(addr));
}
__device__ __forceinline__ void ldsm4t(uint32_t* r, uint32_t addr) {
    asm volatile("ldmatrix.sync.aligned.m8n8.x4.trans.shared.b16 {%0,%1,%2,%3}, [%4];"
        : "=r"(r[0]), "=r"(r[1]), "=r"(r[2]), "=r"(r[3]) : "r"(addr));
}
__device__ __forceinline__ void mma16(float* c, const uint32_t* a, const uint32_t* b) {
    asm volatile("mma.sync.aligned.m16n8k16.row.col.f32.bf16.bf16.f32 "
        "{%0,%1,%2,%3}, {%4,%5,%6,%7}, {%8,%9}, {%0,%1,%2,%3};"
        : "+f"(c[0]), "+f"(c[1]), "+f"(c[2]), "+f"(c[3])
        : "r"(a[0]), "r"(a[1]), "r"(a[2]), "r"(a[3]), "r"(b[0]), "r"(b[1]));
}

// smem byte offsets
#define SH 136                // tile stride in halves
#define OFF_A0   0
#define OFF_A1   34816
#define OFF_B0   69632
#define OFF_B1   104448
#define OFF_BIAS 139264       // 512 floats
#define OFF_RS   141312       // 128 floats
#define OFF_RB   141824       // 128 floats
#define OFF_RBUF 142336       // 512 floats
#define SMB      144384

// =====================================================================
// bf16 mma GEMM (unchanged from round 5)
// =====================================================================
template<int KT, int MT, int MODE, bool RMSOUT>
__global__ void __launch_bounds__(512, 1)
tc_gemm(const bf16* __restrict__ in, const bf16* __restrict__ W,
        const float* __restrict__ bias,
        const float* __restrict__ res, const float* __restrict__ scale_ptr,
        float* __restrict__ out, bf16* __restrict__ outb,
        bf16* __restrict__ outn,
        const float* __restrict__ rs2, const float* __restrict__ rb2)
{
    constexpr int NSUB  = (MODE == 1) ? 2 : 1;
    constexpr int NS    = KT * MT * NSUB;
    constexpr int KTOT  = KT * 128;
    constexpr int OCOUT = (MODE == 1) ? 256 : MT * 128;
    constexpr int NBIAS = (MODE == 1) ? 512 : MT * 128;
    constexpr int NACC  = (MODE == 1) ? 2 : 1;

    extern __shared__ char sm[];
    float* bs   = (float*)(sm + OFF_BIAS);
    float* rsv  = (float*)(sm + OFF_RS);
    float* rbv  = (float*)(sm + OFF_RB);
    float* rbuf = (float*)(sm + OFF_RBUF);
    const uint32_t smb = smem_u32(sm);

    const int tid = threadIdx.x, lane = tid & 31, wid = tid >> 5;
    const int wm = wid & 3, wn = wid >> 2;
    const int gp = blockIdx.x * 128;
    const int b  = gp / HWC;
    const int p0 = gp - b * HWC;
    const bf16* inb = in + (size_t)b * KTOT * HWC + p0;

    for (int i = tid; i < NBIAS; i += 512) bs[i] = bias[i];
    if (RMSOUT) for (int i = tid; i < 128; i += 512) { rsv[i] = rs2[i]; rbv[i] = rb2[i]; }

    const int a_m = (lane & 7) + ((lane >> 3) & 1) * 8;
    const int a_k = (lane >> 4) * 8;
    const int b_k = (lane & 7) + ((lane >> 3) & 1) * 8;
    const int b_n = wn * 32 + (lane >> 4) * 8;

    float acc[NACC][2][4][4];

    {
        for (int i = tid; i < 2048; i += 512) {
            int c = i >> 4, p8 = (i & 15) * 8;
            cpa16(sm + OFF_B0 + (c * SH + p8) * 2, inb + (size_t)c * HWC + p8);
        }
        const bf16* wt = W;
        for (int i = tid; i < 2048; i += 512) {
            int o = i >> 4, k8 = (i & 15) * 8;
            cpa16(sm + OFF_A0 + (o * SH + k8) * 2, wt + (size_t)o * KTOT + k8);
        }
        CP_COMMIT();
    }

    #pragma unroll
    for (int s = 0; s < NS; ++s) {
        const int kc = (KT == 2) ? s : 0;
        __syncthreads();
        if (s + 1 < NS) {
            const int kcn = (KT == 2) ? (s + 1) : 0;
            if (kcn != kc) {
                char* bd = sm + ((kcn & 1) ? OFF_B1 : OFF_B0);
                for (int i = tid; i < 2048; i += 512) {
                    int c = i >> 4, p8 = (i & 15) * 8;
                    cpa16(bd + (c * SH + p8) * 2, inb + (size_t)(kcn * 128 + c) * HWC + p8);
                }
            }
            const int sn = s + 1;
            const int ocb = (MODE == 1) ? ((sn & 1) * 256 + (sn >> 1) * 128)
                          : ((MODE == 0) ? sn * 128 : 0);
            const bf16* wt = W + (size_t)ocb * KTOT + kcn * 128;
            char* ad = sm + ((sn & 1) ? OFF_A1 : OFF_A0);
            for (int i = tid; i < 2048; i += 512) {
                int o = i >> 4, k8 = (i & 15) * 8;
                cpa16(ad + (o * SH + k8) * 2, wt + (size_t)o * KTOT + k8);
            }
            CP_COMMIT();
            CP_WAIT(1);
        } else {
            CP_WAIT(0);
        }
        __syncthreads();

        const int sel = (MODE == 1) ? (s & 1) : 0;
        if (MODE != 2 || s == 0) {
            #pragma unroll
            for (int mi = 0; mi < 2; ++mi)
                #pragma unroll
                for (int j = 0; j < 4; ++j)
                    #pragma unroll
                    for (int q = 0; q < 4; ++q) acc[sel][mi][j][q] = 0.f;
        }

        {
            const uint32_t Ab = smb + ((s & 1) ? OFF_A1 : OFF_A0);
            const uint32_t Bb = smb + ((kc & 1) ? OFF_B1 : OFF_B0);
            const uint32_t aaddr = Ab + ((wm * 32 + a_m) * SH + a_k) * 2;
            const uint32_t baddr = Bb + (b_k * SH + b_n) * 2;
            #pragma unroll
            for (int k0 = 0; k0 < 128; k0 += 16) {
                uint32_t a0[4], a1[4], b0[4], b1[4];
                ldsm4 (a0, aaddr + k0 * 2);
                ldsm4 (a1, aaddr + (16 * SH + k0) * 2);
                ldsm4t(b0, baddr + k0 * SH * 2);
                ldsm4t(b1, baddr + (k0 * SH + 16) * 2);
                mma16(acc[sel][0][0], a0, b0 + 0);
                mma16(acc[sel][0][1], a0, b0 + 2);
                mma16(acc[sel][0][2], a0, b1 + 0);
                mma16(acc[sel][0][3], a0, b1 + 2);
                mma16(acc[sel][1][0], a1, b0 + 0);
                mma16(acc[sel][1][1], a1, b0 + 2);
                mma16(acc[sel][1][2], a1, b1 + 0);
                mma16(acc[sel][1][3], a1, b1 + 2);
            }
        }

        const int r0e = wm * 32 + (lane >> 2);
        const int c0e = wn * 32 + (lane & 3) * 2;

        if (MODE == 0 || (MODE == 1 && (s & 1))) {
            const int mt = (MODE == 1) ? (s >> 1) : s;
            __syncthreads();
            bf16* st = (bf16*)(sm + ((s & 1) ? OFF_A1 : OFF_A0));
            #pragma unroll
            for (int mi = 0; mi < 2; ++mi) {
                int o = r0e + mi * 16;
                if (MODE == 1) {
                    float bu1 = bs[mt * 128 + o],     bv1 = bs[256 + mt * 128 + o];
                    float bu2 = bs[mt * 128 + o + 8], bv2 = bs[256 + mt * 128 + o + 8];
                    #pragma unroll
                    for (int j = 0; j < 4; ++j) {
                        int c = c0e + j * 8;
                        float u0 = (acc[0][mi][j][0] + bu1) * gelu_erf(acc[1][mi][j][0] + bv1);
                        float u1 = (acc[0][mi][j][1] + bu1) * gelu_erf(acc[1][mi][j][1] + bv1);
                        float u2 = (acc[0][mi][j][2] + bu2) * gelu_erf(acc[1][mi][j][2] + bv2);
                        float u3 = (acc[0][mi][j][3] + bu2) * gelu_erf(acc[1][mi][j][3] + bv2);
                        *(__nv_bfloat162*)&st[o * SH + c] =
                            __halves2bfloat162(__float2bfloat16(u0), __float2bfloat16(u1));
                        *(__nv_bfloat162*)&st[(o + 8) * SH + c] =
                            __halves2bfloat162(__float2bfloat16(u2), __float2bfloat16(u3));
                    }
                } else {
                    float b1v = bs[mt * 128 + o], b2v = bs[mt * 128 + o + 8];
                    #pragma unroll
                    for (int j = 0; j < 4; ++j) {
                        int c = c0e + j * 8;
                        *(__nv_bfloat162*)&st[o * SH + c] =
                            __halves2bfloat162(__float2bfloat16(acc[0][mi][j][0] + b1v),
                                               __float2bfloat16(acc[0][mi][j][1] + b1v));
                        *(__nv_bfloat162*)&st[(o + 8) * SH + c] =
                            __halves2bfloat162(__float2bfloat16(acc[0][mi][j][2] + b2v),
                                               __float2bfloat16(acc[0][mi][j][3] + b2v));
                    }
                }
            }
            __syncthreads();
            for (int i = tid; i < 2048; i += 512) {
                int o = i >> 4, p8 = (i & 15) * 8;
                uint4 v = *(uint4*)&st[o * SH + p8];
                *(uint4*)(outb + (size_t)b * OCOUT * HWC
                          + (size_t)(mt * 128 + o) * HWC + p0 + p8) = v;
            }
        } else if (MODE == 2 && s == NS - 1) {
            __syncthreads();
            float* st = (float*)(sm + OFF_B0);
            #pragma unroll
            for (int mi = 0; mi < 2; ++mi) {
                int o = r0e + mi * 16;
                float b1v = bs[o], b2v = bs[o + 8];
                #pragma unroll
                for (int j = 0; j < 4; ++j) {
                    int c = c0e + j * 8;
                    st[o * 132 + c]           = acc[0][mi][j][0] + b1v;
                    st[o * 132 + c + 1]       = acc[0][mi][j][1] + b1v;
                    st[(o + 8) * 132 + c]     = acc[0][mi][j][2] + b2v;
                    st[(o + 8) * 132 + c + 1] = acc[0][mi][j][3] + b2v;
                }
            }
            __syncthreads();
            float scl = *scale_ptr;
            for (int i = tid; i < 4096; i += 512) {
                int o = i >> 5, p4 = (i & 31) * 4;
                float4 v = *(float4*)&st[o * 132 + p4];
                size_t oidx = (size_t)b * 128 * HWC + (size_t)o * HWC + p0 + p4;
                float4 rr = *(const float4*)(res + oidx);
                v.x = rr.x + scl * v.x; v.y = rr.y + scl * v.y;
                v.z = rr.z + scl * v.z; v.w = rr.w + scl * v.w;
                *(float4*)(out + oidx) = v;
                if (RMSOUT) *(float4*)&st[o * 132 + p4] = v;
            }
            if (RMSOUT) {
                __syncthreads();
                int px = tid & 127, part = tid >> 7;
                float ss = 0.f;
                #pragma unroll 8
                for (int c = part * 32; c < part * 32 + 32; ++c) {
                    float v = st[c * 132 + px]; ss += v * v;
                }
                rbuf[part * 128 + px] = ss;
                __syncthreads();
                if (tid < 128)
                    rbuf[tid] = rsqrtf((rbuf[tid] + rbuf[128 + tid] + rbuf[256 + tid]
                                      + rbuf[384 + tid]) * (1.0f / 128.0f) + 1e-6f);
                __syncthreads();
                for (int i = tid; i < 4096; i += 512) {
                    int o = i >> 5, p4 = (i & 31) * 4;
                    float sc = rsv[o], bb = rbv[o];
                    float4 v = *(float4*)&st[o * 132 + p4];
                    float n0 = rbuf[p4], n1 = rbuf[p4 + 1], n2 = rbuf[p4 + 2], n3 = rbuf[p4 + 3];
                    bf16* ob = outn + (size_t)b * 128 * HWC + (size_t)o * HWC + p0 + p4;
                    *(__nv_bfloat162*)ob =
                        __halves2bfloat162(__float2bfloat16(sc * v.x * n0 + bb),
                                           __float2bfloat16(sc * v.y * n1 + bb));
                    *(__nv_bfloat162*)(ob + 2) =
                        __halves2bfloat162(__float2bfloat16(sc * v.z * n2 + bb),
                                           __float2bfloat16(sc * v.w * n3 + bb));
                }
            }
        }
    }
}

// =====================================================================
// weight fp32 -> bf16
// =====================================================================
__global__ void wcvt_kernel(const float* p1, const float* p2, const float* p3,
                            const float* p4, const float* p5, const float* p6,
                            bf16* o)
{
    int i = blockIdx.x * 1024 + threadIdx.x * 4;
    const float* src; int base;
    if      (i < 65536)  { src = p1; base = 0; }
    else if (i < 98304)  { src = p2; base = 65536; }
    else if (i < 147456) { src = p3; base = 98304; }
    else if (i < 163840) { src = p4; base = 147456; }
    else if (i < 229376) { src = p5; base = 163840; }
    else                 { src = p6; base = 229376; }
    float4 v = *(const float4*)(src + (i - base));
    *(__nv_bfloat162*)(o + i)     = __halves2bfloat162(__float2bfloat16(v.x), __float2bfloat16(v.y));
    *(__nv_bfloat162*)(o + i + 2) = __halves2bfloat162(__float2bfloat16(v.z), __float2bfloat16(v.w));
}

// =====================================================================
// rmsnorm(x) -> bf16
// =====================================================================
__global__ void __launch_bounds__(512)
rms_prep(const float* __restrict__ x, const float* __restrict__ s,
         const float* __restrict__ bsh, bf16* __restrict__ xn)
{
    extern __shared__ float smf[];
    float* st = smf;
    float* rbuf = smf + 128 * 132;
    int tid = threadIdx.x;
    int gp = blockIdx.x * 128;
    int b = gp / HWC, p0 = gp - b * HWC;
    const float* xb = x + (size_t)b * 128 * HWC + p0;
    for (int i = tid; i < 4096; i += 512) {
        int c = i >> 5, p4 = (i & 31) * 4;
        *(float4*)&st[c * 132 + p4] = *(const float4*)(xb + (size_t)c * HWC + p4);
    }
    __syncthreads();
    int px = tid & 127, part = tid >> 7;
    float ss = 0.f;
    #pragma unroll 8
    for (int c = part * 32; c < part * 32 + 32; ++c) { float v = st[c * 132 + px]; ss += v * v; }
    rbuf[part * 128 + px] = ss;
    __syncthreads();
    if (tid < 128)
        rbuf[tid] = rsqrtf((rbuf[tid] + rbuf[128 + tid] + rbuf[256 + tid] + rbuf[384 + tid])
                           * (1.0f / 128.0f) + 1e-6f);
    __syncthreads();
    bf16* ob = xn + (size_t)b * 128 * HWC + p0;
    for (int i = tid; i < 4096; i += 512) {
        int c = i >> 5, p4 = (i & 31) * 4;
        float sc = s[c], bb = bsh[c];
        float4 v = *(float4*)&st[c * 132 + p4];
        float n0 = rbuf[p4], n1 = rbuf[p4 + 1], n2 = rbuf[p4 + 2], n3 = rbuf[p4 + 3];
        *(__nv_bfloat162*)(ob + (size_t)c * HWC + p4) =
            __halves2bfloat162(__float2bfloat16(sc * v.x * n0 + bb),
                               __float2bfloat16(sc * v.y * n1 + bb));
        *(__nv_bfloat162*)(ob + (size_t)c * HWC + p4 + 2) =
            __halves2bfloat162(__float2bfloat16(sc * v.z * n2 + bb),
                               __float2bfloat16(sc * v.w * n3 + bb));
    }
}

// =====================================================================
// Depthwise 3x3 + bias + gated GELU — REWRITTEN: 32x32 tiles, 2x2
// outputs/thread, register neighborhood reuse, weights in registers.
// grid: b(2) * ch(256) * 36 tiles, 256 threads.
// =====================================================================
__global__ void __launch_bounds__(256)
dwgate_kernel(const bf16* __restrict__ a, const float* __restrict__ dw,
              const float* __restrict__ db, bf16* __restrict__ out)
{
    __shared__ float su[34 * 36], sv[34 * 36];
    int blk  = blockIdx.x;
    int tile = blk % 36;
    int cp   = (blk / 36) & 255;
    int b    = blk / (36 * 256);
    int ty0 = (tile / 6) * 32, tx0 = (tile % 6) * 32;
    const bf16* ua = a + ((size_t)b * 512 + cp) * HWC;
    const bf16* va = ua + (size_t)256 * HWC;

    // halo fill: 34x34 per plane
    for (int i = threadIdx.x; i < 34 * 34; i += 256) {
        int ly = i / 34, lx = i - ly * 34;
        int gy = ty0 + ly - 1, gx = tx0 + lx - 1;
        bool ok = ((unsigned)gy < (unsigned)IMG) && ((unsigned)gx < (unsigned)IMG);
        int gi = gy * IMG + gx;
        su[ly * 36 + lx] = ok ? __bfloat162float(ua[gi]) : 0.f;
        sv[ly * 36 + lx] = ok ? __bfloat162float(va[gi]) : 0.f;
    }
    // weights to registers (once per block)
    float wu[9], wv[9];
    #pragma unroll
    for (int i = 0; i < 9; ++i) {
        wu[i] = dw[cp * 9 + i];
        wv[i] = dw[(cp + 256) * 9 + i];
    }
    float bu = db[cp], bv = db[cp + 256];
    __syncthreads();

    int y0 = (threadIdx.x >> 4) * 2, x0 = (threadIdx.x & 15) * 2;
    // 4x4 register neighborhoods
    float U[4][4], V[4][4];
    #pragma unroll
    for (int i = 0; i < 4; ++i)
        #pragma unroll
        for (int j = 0; j < 4; ++j) {
            U[i][j] = su[(y0 + i) * 36 + x0 + j];
            V[i][j] = sv[(y0 + i) * 36 + x0 + j];
        }

    bf16* ob = out + ((size_t)b * 256 + cp) * HWC;
    #pragma unroll
    for (int dy = 0; dy < 2; ++dy) {
        float r[2];
        #pragma unroll
        for (int dx = 0; dx < 2; ++dx) {
            float u = bu, v = bv;
            #pragma unroll
            for (int i = 0; i < 3; ++i)
                #pragma unroll
                for (int j = 0; j < 3; ++j) {
                    u = fmaf(U[dy + i][dx + j], wu[i * 3 + j], u);
                    v = fmaf(V[dy + i][dx + j], wv[i * 3 + j], v);
                }
            r[dx] = u * gelu_erf(v);
        }
        *(__nv_bfloat162*)&ob[(ty0 + y0 + dy) * IMG + tx0 + x0] =
            __halves2bfloat162(__float2bfloat16(r[0]), __float2bfloat16(r[1]));
    }
}

// =====================================================================
// Attention (unchanged)
// =====================================================================
__global__ void __launch_bounds__(64)
attn2_kernel(const bf16* __restrict__ qkv, const float* __restrict__ rpe,
             bf16* __restrict__ aog)
{
    __shared__ float Ks[64 * 36], Vs[64 * 36], rpe_s[225], outs[64 * 33];
    __shared__ int pix[64], lk[64];
    int w = blockIdx.x >> 2, head = blockIdx.x & 3;
    int tid = threadIdx.x;
    int b = w / NWPB, wrem = w - b * NWPB;
    int wy = wrem / NWSIDE, wx = wrem - wy * NWSIDE;
    int qy = tid >> 3, qx = tid & 7;
    {
        int gh = wy * 8 + qy + 4; if (gh >= IMG) gh -= IMG;
        int gw = wx * 8 + qx + 4; if (gw >= IMG) gw -= IMG;
        pix[tid] = gh * IMG + gw;
    }
    {
        int gh = wy * 8 + qy, gw = wx * 8 + qx;
        int lh = gh < 184 ? 0 : (gh < 188 ? 1 : 2);
        int lw = gw < 184 ? 0 : (gw < 188 ? 1 : 2);
        lk[tid] = lh * 3 + lw;
    }
    for (int i = tid; i < 225; i += 64) rpe_s[i] = rpe[i * 4 + head];
    __syncthreads();

    const bf16* qb = qkv + (size_t)b * 384 * HWC + (size_t)(head * 32) * HWC;
    const bf16* kb = qb + (size_t)128 * HWC;
    const bf16* vb = qb + (size_t)256 * HWC;
    int myp = pix[tid];
    float q[32];
    #pragma unroll
    for (int d = 0; d < 32; ++d) {
        q[d] = __bfloat162float(qb[(size_t)d * HWC + myp]) * 0.17677669529663687f;
        Ks[tid * 36 + d] = __bfloat162float(kb[(size_t)d * HWC + myp]);
        Vs[tid * 36 + d] = __bfloat162float(vb[(size_t)d * HWC + myp]);
    }
    int lab = lk[tid];
    __syncthreads();

    float sc[64];
    float mx = -1e30f;
    #pragma unroll
    for (int kk = 0; kk < 64; ++kk) {
        const float4* kp = (const float4*)(Ks + kk * 36);
        float dot = 0.f;
        #pragma unroll
        for (int d4 = 0; d4 < 8; ++d4) {
            float4 kv = kp[d4];
            dot = fmaf(q[d4 * 4 + 0], kv.x, dot);
            dot = fmaf(q[d4 * 4 + 1], kv.y, dot);
            dot = fmaf(q[d4 * 4 + 2], kv.z, dot);
            dot = fmaf(q[d4 * 4 + 3], kv.w, dot);
        }
        int ky = kk >> 3, kx = kk & 7;
        dot += rpe_s[(qy - ky + 7) * 15 + (qx - kx + 7)];
        if (lab != lk[kk]) dot = -1e30f;
        sc[kk] = dot;
        mx = fmaxf(mx, dot);
    }
    float sum = 0.f;
    #pragma unroll
    for (int kk = 0; kk < 64; ++kk) {
        float e = __expf(sc[kk] - mx);
        sc[kk] = e; sum += e;
    }
    float inv = 1.0f / sum;
    float acc[32];
    #pragma unroll
    for (int d = 0; d < 32; ++d) acc[d] = 0.f;
    #pragma unroll
    for (int kk = 0; kk < 64; ++kk) {
        float p = sc[kk];
        const float4* vp = (const float4*)(Vs + kk * 36);
        #pragma unroll
        for (int d4 = 0; d4 < 8; ++d4) {
            float4 vv = vp[d4];
            acc[d4 * 4 + 0] = fmaf(p, vv.x, acc[d4 * 4 + 0]);
            acc[d4 * 4 + 1] = fmaf(p, vv.y, acc[d4 * 4 + 1]);
            acc[d4 * 4 + 2] = fmaf(p, vv.z, acc[d4 * 4 + 2]);
            acc[d4 * 4 + 3] = fmaf(p, vv.w, acc[d4 * 4 + 3]);
        }
    }
    #pragma unroll
    for (int d = 0; d < 32; ++d) outs[tid * 33 + d] = acc[d] * inv;
    __syncthreads();
    size_t cb = (size_t)b * 128 * HWC + (size_t)(head * 32) * HWC;
    #pragma unroll
    for (int d = 0; d < 32; ++d)
        aog[cb + (size_t)d * HWC + myp] = __float2bfloat16(outs[tid * 33 + d]);
}

// =====================================================================
extern "C" void kernel_launch(void* const* d_in, const int* in_sizes, int n_in,
                              void* d_out, int out_size)
{
    const float* x      = (const float*)d_in[0];
    const float* cg_s   = (const float*)d_in[1];
    const float* cg_b   = (const float*)d_in[2];
    const float* pw1_w  = (const float*)d_in[3];
    const float* pw1_b  = (const float*)d_in[4];
    const float* dw_w   = (const float*)d_in[5];
    const float* dw_b   = (const float*)d_in[6];
    const float* pw2_w  = (const float*)d_in[7];
    const float* pw2_b  = (const float*)d_in[8];
    const float* beta   = (const float*)d_in[9];
    const float* at_s   = (const float*)d_in[10];
    const float* at_b   = (const float*)d_in[11];
    const float* qkv_w  = (const float*)d_in[12];
    const float* qkv_b  = (const float*)d_in[13];
    const float* rpe    = (const float*)d_in[14];
    const float* proj_w = (const float*)d_in[15];
    const float* proj_b = (const float*)d_in[16];
    const float* alpha  = (const float*)d_in[17];
    const float* ff_s   = (const float*)d_in[18];
    const float* ff_b   = (const float*)d_in[19];
    const float* fc1_w  = (const float*)d_in[20];
    const float* fc1_b  = (const float*)d_in[21];
    const float* fc2_w  = (const float*)d_in[22];
    const float* fc2_b  = (const float*)d_in[23];
    const float* gamma  = (const float*)d_in[24];
    float* out = (float*)d_out;

    bf16 *wbf, *xn, *a512, *g256, *qkvb, *aob, *x1n, *x2n;
    float *x1, *x2;
    cudaGetSymbolAddress((void**)&wbf,  g_wbf);
    cudaGetSymbolAddress((void**)&xn,   g_xn);
    cudaGetSymbolAddress((void**)&a512, g_a512);
    cudaGetSymbolAddress((void**)&g256, g_g256);
    cudaGetSymbolAddress((void**)&qkvb, g_qkv);
    cudaGetSymbolAddress((void**)&aob,  g_ao);
    cudaGetSymbolAddress((void**)&x1n,  g_x1n);
    cudaGetSymbolAddress((void**)&x2n,  g_x2n);
    cudaGetSymbolAddress((void**)&x1,   g_x1);
    cudaGetSymbolAddress((void**)&x2,   g_x2);

    cudaFuncSetAttribute(tc_gemm<1, 4, 0, false>, cudaFuncAttributeMaxDynamicSharedMemorySize, SMB);
    cudaFuncSetAttribute(tc_gemm<1, 3, 0, false>, cudaFuncAttributeMaxDynamicSharedMemorySize, SMB);
    cudaFuncSetAttribute(tc_gemm<2, 1, 2, true >, cudaFuncAttributeMaxDynamicSharedMemorySize, SMB);
    cudaFuncSetAttribute(tc_gemm<1, 1, 2, true >, cudaFuncAttributeMaxDynamicSharedMemorySize, SMB);
    cudaFuncSetAttribute(tc_gemm<1, 2, 1, false>, cudaFuncAttributeMaxDynamicSharedMemorySize, SMB);
    cudaFuncSetAttribute(tc_gemm<2, 1, 2, false>, cudaFuncAttributeMaxDynamicSharedMemorySize, SMB);
    cudaFuncSetAttribute(rms_prep, cudaFuncAttributeMaxDynamicSharedMemorySize, 69632);

    // ---- prep ----
    wcvt_kernel<<<256, 256>>>(pw1_w, pw2_w, qkv_w, proj_w, fc1_w, fc2_w, wbf);
    rms_prep<<<576, 512, 69632>>>(x, cg_s, cg_b, xn);

    // ---- conv gated block ----
    tc_gemm<1, 4, 0, false><<<576, 512, SMB>>>(
        xn, wbf + 0, pw1_b, nullptr, nullptr, nullptr, a512, nullptr, nullptr, nullptr);
    dwgate_kernel<<<2 * 256 * 36, 256>>>(a512, dw_w, dw_b, g256);
    tc_gemm<2, 1, 2, true><<<576, 512, SMB>>>(
        g256, wbf + 65536, pw2_b, x, beta, x1, nullptr, x1n, at_s, at_b);

    // ---- window attention ----
    tc_gemm<1, 3, 0, false><<<576, 512, SMB>>>(
        x1n, wbf + 98304, qkv_b, nullptr, nullptr, nullptr, qkvb, nullptr, nullptr, nullptr);
    attn2_kernel<<<NWTOT * 4, 64>>>(qkvb, rpe, aob);
    tc_gemm<1, 1, 2, true><<<576, 512, SMB>>>(
        aob, wbf + 147456, proj_b, x1, alpha, x2, nullptr, x2n, ff_s, ff_b);

    // ---- gated FFN ----
    tc_gemm<1, 2, 1, false><<<576, 512, SMB>>>(
        x2n, wbf + 163840, fc1_b, nullptr, nullptr, nullptr, g256, nullptr, nullptr, nullptr);
    tc_gemm<2, 1, 2, false><<<576, 512, SMB>>>(
        g256, wbf + 229376, fc2_b, x2, gamma, out, nullptr, nullptr, nullptr, nullptr);
}

// round 7
// speedup vs baseline: 4.1481x; 1.0553x over previous
#include <cuda_runtime.h>
#include <cuda_bf16.h>
#include <math.h>
#include <stdint.h>

#define IMG 192
#define HWC (192*192)
#define NWSIDE 24
#define NWPB 576
#define NWTOT 1152
typedef __nv_bfloat16 bf16;

// ---------------- scratch (device globals) ----------------
static __device__ bf16  g_wbf [262144];               // all weights bf16
static __device__ bf16  g_xn  [(size_t)2*128*HWC];    // rmsnorm(x)
static __device__ bf16  g_a512[(size_t)2*512*HWC];    // pw1 out
static __device__ bf16  g_g256[(size_t)2*256*HWC];    // dwgate out / fc1 out
static __device__ bf16  g_qkv [(size_t)2*384*HWC];    // qkv out
static __device__ bf16  g_ao  [(size_t)2*128*HWC];    // attn out
static __device__ bf16  g_x1n [(size_t)2*128*HWC];    // rmsnorm(x1)
static __device__ bf16  g_x2n [(size_t)2*128*HWC];    // rmsnorm(x2)
static __device__ float g_x1  [(size_t)2*128*HWC];
static __device__ float g_x2  [(size_t)2*128*HWC];

__device__ __forceinline__ float gelu_erf(float v) {
    return 0.5f * v * (1.0f + erff(v * 0.70710678118654752f));
}
__device__ __forceinline__ uint32_t smem_u32(const void* p) {
    uint32_t a;
    asm("{ .reg .u64 t; cvta.to.shared.u64 t, %1; cvt.u32.u64 %0, t; }" : "=r"(a) : "l"(p));
    return a;
}
__device__ __forceinline__ void cpa16(void* dst, const void* src) {
    uint32_t d = smem_u32(dst);
    asm volatile("cp.async.cg.shared.global [%0], [%1], 16;" :: "r"(d), "l"(src) : "memory");
}
#define CP_COMMIT() asm volatile("cp.async.commit_group;" ::: "memory")
#define CP_WAIT(n)  asm volatile("cp.async.wait_group %0;" :: "n"(n) : "memory")

__device__ __forceinline__ void ldsm4(uint32_t* r, uint32_t addr) {
    asm volatile("ldmatrix.sync.aligned.m8n8.x4.shared.b16 {%0,%1,%2,%3}, [%4];"
        : "=r"(r[0]), "=r"(r[1]), "=r"(r[2]), "=r"(r[3]) : "r"(addr));
}
__device__ __forceinline__ void ldsm4t(uint32_t* r, uint32_t addr) {
    asm volatile("ldmatrix.sync.aligned.m8n8.x4.trans.shared.b16 {%0,%1,%2,%3}, [%4];"
        : "=r"(r[0]), "=r"(r[1]), "=r"(r[2]), "=r"(r[3]) : "r"(addr));
}
__device__ __forceinline__ void mma16(float* c, const uint32_t* a, const uint32_t* b) {
    asm volatile("mma.sync.aligned.m16n8k16.row.col.f32.bf16.bf16.f32 "
        "{%0,%1,%2,%3}, {%4,%5,%6,%7}, {%8,%9}, {%0,%1,%2,%3};"
        : "+f"(c[0]), "+f"(c[1]), "+f"(c[2]), "+f"(c[3])
        : "r"(a[0]), "r"(a[1]), "r"(a[2]), "r"(a[3]), "r"(b[0]), "r"(b[1]));
}

// smem byte offsets
#define SH 136                // tile stride in halves
#define OFF_A0   0
#define OFF_A1   34816
#define OFF_B0   69632
#define OFF_B1   104448
#define OFF_BIAS 139264       // 512 floats
#define OFF_RS   141312       // 128 floats
#define OFF_RB   141824       // 128 floats
#define OFF_RBUF 142336       // 512 floats
#define SMB      144384

// =====================================================================
// bf16 mma GEMM (unchanged)
// =====================================================================
template<int KT, int MT, int MODE, bool RMSOUT>
__global__ void __launch_bounds__(512, 1)
tc_gemm(const bf16* __restrict__ in, const bf16* __restrict__ W,
        const float* __restrict__ bias,
        const float* __restrict__ res, const float* __restrict__ scale_ptr,
        float* __restrict__ out, bf16* __restrict__ outb,
        bf16* __restrict__ outn,
        const float* __restrict__ rs2, const float* __restrict__ rb2)
{
    constexpr int NSUB  = (MODE == 1) ? 2 : 1;
    constexpr int NS    = KT * MT * NSUB;
    constexpr int KTOT  = KT * 128;
    constexpr int OCOUT = (MODE == 1) ? 256 : MT * 128;
    constexpr int NBIAS = (MODE == 1) ? 512 : MT * 128;
    constexpr int NACC  = (MODE == 1) ? 2 : 1;

    extern __shared__ char sm[];
    float* bs   = (float*)(sm + OFF_BIAS);
    float* rsv  = (float*)(sm + OFF_RS);
    float* rbv  = (float*)(sm + OFF_RB);
    float* rbuf = (float*)(sm + OFF_RBUF);
    const uint32_t smb = smem_u32(sm);

    const int tid = threadIdx.x, lane = tid & 31, wid = tid >> 5;
    const int wm = wid & 3, wn = wid >> 2;
    const int gp = blockIdx.x * 128;
    const int b  = gp / HWC;
    const int p0 = gp - b * HWC;
    const bf16* inb = in + (size_t)b * KTOT * HWC + p0;

    for (int i = tid; i < NBIAS; i += 512) bs[i] = bias[i];
    if (RMSOUT) for (int i = tid; i < 128; i += 512) { rsv[i] = rs2[i]; rbv[i] = rb2[i]; }

    const int a_m = (lane & 7) + ((lane >> 3) & 1) * 8;
    const int a_k = (lane >> 4) * 8;
    const int b_k = (lane & 7) + ((lane >> 3) & 1) * 8;
    const int b_n = wn * 32 + (lane >> 4) * 8;

    float acc[NACC][2][4][4];

    {
        for (int i = tid; i < 2048; i += 512) {
            int c = i >> 4, p8 = (i & 15) * 8;
            cpa16(sm + OFF_B0 + (c * SH + p8) * 2, inb + (size_t)c * HWC + p8);
        }
        const bf16* wt = W;
        for (int i = tid; i < 2048; i += 512) {
            int o = i >> 4, k8 = (i & 15) * 8;
            cpa16(sm + OFF_A0 + (o * SH + k8) * 2, wt + (size_t)o * KTOT + k8);
        }
        CP_COMMIT();
    }

    #pragma unroll
    for (int s = 0; s < NS; ++s) {
        const int kc = (KT == 2) ? s : 0;
        __syncthreads();
        if (s + 1 < NS) {
            const int kcn = (KT == 2) ? (s + 1) : 0;
            if (kcn != kc) {
                char* bd = sm + ((kcn & 1) ? OFF_B1 : OFF_B0);
                for (int i = tid; i < 2048; i += 512) {
                    int c = i >> 4, p8 = (i & 15) * 8;
                    cpa16(bd + (c * SH + p8) * 2, inb + (size_t)(kcn * 128 + c) * HWC + p8);
                }
            }
            const int sn = s + 1;
            const int ocb = (MODE == 1) ? ((sn & 1) * 256 + (sn >> 1) * 128)
                          : ((MODE == 0) ? sn * 128 : 0);
            const bf16* wt = W + (size_t)ocb * KTOT + kcn * 128;
            char* ad = sm + ((sn & 1) ? OFF_A1 : OFF_A0);
            for (int i = tid; i < 2048; i += 512) {
                int o = i >> 4, k8 = (i & 15) * 8;
                cpa16(ad + (o * SH + k8) * 2, wt + (size_t)o * KTOT + k8);
            }
            CP_COMMIT();
            CP_WAIT(1);
        } else {
            CP_WAIT(0);
        }
        __syncthreads();

        const int sel = (MODE == 1) ? (s & 1) : 0;
        if (MODE != 2 || s == 0) {
            #pragma unroll
            for (int mi = 0; mi < 2; ++mi)
                #pragma unroll
                for (int j = 0; j < 4; ++j)
                    #pragma unroll
                    for (int q = 0; q < 4; ++q) acc[sel][mi][j][q] = 0.f;
        }

        {
            const uint32_t Ab = smb + ((s & 1) ? OFF_A1 : OFF_A0);
            const uint32_t Bb = smb + ((kc & 1) ? OFF_B1 : OFF_B0);
            const uint32_t aaddr = Ab + ((wm * 32 + a_m) * SH + a_k) * 2;
            const uint32_t baddr = Bb + (b_k * SH + b_n) * 2;
            #pragma unroll
            for (int k0 = 0; k0 < 128; k0 += 16) {
                uint32_t a0[4], a1[4], b0[4], b1[4];
                ldsm4 (a0, aaddr + k0 * 2);
                ldsm4 (a1, aaddr + (16 * SH + k0) * 2);
                ldsm4t(b0, baddr + k0 * SH * 2);
                ldsm4t(b1, baddr + (k0 * SH + 16) * 2);
                mma16(acc[sel][0][0], a0, b0 + 0);
                mma16(acc[sel][0][1], a0, b0 + 2);
                mma16(acc[sel][0][2], a0, b1 + 0);
                mma16(acc[sel][0][3], a0, b1 + 2);
                mma16(acc[sel][1][0], a1, b0 + 0);
                mma16(acc[sel][1][1], a1, b0 + 2);
                mma16(acc[sel][1][2], a1, b1 + 0);
                mma16(acc[sel][1][3], a1, b1 + 2);
            }
        }

        const int r0e = wm * 32 + (lane >> 2);
        const int c0e = wn * 32 + (lane & 3) * 2;

        if (MODE == 0 || (MODE == 1 && (s & 1))) {
            const int mt = (MODE == 1) ? (s >> 1) : s;
            __syncthreads();
            bf16* st = (bf16*)(sm + ((s & 1) ? OFF_A1 : OFF_A0));
            #pragma unroll
            for (int mi = 0; mi < 2; ++mi) {
                int o = r0e + mi * 16;
                if (MODE == 1) {
                    float bu1 = bs[mt * 128 + o],     bv1 = bs[256 + mt * 128 + o];
                    float bu2 = bs[mt * 128 + o + 8], bv2 = bs[256 + mt * 128 + o + 8];
                    #pragma unroll
                    for (int j = 0; j < 4; ++j) {
                        int c = c0e + j * 8;
                        float u0 = (acc[0][mi][j][0] + bu1) * gelu_erf(acc[1][mi][j][0] + bv1);
                        float u1 = (acc[0][mi][j][1] + bu1) * gelu_erf(acc[1][mi][j][1] + bv1);
                        float u2 = (acc[0][mi][j][2] + bu2) * gelu_erf(acc[1][mi][j][2] + bv2);
                        float u3 = (acc[0][mi][j][3] + bu2) * gelu_erf(acc[1][mi][j][3] + bv2);
                        *(__nv_bfloat162*)&st[o * SH + c] =
                            __halves2bfloat162(__float2bfloat16(u0), __float2bfloat16(u1));
                        *(__nv_bfloat162*)&st[(o + 8) * SH + c] =
                            __halves2bfloat162(__float2bfloat16(u2), __float2bfloat16(u3));
                    }
                } else {
                    float b1v = bs[mt * 128 + o], b2v = bs[mt * 128 + o + 8];
                    #pragma unroll
                    for (int j = 0; j < 4; ++j) {
                        int c = c0e + j * 8;
                        *(__nv_bfloat162*)&st[o * SH + c] =
                            __halves2bfloat162(__float2bfloat16(acc[0][mi][j][0] + b1v),
                                               __float2bfloat16(acc[0][mi][j][1] + b1v));
                        *(__nv_bfloat162*)&st[(o + 8) * SH + c] =
                            __halves2bfloat162(__float2bfloat16(acc[0][mi][j][2] + b2v),
                                               __float2bfloat16(acc[0][mi][j][3] + b2v));
                    }
                }
            }
            __syncthreads();
            for (int i = tid; i < 2048; i += 512) {
                int o = i >> 4, p8 = (i & 15) * 8;
                uint4 v = *(uint4*)&st[o * SH + p8];
                *(uint4*)(outb + (size_t)b * OCOUT * HWC
                          + (size_t)(mt * 128 + o) * HWC + p0 + p8) = v;
            }
        } else if (MODE == 2 && s == NS - 1) {
            __syncthreads();
            float* st = (float*)(sm + OFF_B0);
            #pragma unroll
            for (int mi = 0; mi < 2; ++mi) {
                int o = r0e + mi * 16;
                float b1v = bs[o], b2v = bs[o + 8];
                #pragma unroll
                for (int j = 0; j < 4; ++j) {
                    int c = c0e + j * 8;
                    st[o * 132 + c]           = acc[0][mi][j][0] + b1v;
                    st[o * 132 + c + 1]       = acc[0][mi][j][1] + b1v;
                    st[(o + 8) * 132 + c]     = acc[0][mi][j][2] + b2v;
                    st[(o + 8) * 132 + c + 1] = acc[0][mi][j][3] + b2v;
                }
            }
            __syncthreads();
            float scl = *scale_ptr;
            for (int i = tid; i < 4096; i += 512) {
                int o = i >> 5, p4 = (i & 31) * 4;
                float4 v = *(float4*)&st[o * 132 + p4];
                size_t oidx = (size_t)b * 128 * HWC + (size_t)o * HWC + p0 + p4;
                float4 rr = *(const float4*)(res + oidx);
                v.x = rr.x + scl * v.x; v.y = rr.y + scl * v.y;
                v.z = rr.z + scl * v.z; v.w = rr.w + scl * v.w;
                *(float4*)(out + oidx) = v;
                if (RMSOUT) *(float4*)&st[o * 132 + p4] = v;
            }
            if (RMSOUT) {
                __syncthreads();
                int px = tid & 127, part = tid >> 7;
                float ss = 0.f;
                #pragma unroll 8
                for (int c = part * 32; c < part * 32 + 32; ++c) {
                    float v = st[c * 132 + px]; ss += v * v;
                }
                rbuf[part * 128 + px] = ss;
                __syncthreads();
                if (tid < 128)
                    rbuf[tid] = rsqrtf((rbuf[tid] + rbuf[128 + tid] + rbuf[256 + tid]
                                      + rbuf[384 + tid]) * (1.0f / 128.0f) + 1e-6f);
                __syncthreads();
                for (int i = tid; i < 4096; i += 512) {
                    int o = i >> 5, p4 = (i & 31) * 4;
                    float sc = rsv[o], bb = rbv[o];
                    float4 v = *(float4*)&st[o * 132 + p4];
                    float n0 = rbuf[p4], n1 = rbuf[p4 + 1], n2 = rbuf[p4 + 2], n3 = rbuf[p4 + 3];
                    bf16* ob = outn + (size_t)b * 128 * HWC + (size_t)o * HWC + p0 + p4;
                    *(__nv_bfloat162*)ob =
                        __halves2bfloat162(__float2bfloat16(sc * v.x * n0 + bb),
                                           __float2bfloat16(sc * v.y * n1 + bb));
                    *(__nv_bfloat162*)(ob + 2) =
                        __halves2bfloat162(__float2bfloat16(sc * v.z * n2 + bb),
                                           __float2bfloat16(sc * v.w * n3 + bb));
                }
            }
        }
    }
}

// =====================================================================
// weight fp32 -> bf16
// =====================================================================
__global__ void wcvt_kernel(const float* p1, const float* p2, const float* p3,
                            const float* p4, const float* p5, const float* p6,
                            bf16* o)
{
    int i = blockIdx.x * 1024 + threadIdx.x * 4;
    const float* src; int base;
    if      (i < 65536)  { src = p1; base = 0; }
    else if (i < 98304)  { src = p2; base = 65536; }
    else if (i < 147456) { src = p3; base = 98304; }
    else if (i < 163840) { src = p4; base = 147456; }
    else if (i < 229376) { src = p5; base = 163840; }
    else                 { src = p6; base = 229376; }
    float4 v = *(const float4*)(src + (i - base));
    *(__nv_bfloat162*)(o + i)     = __halves2bfloat162(__float2bfloat16(v.x), __float2bfloat16(v.y));
    *(__nv_bfloat162*)(o + i + 2) = __halves2bfloat162(__float2bfloat16(v.z), __float2bfloat16(v.w));
}

// =====================================================================
// rmsnorm(x) -> bf16
// =====================================================================
__global__ void __launch_bounds__(512)
rms_prep(const float* __restrict__ x, const float* __restrict__ s,
         const float* __restrict__ bsh, bf16* __restrict__ xn)
{
    extern __shared__ float smf[];
    float* st = smf;
    float* rbuf = smf + 128 * 132;
    int tid = threadIdx.x;
    int gp = blockIdx.x * 128;
    int b = gp / HWC, p0 = gp - b * HWC;
    const float* xb = x + (size_t)b * 128 * HWC + p0;
    for (int i = tid; i < 4096; i += 512) {
        int c = i >> 5, p4 = (i & 31) * 4;
        *(float4*)&st[c * 132 + p4] = *(const float4*)(xb + (size_t)c * HWC + p4);
    }
    __syncthreads();
    int px = tid & 127, part = tid >> 7;
    float ss = 0.f;
    #pragma unroll 8
    for (int c = part * 32; c < part * 32 + 32; ++c) { float v = st[c * 132 + px]; ss += v * v; }
    rbuf[part * 128 + px] = ss;
    __syncthreads();
    if (tid < 128)
        rbuf[tid] = rsqrtf((rbuf[tid] + rbuf[128 + tid] + rbuf[256 + tid] + rbuf[384 + tid])
                           * (1.0f / 128.0f) + 1e-6f);
    __syncthreads();
    bf16* ob = xn + (size_t)b * 128 * HWC + p0;
    for (int i = tid; i < 4096; i += 512) {
        int c = i >> 5, p4 = (i & 31) * 4;
        float sc = s[c], bb = bsh[c];
        float4 v = *(float4*)&st[c * 132 + p4];
        float n0 = rbuf[p4], n1 = rbuf[p4 + 1], n2 = rbuf[p4 + 2], n3 = rbuf[p4 + 3];
        *(__nv_bfloat162*)(ob + (size_t)c * HWC + p4) =
            __halves2bfloat162(__float2bfloat16(sc * v.x * n0 + bb),
                               __float2bfloat16(sc * v.y * n1 + bb));
        *(__nv_bfloat162*)(ob + (size_t)c * HWC + p4 + 2) =
            __halves2bfloat162(__float2bfloat16(sc * v.z * n2 + bb),
                               __float2bfloat16(sc * v.w * n3 + bb));
    }
}

// =====================================================================
// Depthwise 3x3 + bias + gated GELU — v3: vectorized bf162 halo fill
// (even-aligned halo window: pair validity is uniform), 2x2 out/thread.
// =====================================================================
__global__ void __launch_bounds__(256)
dwgate_kernel(const bf16* __restrict__ a, const float* __restrict__ dw,
              const float* __restrict__ db, bf16* __restrict__ out)
{
    __shared__ float su[34 * 40], sv[34 * 40];   // col i = gx (tx0-2+i)
    int blk  = blockIdx.x;
    int tile = blk % 36;
    int cp   = (blk / 36) & 255;
    int b    = blk / (36 * 256);
    int ty0 = (tile / 6) * 32, tx0 = (tile % 6) * 32;
    const bf16* ua = a + ((size_t)b * 512 + cp) * HWC;
    const bf16* va = ua + (size_t)256 * HWC;

    // halo fill: 34 rows x 18 aligned bf162 pairs (gx from tx0-2, even)
    #pragma unroll
    for (int it = 0; it < 3; ++it) {
        int i = threadIdx.x + it * 256;
        if (i < 34 * 18) {
            int ly = i / 18, px = i - ly * 18;
            int gy = ty0 + ly - 1;
            int gx = tx0 - 2 + px * 2;
            float2 uu = make_float2(0.f, 0.f), vv = make_float2(0.f, 0.f);
            if (((unsigned)gy < (unsigned)IMG) && ((unsigned)gx < (unsigned)IMG)) {
                int gi = gy * IMG + gx;
                uu = __bfloat1622float2(*(const __nv_bfloat162*)&ua[gi]);
                vv = __bfloat1622float2(*(const __nv_bfloat162*)&va[gi]);
            }
            *(float2*)&su[ly * 40 + px * 2] = uu;
            *(float2*)&sv[ly * 40 + px * 2] = vv;
        }
    }
    float wu[9], wv[9];
    #pragma unroll
    for (int i = 0; i < 9; ++i) {
        wu[i] = dw[cp * 9 + i];
        wv[i] = dw[(cp + 256) * 9 + i];
    }
    float bu = db[cp], bv = db[cp + 256];
    __syncthreads();

    int y0 = (threadIdx.x >> 4) * 2, x0 = (threadIdx.x & 15) * 2;
    // neighborhood: rows y0..y0+3 (smem row y0+i), cols x0-1..x0+2 (smem col x0+i+1)
    float U[4][4], V[4][4];
    #pragma unroll
    for (int i = 0; i < 4; ++i)
        #pragma unroll
        for (int j = 0; j < 4; ++j) {
            U[i][j] = su[(y0 + i) * 40 + x0 + j + 1];
            V[i][j] = sv[(y0 + i) * 40 + x0 + j + 1];
        }

    bf16* ob = out + ((size_t)b * 256 + cp) * HWC;
    #pragma unroll
    for (int dy = 0; dy < 2; ++dy) {
        float r[2];
        #pragma unroll
        for (int dx = 0; dx < 2; ++dx) {
            float u = bu, v = bv;
            #pragma unroll
            for (int i = 0; i < 3; ++i)
                #pragma unroll
                for (int j = 0; j < 3; ++j) {
                    u = fmaf(U[dy + i][dx + j], wu[i * 3 + j], u);
                    v = fmaf(V[dy + i][dx + j], wv[i * 3 + j], v);
                }
            r[dx] = u * gelu_erf(v);
        }
        *(__nv_bfloat162*)&ob[(ty0 + y0 + dy) * IMG + tx0 + x0] =
            __halves2bfloat162(__float2bfloat16(r[0]), __float2bfloat16(r[1]));
    }
}

// =====================================================================
// Attention: direct global store (no outs staging)
// =====================================================================
__global__ void __launch_bounds__(64)
attn2_kernel(const bf16* __restrict__ qkv, const float* __restrict__ rpe,
             bf16* __restrict__ aog)
{
    __shared__ float Ks[64 * 36], Vs[64 * 36], rpe_s[225];
    __shared__ int pix[64], lk[64];
    int w = blockIdx.x >> 2, head = blockIdx.x & 3;
    int tid = threadIdx.x;
    int b = w / NWPB, wrem = w - b * NWPB;
    int wy = wrem / NWSIDE, wx = wrem - wy * NWSIDE;
    int qy = tid >> 3, qx = tid & 7;
    {
        int gh = wy * 8 + qy + 4; if (gh >= IMG) gh -= IMG;
        int gw = wx * 8 + qx + 4; if (gw >= IMG) gw -= IMG;
        pix[tid] = gh * IMG + gw;
    }
    {
        int gh = wy * 8 + qy, gw = wx * 8 + qx;
        int lh = gh < 184 ? 0 : (gh < 188 ? 1 : 2);
        int lw = gw < 184 ? 0 : (gw < 188 ? 1 : 2);
        lk[tid] = lh * 3 + lw;
    }
    for (int i = tid; i < 225; i += 64) rpe_s[i] = rpe[i * 4 + head];
    __syncthreads();

    const bf16* qb = qkv + (size_t)b * 384 * HWC + (size_t)(head * 32) * HWC;
    const bf16* kb = qb + (size_t)128 * HWC;
    const bf16* vb = qb + (size_t)256 * HWC;
    int myp = pix[tid];
    float q[32];
    #pragma unroll
    for (int d = 0; d < 32; ++d) {
        q[d] = __bfloat162float(qb[(size_t)d * HWC + myp]) * 0.17677669529663687f;
        Ks[tid * 36 + d] = __bfloat162float(kb[(size_t)d * HWC + myp]);
        Vs[tid * 36 + d] = __bfloat162float(vb[(size_t)d * HWC + myp]);
    }
    int lab = lk[tid];
    __syncthreads();

    float sc[64];
    float mx = -1e30f;
    #pragma unroll
    for (int kk = 0; kk < 64; ++kk) {
        const float4* kp = (const float4*)(Ks + kk * 36);
        float dot = 0.f;
        #pragma unroll
        for (int d4 = 0; d4 < 8; ++d4) {
            float4 kv = kp[d4];
            dot = fmaf(q[d4 * 4 + 0], kv.x, dot);
            dot = fmaf(q[d4 * 4 + 1], kv.y, dot);
            dot = fmaf(q[d4 * 4 + 2], kv.z, dot);
            dot = fmaf(q[d4 * 4 + 3], kv.w, dot);
        }
        int ky = kk >> 3, kx = kk & 7;
        dot += rpe_s[(qy - ky + 7) * 15 + (qx - kx + 7)];
        if (lab != lk[kk]) dot = -1e30f;
        sc[kk] = dot;
        mx = fmaxf(mx, dot);
    }
    float sum = 0.f;
    #pragma unroll
    for (int kk = 0; kk < 64; ++kk) {
        float e = __expf(sc[kk] - mx);
        sc[kk] = e; sum += e;
    }
    float inv = 1.0f / sum;
    float acc[32];
    #pragma unroll
    for (int d = 0; d < 32; ++d) acc[d] = 0.f;
    #pragma unroll
    for (int kk = 0; kk < 64; ++kk) {
        float p = sc[kk];
        const float4* vp = (const float4*)(Vs + kk * 36);
        #pragma unroll
        for (int d4 = 0; d4 < 8; ++d4) {
            float4 vv = vp[d4];
            acc[d4 * 4 + 0] = fmaf(p, vv.x, acc[d4 * 4 + 0]);
            acc[d4 * 4 + 1] = fmaf(p, vv.y, acc[d4 * 4 + 1]);
            acc[d4 * 4 + 2] = fmaf(p, vv.z, acc[d4 * 4 + 2]);
            acc[d4 * 4 + 3] = fmaf(p, vv.w, acc[d4 * 4 + 3]);
        }
    }
    size_t cb = (size_t)b * 128 * HWC + (size_t)(head * 32) * HWC;
    #pragma unroll
    for (int d = 0; d < 32; ++d)
        aog[cb + (size_t)d * HWC + myp] = __float2bfloat16(acc[d] * inv);
}

// =====================================================================
extern "C" void kernel_launch(void* const* d_in, const int* in_sizes, int n_in,
                              void* d_out, int out_size)
{
    const float* x      = (const float*)d_in[0];
    const float* cg_s   = (const float*)d_in[1];
    const float* cg_b   = (const float*)d_in[2];
    const float* pw1_w  = (const float*)d_in[3];
    const float* pw1_b  = (const float*)d_in[4];
    const float* dw_w   = (const float*)d_in[5];
    const float* dw_b   = (const float*)d_in[6];
    const float* pw2_w  = (const float*)d_in[7];
    const float* pw2_b  = (const float*)d_in[8];
    const float* beta   = (const float*)d_in[9];
    const float* at_s   = (const float*)d_in[10];
    const float* at_b   = (const float*)d_in[11];
    const float* qkv_w  = (const float*)d_in[12];
    const float* qkv_b  = (const float*)d_in[13];
    const float* rpe    = (const float*)d_in[14];
    const float* proj_w = (const float*)d_in[15];
    const float* proj_b = (const float*)d_in[16];
    const float* alpha  = (const float*)d_in[17];
    const float* ff_s   = (const float*)d_in[18];
    const float* ff_b   = (const float*)d_in[19];
    const float* fc1_w  = (const float*)d_in[20];
    const float* fc1_b  = (const float*)d_in[21];
    const float* fc2_w  = (const float*)d_in[22];
    const float* fc2_b  = (const float*)d_in[23];
    const float* gamma  = (const float*)d_in[24];
    float* out = (float*)d_out;

    bf16 *wbf, *xn, *a512, *g256, *qkvb, *aob, *x1n, *x2n;
    float *x1, *x2;
    cudaGetSymbolAddress((void**)&wbf,  g_wbf);
    cudaGetSymbolAddress((void**)&xn,   g_xn);
    cudaGetSymbolAddress((void**)&a512, g_a512);
    cudaGetSymbolAddress((void**)&g256, g_g256);
    cudaGetSymbolAddress((void**)&qkvb, g_qkv);
    cudaGetSymbolAddress((void**)&aob,  g_ao);
    cudaGetSymbolAddress((void**)&x1n,  g_x1n);
    cudaGetSymbolAddress((void**)&x2n,  g_x2n);
    cudaGetSymbolAddress((void**)&x1,   g_x1);
    cudaGetSymbolAddress((void**)&x2,   g_x2);

    cudaFuncSetAttribute(tc_gemm<1, 4, 0, false>, cudaFuncAttributeMaxDynamicSharedMemorySize, SMB);
    cudaFuncSetAttribute(tc_gemm<1, 3, 0, false>, cudaFuncAttributeMaxDynamicSharedMemorySize, SMB);
    cudaFuncSetAttribute(tc_gemm<2, 1, 2, true >, cudaFuncAttributeMaxDynamicSharedMemorySize, SMB);
    cudaFuncSetAttribute(tc_gemm<1, 1, 2, true >, cudaFuncAttributeMaxDynamicSharedMemorySize, SMB);
    cudaFuncSetAttribute(tc_gemm<1, 2, 1, false>, cudaFuncAttributeMaxDynamicSharedMemorySize, SMB);
    cudaFuncSetAttribute(tc_gemm<2, 1, 2, false>, cudaFuncAttributeMaxDynamicSharedMemorySize, SMB);
    cudaFuncSetAttribute(rms_prep, cudaFuncAttributeMaxDynamicSharedMemorySize, 69632);

    // ---- prep ----
    wcvt_kernel<<<256, 256>>>(pw1_w, pw2_w, qkv_w, proj_w, fc1_w, fc2_w, wbf);
    rms_prep<<<576, 512, 69632>>>(x, cg_s, cg_b, xn);

    // ---- conv gated block ----
    tc_gemm<1, 4, 0, false><<<576, 512, SMB>>>(
        xn, wbf + 0, pw1_b, nullptr, nullptr, nullptr, a512, nullptr, nullptr, nullptr);
    dwgate_kernel<<<2 * 256 * 36, 256>>>(a512, dw_w, dw_b, g256);
    tc_gemm<2, 1, 2, true><<<576, 512, SMB>>>(
        g256, wbf + 65536, pw2_b, x, beta, x1, nullptr, x1n, at_s, at_b);

    // ---- window attention ----
    tc_gemm<1, 3, 0, false><<<576, 512, SMB>>>(
        x1n, wbf + 98304, qkv_b, nullptr, nullptr, nullptr, qkvb, nullptr, nullptr, nullptr);
    attn2_kernel<<<NWTOT * 4, 64>>>(qkvb, rpe, aob);
    tc_gemm<1, 1, 2, true><<<576, 512, SMB>>>(
        aob, wbf + 147456, proj_b, x1, alpha, x2, nullptr, x2n, ff_s, ff_b);

    // ---- gated FFN ----
    tc_gemm<1, 2, 1, false><<<576, 512, SMB>>>(
        x2n, wbf + 163840, fc1_b, nullptr, nullptr, nullptr, g256, nullptr, nullptr, nullptr);
    tc_gemm<2, 1, 2, false><<<576, 512, SMB>>>(
        g256, wbf + 229376, fc2_b, x2, gamma, out, nullptr, nullptr, nullptr, nullptr);
}

// round 8
// speedup vs baseline: 4.3177x; 1.0409x over previous
#include <cuda_runtime.h>
#include <cuda_bf16.h>
#include <math.h>
#include <stdint.h>

#define IMG 192
#define HWC (192*192)
#define NWSIDE 24
#define NWPB 576
#define NWTOT 1152
typedef __nv_bfloat16 bf16;

// ---------------- scratch (device globals) ----------------
static __device__ bf16  g_wbf [262144];               // all weights bf16
static __device__ bf16  g_xn  [(size_t)2*128*HWC];    // rmsnorm(x)
static __device__ bf16  g_a512[(size_t)2*512*HWC];    // pw1 out
static __device__ bf16  g_g256[(size_t)2*256*HWC];    // dwgate out / fc1 out
static __device__ bf16  g_qkv [(size_t)2*384*HWC];    // qkv out
static __device__ bf16  g_ao  [(size_t)2*128*HWC];    // attn out
static __device__ bf16  g_x1n [(size_t)2*128*HWC];    // rmsnorm(x1)
static __device__ bf16  g_x2n [(size_t)2*128*HWC];    // rmsnorm(x2)
static __device__ float g_x1  [(size_t)2*128*HWC];
static __device__ float g_x2  [(size_t)2*128*HWC];

__device__ __forceinline__ float gelu_erf(float v) {
    return 0.5f * v * (1.0f + erff(v * 0.70710678118654752f));
}
__device__ __forceinline__ uint32_t smem_u32(const void* p) {
    uint32_t a;
    asm("{ .reg .u64 t; cvta.to.shared.u64 t, %1; cvt.u32.u64 %0, t; }" : "=r"(a) : "l"(p));
    return a;
}
__device__ __forceinline__ void cpa16(void* dst, const void* src) {
    uint32_t d = smem_u32(dst);
    asm volatile("cp.async.cg.shared.global [%0], [%1], 16;" :: "r"(d), "l"(src) : "memory");
}
#define CP_COMMIT() asm volatile("cp.async.commit_group;" ::: "memory")
#define CP_WAIT(n)  asm volatile("cp.async.wait_group %0;" :: "n"(n) : "memory")

__device__ __forceinline__ void ldsm4(uint32_t* r, uint32_t addr) {
    asm volatile("ldmatrix.sync.aligned.m8n8.x4.shared.b16 {%0,%1,%2,%3}, [%4];"
        : "=r"(r[0]), "=r"(r[1]), "=r"(r[2]), "=r"(r[3]) : "r"(addr));
}
__device__ __forceinline__ void ldsm4t(uint32_t* r, uint32_t addr) {
    asm volatile("ldmatrix.sync.aligned.m8n8.x4.trans.shared.b16 {%0,%1,%2,%3}, [%4];"
        : "=r"(r[0]), "=r"(r[1]), "=r"(r[2]), "=r"(r[3]) : "r"(addr));
}
__device__ __forceinline__ void mma16(float* c, const uint32_t* a, const uint32_t* b) {
    asm volatile("mma.sync.aligned.m16n8k16.row.col.f32.bf16.bf16.f32 "
        "{%0,%1,%2,%3}, {%4,%5,%6,%7}, {%8,%9}, {%0,%1,%2,%3};"
        : "+f"(c[0]), "+f"(c[1]), "+f"(c[2]), "+f"(c[3])
        : "r"(a[0]), "r"(a[1]), "r"(a[2]), "r"(a[3]), "r"(b[0]), "r"(b[1]));
}

// smem byte offsets
#define SH 136                // tile stride in halves
#define OFF_A0   0
#define OFF_A1   34816
#define OFF_B0   69632
#define OFF_B1   104448
#define OFF_BIAS 139264       // 512 floats
#define OFF_RS   141312       // 128 floats
#define OFF_RB   141824       // 128 floats
#define OFF_RBUF 142336       // 512 floats
#define SMB      144384

// =====================================================================
// bf16 mma GEMM (unchanged)
// =====================================================================
template<int KT, int MT, int MODE, bool RMSOUT>
__global__ void __launch_bounds__(512, 1)
tc_gemm(const bf16* __restrict__ in, const bf16* __restrict__ W,
        const float* __restrict__ bias,
        const float* __restrict__ res, const float* __restrict__ scale_ptr,
        float* __restrict__ out, bf16* __restrict__ outb,
        bf16* __restrict__ outn,
        const float* __restrict__ rs2, const float* __restrict__ rb2)
{
    constexpr int NSUB  = (MODE == 1) ? 2 : 1;
    constexpr int NS    = KT * MT * NSUB;
    constexpr int KTOT  = KT * 128;
    constexpr int OCOUT = (MODE == 1) ? 256 : MT * 128;
    constexpr int NBIAS = (MODE == 1) ? 512 : MT * 128;
    constexpr int NACC  = (MODE == 1) ? 2 : 1;

    extern __shared__ char sm[];
    float* bs   = (float*)(sm + OFF_BIAS);
    float* rsv  = (float*)(sm + OFF_RS);
    float* rbv  = (float*)(sm + OFF_RB);
    float* rbuf = (float*)(sm + OFF_RBUF);
    const uint32_t smb = smem_u32(sm);

    const int tid = threadIdx.x, lane = tid & 31, wid = tid >> 5;
    const int wm = wid & 3, wn = wid >> 2;
    const int gp = blockIdx.x * 128;
    const int b  = gp / HWC;
    const int p0 = gp - b * HWC;
    const bf16* inb = in + (size_t)b * KTOT * HWC + p0;

    for (int i = tid; i < NBIAS; i += 512) bs[i] = bias[i];
    if (RMSOUT) for (int i = tid; i < 128; i += 512) { rsv[i] = rs2[i]; rbv[i] = rb2[i]; }

    const int a_m = (lane & 7) + ((lane >> 3) & 1) * 8;
    const int a_k = (lane >> 4) * 8;
    const int b_k = (lane & 7) + ((lane >> 3) & 1) * 8;
    const int b_n = wn * 32 + (lane >> 4) * 8;

    float acc[NACC][2][4][4];

    {
        for (int i = tid; i < 2048; i += 512) {
            int c = i >> 4, p8 = (i & 15) * 8;
            cpa16(sm + OFF_B0 + (c * SH + p8) * 2, inb + (size_t)c * HWC + p8);
        }
        const bf16* wt = W;
        for (int i = tid; i < 2048; i += 512) {
            int o = i >> 4, k8 = (i & 15) * 8;
            cpa16(sm + OFF_A0 + (o * SH + k8) * 2, wt + (size_t)o * KTOT + k8);
        }
        CP_COMMIT();
    }

    #pragma unroll
    for (int s = 0; s < NS; ++s) {
        const int kc = (KT == 2) ? s : 0;
        __syncthreads();
        if (s + 1 < NS) {
            const int kcn = (KT == 2) ? (s + 1) : 0;
            if (kcn != kc) {
                char* bd = sm + ((kcn & 1) ? OFF_B1 : OFF_B0);
                for (int i = tid; i < 2048; i += 512) {
                    int c = i >> 4, p8 = (i & 15) * 8;
                    cpa16(bd + (c * SH + p8) * 2, inb + (size_t)(kcn * 128 + c) * HWC + p8);
                }
            }
            const int sn = s + 1;
            const int ocb = (MODE == 1) ? ((sn & 1) * 256 + (sn >> 1) * 128)
                          : ((MODE == 0) ? sn * 128 : 0);
            const bf16* wt = W + (size_t)ocb * KTOT + kcn * 128;
            char* ad = sm + ((sn & 1) ? OFF_A1 : OFF_A0);
            for (int i = tid; i < 2048; i += 512) {
                int o = i >> 4, k8 = (i & 15) * 8;
                cpa16(ad + (o * SH + k8) * 2, wt + (size_t)o * KTOT + k8);
            }
            CP_COMMIT();
            CP_WAIT(1);
        } else {
            CP_WAIT(0);
        }
        __syncthreads();

        const int sel = (MODE == 1) ? (s & 1) : 0;
        if (MODE != 2 || s == 0) {
            #pragma unroll
            for (int mi = 0; mi < 2; ++mi)
                #pragma unroll
                for (int j = 0; j < 4; ++j)
                    #pragma unroll
                    for (int q = 0; q < 4; ++q) acc[sel][mi][j][q] = 0.f;
        }

        {
            const uint32_t Ab = smb + ((s & 1) ? OFF_A1 : OFF_A0);
            const uint32_t Bb = smb + ((kc & 1) ? OFF_B1 : OFF_B0);
            const uint32_t aaddr = Ab + ((wm * 32 + a_m) * SH + a_k) * 2;
            const uint32_t baddr = Bb + (b_k * SH + b_n) * 2;
            #pragma unroll
            for (int k0 = 0; k0 < 128; k0 += 16) {
                uint32_t a0[4], a1[4], b0[4], b1[4];
                ldsm4 (a0, aaddr + k0 * 2);
                ldsm4 (a1, aaddr + (16 * SH + k0) * 2);
                ldsm4t(b0, baddr + k0 * SH * 2);
                ldsm4t(b1, baddr + (k0 * SH + 16) * 2);
                mma16(acc[sel][0][0], a0, b0 + 0);
                mma16(acc[sel][0][1], a0, b0 + 2);
                mma16(acc[sel][0][2], a0, b1 + 0);
                mma16(acc[sel][0][3], a0, b1 + 2);
                mma16(acc[sel][1][0], a1, b0 + 0);
                mma16(acc[sel][1][1], a1, b0 + 2);
                mma16(acc[sel][1][2], a1, b1 + 0);
                mma16(acc[sel][1][3], a1, b1 + 2);
            }
        }

        const int r0e = wm * 32 + (lane >> 2);
        const int c0e = wn * 32 + (lane & 3) * 2;

        if (MODE == 0 || (MODE == 1 && (s & 1))) {
            const int mt = (MODE == 1) ? (s >> 1) : s;
            __syncthreads();
            bf16* st = (bf16*)(sm + ((s & 1) ? OFF_A1 : OFF_A0));
            #pragma unroll
            for (int mi = 0; mi < 2; ++mi) {
                int o = r0e + mi * 16;
                if (MODE == 1) {
                    float bu1 = bs[mt * 128 + o],     bv1 = bs[256 + mt * 128 + o];
                    float bu2 = bs[mt * 128 + o + 8], bv2 = bs[256 + mt * 128 + o + 8];
                    #pragma unroll
                    for (int j = 0; j < 4; ++j) {
                        int c = c0e + j * 8;
                        float u0 = (acc[0][mi][j][0] + bu1) * gelu_erf(acc[1][mi][j][0] + bv1);
                        float u1 = (acc[0][mi][j][1] + bu1) * gelu_erf(acc[1][mi][j][1] + bv1);
                        float u2 = (acc[0][mi][j][2] + bu2) * gelu_erf(acc[1][mi][j][2] + bv2);
                        float u3 = (acc[0][mi][j][3] + bu2) * gelu_erf(acc[1][mi][j][3] + bv2);
                        *(__nv_bfloat162*)&st[o * SH + c] =
                            __halves2bfloat162(__float2bfloat16(u0), __float2bfloat16(u1));
                        *(__nv_bfloat162*)&st[(o + 8) * SH + c] =
                            __halves2bfloat162(__float2bfloat16(u2), __float2bfloat16(u3));
                    }
                } else {
                    float b1v = bs[mt * 128 + o], b2v = bs[mt * 128 + o + 8];
                    #pragma unroll
                    for (int j = 0; j < 4; ++j) {
                        int c = c0e + j * 8;
                        *(__nv_bfloat162*)&st[o * SH + c] =
                            __halves2bfloat162(__float2bfloat16(acc[0][mi][j][0] + b1v),
                                               __float2bfloat16(acc[0][mi][j][1] + b1v));
                        *(__nv_bfloat162*)&st[(o + 8) * SH + c] =
                            __halves2bfloat162(__float2bfloat16(acc[0][mi][j][2] + b2v),
                                               __float2bfloat16(acc[0][mi][j][3] + b2v));
                    }
                }
            }
            __syncthreads();
            for (int i = tid; i < 2048; i += 512) {
                int o = i >> 4, p8 = (i & 15) * 8;
                uint4 v = *(uint4*)&st[o * SH + p8];
                *(uint4*)(outb + (size_t)b * OCOUT * HWC
                          + (size_t)(mt * 128 + o) * HWC + p0 + p8) = v;
            }
        } else if (MODE == 2 && s == NS - 1) {
            __syncthreads();
            float* st = (float*)(sm + OFF_B0);
            #pragma unroll
            for (int mi = 0; mi < 2; ++mi) {
                int o = r0e + mi * 16;
                float b1v = bs[o], b2v = bs[o + 8];
                #pragma unroll
                for (int j = 0; j < 4; ++j) {
                    int c = c0e + j * 8;
                    st[o * 132 + c]           = acc[0][mi][j][0] + b1v;
                    st[o * 132 + c + 1]       = acc[0][mi][j][1] + b1v;
                    st[(o + 8) * 132 + c]     = acc[0][mi][j][2] + b2v;
                    st[(o + 8) * 132 + c + 1] = acc[0][mi][j][3] + b2v;
                }
            }
            __syncthreads();
            float scl = *scale_ptr;
            for (int i = tid; i < 4096; i += 512) {
                int o = i >> 5, p4 = (i & 31) * 4;
                float4 v = *(float4*)&st[o * 132 + p4];
                size_t oidx = (size_t)b * 128 * HWC + (size_t)o * HWC + p0 + p4;
                float4 rr = *(const float4*)(res + oidx);
                v.x = rr.x + scl * v.x; v.y = rr.y + scl * v.y;
                v.z = rr.z + scl * v.z; v.w = rr.w + scl * v.w;
                *(float4*)(out + oidx) = v;
                if (RMSOUT) *(float4*)&st[o * 132 + p4] = v;
            }
            if (RMSOUT) {
                __syncthreads();
                int px = tid & 127, part = tid >> 7;
                float ss = 0.f;
                #pragma unroll 8
                for (int c = part * 32; c < part * 32 + 32; ++c) {
                    float v = st[c * 132 + px]; ss += v * v;
                }
                rbuf[part * 128 + px] = ss;
                __syncthreads();
                if (tid < 128)
                    rbuf[tid] = rsqrtf((rbuf[tid] + rbuf[128 + tid] + rbuf[256 + tid]
                                      + rbuf[384 + tid]) * (1.0f / 128.0f) + 1e-6f);
                __syncthreads();
                for (int i = tid; i < 4096; i += 512) {
                    int o = i >> 5, p4 = (i & 31) * 4;
                    float sc = rsv[o], bb = rbv[o];
                    float4 v = *(float4*)&st[o * 132 + p4];
                    float n0 = rbuf[p4], n1 = rbuf[p4 + 1], n2 = rbuf[p4 + 2], n3 = rbuf[p4 + 3];
                    bf16* ob = outn + (size_t)b * 128 * HWC + (size_t)o * HWC + p0 + p4;
                    *(__nv_bfloat162*)ob =
                        __halves2bfloat162(__float2bfloat16(sc * v.x * n0 + bb),
                                           __float2bfloat16(sc * v.y * n1 + bb));
                    *(__nv_bfloat162*)(ob + 2) =
                        __halves2bfloat162(__float2bfloat16(sc * v.z * n2 + bb),
                                           __float2bfloat16(sc * v.w * n3 + bb));
                }
            }
        }
    }
}

// =====================================================================
// weight fp32 -> bf16
// =====================================================================
__global__ void wcvt_kernel(const float* p1, const float* p2, const float* p3,
                            const float* p4, const float* p5, const float* p6,
                            bf16* o)
{
    int i = blockIdx.x * 1024 + threadIdx.x * 4;
    const float* src; int base;
    if      (i < 65536)  { src = p1; base = 0; }
    else if (i < 98304)  { src = p2; base = 65536; }
    else if (i < 147456) { src = p3; base = 98304; }
    else if (i < 163840) { src = p4; base = 147456; }
    else if (i < 229376) { src = p5; base = 163840; }
    else                 { src = p6; base = 229376; }
    float4 v = *(const float4*)(src + (i - base));
    *(__nv_bfloat162*)(o + i)     = __halves2bfloat162(__float2bfloat16(v.x), __float2bfloat16(v.y));
    *(__nv_bfloat162*)(o + i + 2) = __halves2bfloat162(__float2bfloat16(v.z), __float2bfloat16(v.w));
}

// =====================================================================
// rmsnorm(x) -> bf16
// =====================================================================
__global__ void __launch_bounds__(512)
rms_prep(const float* __restrict__ x, const float* __restrict__ s,
         const float* __restrict__ bsh, bf16* __restrict__ xn)
{
    extern __shared__ float smf[];
    float* st = smf;
    float* rbuf = smf + 128 * 132;
    int tid = threadIdx.x;
    int gp = blockIdx.x * 128;
    int b = gp / HWC, p0 = gp - b * HWC;
    const float* xb = x + (size_t)b * 128 * HWC + p0;
    for (int i = tid; i < 4096; i += 512) {
        int c = i >> 5, p4 = (i & 31) * 4;
        *(float4*)&st[c * 132 + p4] = *(const float4*)(xb + (size_t)c * HWC + p4);
    }
    __syncthreads();
    int px = tid & 127, part = tid >> 7;
    float ss = 0.f;
    #pragma unroll 8
    for (int c = part * 32; c < part * 32 + 32; ++c) { float v = st[c * 132 + px]; ss += v * v; }
    rbuf[part * 128 + px] = ss;
    __syncthreads();
    if (tid < 128)
        rbuf[tid] = rsqrtf((rbuf[tid] + rbuf[128 + tid] + rbuf[256 + tid] + rbuf[384 + tid])
                           * (1.0f / 128.0f) + 1e-6f);
    __syncthreads();
    bf16* ob = xn + (size_t)b * 128 * HWC + p0;
    for (int i = tid; i < 4096; i += 512) {
        int c = i >> 5, p4 = (i & 31) * 4;
        float sc = s[c], bb = bsh[c];
        float4 v = *(float4*)&st[c * 132 + p4];
        float n0 = rbuf[p4], n1 = rbuf[p4 + 1], n2 = rbuf[p4 + 2], n3 = rbuf[p4 + 3];
        *(__nv_bfloat162*)(ob + (size_t)c * HWC + p4) =
            __halves2bfloat162(__float2bfloat16(sc * v.x * n0 + bb),
                               __float2bfloat16(sc * v.y * n1 + bb));
        *(__nv_bfloat162*)(ob + (size_t)c * HWC + p4 + 2) =
            __halves2bfloat162(__float2bfloat16(sc * v.z * n2 + bb),
                               __float2bfloat16(sc * v.w * n3 + bb));
    }
}

// =====================================================================
// Depthwise 3x3 + bias + gated GELU — v4: 32x64 tiles, 2x4 out/thread,
// float4 smem interior loads (2 LDS.128 per row per plane), uint2 stores.
// grid: b(2) * ch(256) * 18 tiles, 256 threads.
// =====================================================================
__global__ void __launch_bounds__(256)
dwgate_kernel(const bf16* __restrict__ a, const float* __restrict__ dw,
              const float* __restrict__ db, bf16* __restrict__ out)
{
    __shared__ float su[34 * 68], sv[34 * 68];   // col s = local_col + 2
    int blk  = blockIdx.x;
    int tile = blk % 18;              // 6 row-tiles x 3 col-tiles
    int cp   = (blk / 18) & 255;
    int b    = blk / (18 * 256);
    int ty0 = (tile / 3) * 32, tx0 = (tile % 3) * 64;
    const bf16* ua = a + ((size_t)b * 512 + cp) * HWC;
    const bf16* va = ua + (size_t)256 * HWC;

    // halo fill: 34 rows x 34 aligned bf162 pairs (gx from tx0-2, even)
    #pragma unroll
    for (int it = 0; it < 5; ++it) {
        int i = threadIdx.x + it * 256;
        if (i < 34 * 34) {
            int ly = i / 34, px = i - ly * 34;
            int gy = ty0 + ly - 1;
            int gx = tx0 - 2 + px * 2;
            float2 uu = make_float2(0.f, 0.f), vv = make_float2(0.f, 0.f);
            if (((unsigned)gy < (unsigned)IMG) && ((unsigned)gx < (unsigned)IMG)) {
                int gi = gy * IMG + gx;
                uu = __bfloat1622float2(*(const __nv_bfloat162*)&ua[gi]);
                vv = __bfloat1622float2(*(const __nv_bfloat162*)&va[gi]);
            }
            *(float2*)&su[ly * 68 + px * 2] = uu;
            *(float2*)&sv[ly * 68 + px * 2] = vv;
        }
    }
    float wu[9], wv[9];
    #pragma unroll
    for (int i = 0; i < 9; ++i) {
        wu[i] = dw[cp * 9 + i];
        wv[i] = dw[(cp + 256) * 9 + i];
    }
    float bu = db[cp], bv = db[cp + 256];
    __syncthreads();

    int y0 = (threadIdx.x >> 4) * 2;     // out rows y0, y0+1 (local)
    int x0 = (threadIdx.x & 15) * 4;     // out cols x0..x0+3 (local)
    // neighborhood: rows y0..y0+3, smem cols x0..x0+7 (k index; col k = local x0+k-2)
    float U[4][8], V[4][8];
    #pragma unroll
    for (int r = 0; r < 4; ++r) {
        *(float4*)&U[r][0] = *(float4*)&su[(y0 + r) * 68 + x0];
        *(float4*)&U[r][4] = *(float4*)&su[(y0 + r) * 68 + x0 + 4];
        *(float4*)&V[r][0] = *(float4*)&sv[(y0 + r) * 68 + x0];
        *(float4*)&V[r][4] = *(float4*)&sv[(y0 + r) * 68 + x0 + 4];
    }

    bf16* ob = out + ((size_t)b * 256 + cp) * HWC;
    #pragma unroll
    for (int dy = 0; dy < 2; ++dy) {
        uint32_t pk[2];
        #pragma unroll
        for (int dp = 0; dp < 2; ++dp) {     // pairs of output columns
            float r2[2];
            #pragma unroll
            for (int h = 0; h < 2; ++h) {
                int dx = dp * 2 + h;
                float u = bu, v = bv;
                #pragma unroll
                for (int i = 0; i < 3; ++i)
                    #pragma unroll
                    for (int j = 0; j < 3; ++j) {
                        u = fmaf(U[dy + i][dx + 1 + j], wu[i * 3 + j], u);
                        v = fmaf(V[dy + i][dx + 1 + j], wv[i * 3 + j], v);
                    }
                r2[h] = u * gelu_erf(v);
            }
            __nv_bfloat162 p2 = __halves2bfloat162(__float2bfloat16(r2[0]),
                                                   __float2bfloat16(r2[1]));
            pk[dp] = *(uint32_t*)&p2;
        }
        *(uint2*)&ob[(ty0 + y0 + dy) * IMG + tx0 + x0] = make_uint2(pk[0], pk[1]);
    }
}

// =====================================================================
// Attention: direct global store (no outs staging)
// =====================================================================
__global__ void __launch_bounds__(64)
attn2_kernel(const bf16* __restrict__ qkv, const float* __restrict__ rpe,
             bf16* __restrict__ aog)
{
    __shared__ float Ks[64 * 36], Vs[64 * 36], rpe_s[225];
    __shared__ int pix[64], lk[64];
    int w = blockIdx.x >> 2, head = blockIdx.x & 3;
    int tid = threadIdx.x;
    int b = w / NWPB, wrem = w - b * NWPB;
    int wy = wrem / NWSIDE, wx = wrem - wy * NWSIDE;
    int qy = tid >> 3, qx = tid & 7;
    {
        int gh = wy * 8 + qy + 4; if (gh >= IMG) gh -= IMG;
        int gw = wx * 8 + qx + 4; if (gw >= IMG) gw -= IMG;
        pix[tid] = gh * IMG + gw;
    }
    {
        int gh = wy * 8 + qy, gw = wx * 8 + qx;
        int lh = gh < 184 ? 0 : (gh < 188 ? 1 : 2);
        int lw = gw < 184 ? 0 : (gw < 188 ? 1 : 2);
        lk[tid] = lh * 3 + lw;
    }
    for (int i = tid; i < 225; i += 64) rpe_s[i] = rpe[i * 4 + head];
    __syncthreads();

    const bf16* qb = qkv + (size_t)b * 384 * HWC + (size_t)(head * 32) * HWC;
    const bf16* kb = qb + (size_t)128 * HWC;
    const bf16* vb = qb + (size_t)256 * HWC;
    int myp = pix[tid];
    float q[32];
    #pragma unroll
    for (int d = 0; d < 32; ++d) {
        q[d] = __bfloat162float(qb[(size_t)d * HWC + myp]) * 0.17677669529663687f;
        Ks[tid * 36 + d] = __bfloat162float(kb[(size_t)d * HWC + myp]);
        Vs[tid * 36 + d] = __bfloat162float(vb[(size_t)d * HWC + myp]);
    }
    int lab = lk[tid];
    __syncthreads();

    float sc[64];
    float mx = -1e30f;
    #pragma unroll
    for (int kk = 0; kk < 64; ++kk) {
        const float4* kp = (const float4*)(Ks + kk * 36);
        float dot = 0.f;
        #pragma unroll
        for (int d4 = 0; d4 < 8; ++d4) {
            float4 kv = kp[d4];
            dot = fmaf(q[d4 * 4 + 0], kv.x, dot);
            dot = fmaf(q[d4 * 4 + 1], kv.y, dot);
            dot = fmaf(q[d4 * 4 + 2], kv.z, dot);
            dot = fmaf(q[d4 * 4 + 3], kv.w, dot);
        }
        int ky = kk >> 3, kx = kk & 7;
        dot += rpe_s[(qy - ky + 7) * 15 + (qx - kx + 7)];
        if (lab != lk[kk]) dot = -1e30f;
        sc[kk] = dot;
        mx = fmaxf(mx, dot);
    }
    float sum = 0.f;
    #pragma unroll
    for (int kk = 0; kk < 64; ++kk) {
        float e = __expf(sc[kk] - mx);
        sc[kk] = e; sum += e;
    }
    float inv = 1.0f / sum;
    float acc[32];
    #pragma unroll
    for (int d = 0; d < 32; ++d) acc[d] = 0.f;
    #pragma unroll
    for (int kk = 0; kk < 64; ++kk) {
        float p = sc[kk];
        const float4* vp = (const float4*)(Vs + kk * 36);
        #pragma unroll
        for (int d4 = 0; d4 < 8; ++d4) {
            float4 vv = vp[d4];
            acc[d4 * 4 + 0] = fmaf(p, vv.x, acc[d4 * 4 + 0]);
            acc[d4 * 4 + 1] = fmaf(p, vv.y, acc[d4 * 4 + 1]);
            acc[d4 * 4 + 2] = fmaf(p, vv.z, acc[d4 * 4 + 2]);
            acc[d4 * 4 + 3] = fmaf(p, vv.w, acc[d4 * 4 + 3]);
        }
    }
    size_t cb = (size_t)b * 128 * HWC + (size_t)(head * 32) * HWC;
    #pragma unroll
    for (int d = 0; d < 32; ++d)
        aog[cb + (size_t)d * HWC + myp] = __float2bfloat16(acc[d] * inv);
}

// =====================================================================
extern "C" void kernel_launch(void* const* d_in, const int* in_sizes, int n_in,
                              void* d_out, int out_size)
{
    const float* x      = (const float*)d_in[0];
    const float* cg_s   = (const float*)d_in[1];
    const float* cg_b   = (const float*)d_in[2];
    const float* pw1_w  = (const float*)d_in[3];
    const float* pw1_b  = (const float*)d_in[4];
    const float* dw_w   = (const float*)d_in[5];
    const float* dw_b   = (const float*)d_in[6];
    const float* pw2_w  = (const float*)d_in[7];
    const float* pw2_b  = (const float*)d_in[8];
    const float* beta   = (const float*)d_in[9];
    const float* at_s   = (const float*)d_in[10];
    const float* at_b   = (const float*)d_in[11];
    const float* qkv_w  = (const float*)d_in[12];
    const float* qkv_b  = (const float*)d_in[13];
    const float* rpe    = (const float*)d_in[14];
    const float* proj_w = (const float*)d_in[15];
    const float* proj_b = (const float*)d_in[16];
    const float* alpha  = (const float*)d_in[17];
    const float* ff_s   = (const float*)d_in[18];
    const float* ff_b   = (const float*)d_in[19];
    const float* fc1_w  = (const float*)d_in[20];
    const float* fc1_b  = (const float*)d_in[21];
    const float* fc2_w  = (const float*)d_in[22];
    const float* fc2_b  = (const float*)d_in[23];
    const float* gamma  = (const float*)d_in[24];
    float* out = (float*)d_out;

    bf16 *wbf, *xn, *a512, *g256, *qkvb, *aob, *x1n, *x2n;
    float *x1, *x2;
    cudaGetSymbolAddress((void**)&wbf,  g_wbf);
    cudaGetSymbolAddress((void**)&xn,   g_xn);
    cudaGetSymbolAddress((void**)&a512, g_a512);
    cudaGetSymbolAddress((void**)&g256, g_g256);
    cudaGetSymbolAddress((void**)&qkvb, g_qkv);
    cudaGetSymbolAddress((void**)&aob,  g_ao);
    cudaGetSymbolAddress((void**)&x1n,  g_x1n);
    cudaGetSymbolAddress((void**)&x2n,  g_x2n);
    cudaGetSymbolAddress((void**)&x1,   g_x1);
    cudaGetSymbolAddress((void**)&x2,   g_x2);

    cudaFuncSetAttribute(tc_gemm<1, 4, 0, false>, cudaFuncAttributeMaxDynamicSharedMemorySize, SMB);
    cudaFuncSetAttribute(tc_gemm<1, 3, 0, false>, cudaFuncAttributeMaxDynamicSharedMemorySize, SMB);
    cudaFuncSetAttribute(tc_gemm<2, 1, 2, true >, cudaFuncAttributeMaxDynamicSharedMemorySize, SMB);
    cudaFuncSetAttribute(tc_gemm<1, 1, 2, true >, cudaFuncAttributeMaxDynamicSharedMemorySize, SMB);
    cudaFuncSetAttribute(tc_gemm<1, 2, 1, false>, cudaFuncAttributeMaxDynamicSharedMemorySize, SMB);
    cudaFuncSetAttribute(tc_gemm<2, 1, 2, false>, cudaFuncAttributeMaxDynamicSharedMemorySize, SMB);
    cudaFuncSetAttribute(rms_prep, cudaFuncAttributeMaxDynamicSharedMemorySize, 69632);

    // ---- prep ----
    wcvt_kernel<<<256, 256>>>(pw1_w, pw2_w, qkv_w, proj_w, fc1_w, fc2_w, wbf);
    rms_prep<<<576, 512, 69632>>>(x, cg_s, cg_b, xn);

    // ---- conv gated block ----
    tc_gemm<1, 4, 0, false><<<576, 512, SMB>>>(
        xn, wbf + 0, pw1_b, nullptr, nullptr, nullptr, a512, nullptr, nullptr, nullptr);
    dwgate_kernel<<<2 * 256 * 18, 256>>>(a512, dw_w, dw_b, g256);
    tc_gemm<2, 1, 2, true><<<576, 512, SMB>>>(
        g256, wbf + 65536, pw2_b, x, beta, x1, nullptr, x1n, at_s, at_b);

    // ---- window attention ----
    tc_gemm<1, 3, 0, false><<<576, 512, SMB>>>(
        x1n, wbf + 98304, qkv_b, nullptr, nullptr, nullptr, qkvb, nullptr, nullptr, nullptr);
    attn2_kernel<<<NWTOT * 4, 64>>>(qkvb, rpe, aob);
    tc_gemm<1, 1, 2, true><<<576, 512, SMB>>>(
        aob, wbf + 147456, proj_b, x1, alpha, x2, nullptr, x2n, ff_s, ff_b);

    // ---- gated FFN ----
    tc_gemm<1, 2, 1, false><<<576, 512, SMB>>>(
        x2n, wbf + 163840, fc1_b, nullptr, nullptr, nullptr, g256, nullptr, nullptr, nullptr);
    tc_gemm<2, 1, 2, false><<<576, 512, SMB>>>(
        g256, wbf + 229376, fc2_b, x2, gamma, out, nullptr, nullptr, nullptr, nullptr);
}

// round 9
// speedup vs baseline: 4.3868x; 1.0160x over previous
#include <cuda_runtime.h>
#include <cuda_bf16.h>
#include <math.h>
#include <stdint.h>

#define IMG 192
#define HWC (192*192)
#define NWSIDE 24
#define NWPB 576
#define NWTOT 1152
typedef __nv_bfloat16 bf16;

// ---------------- scratch (device globals) ----------------
static __device__ bf16  g_wbf [262144];
static __device__ bf16  g_xn  [(size_t)2*128*HWC];
static __device__ bf16  g_a512[(size_t)2*512*HWC];
static __device__ bf16  g_g256[(size_t)2*256*HWC];
static __device__ bf16  g_qkv [(size_t)2*384*HWC];
static __device__ bf16  g_ao  [(size_t)2*128*HWC];
static __device__ bf16  g_x1n [(size_t)2*128*HWC];
static __device__ bf16  g_x2n [(size_t)2*128*HWC];
static __device__ float g_x1  [(size_t)2*128*HWC];
static __device__ float g_x2  [(size_t)2*128*HWC];

__device__ __forceinline__ float gelu_erf(float v) {
    return 0.5f * v * (1.0f + erff(v * 0.70710678118654752f));
}
__device__ __forceinline__ uint32_t smem_u32(const void* p) {
    uint32_t a;
    asm("{ .reg .u64 t; cvta.to.shared.u64 t, %1; cvt.u32.u64 %0, t; }" : "=r"(a) : "l"(p));
    return a;
}
__device__ __forceinline__ void cpa16(void* dst, const void* src) {
    uint32_t d = smem_u32(dst);
    asm volatile("cp.async.cg.shared.global [%0], [%1], 16;" :: "r"(d), "l"(src) : "memory");
}
#define CP_COMMIT() asm volatile("cp.async.commit_group;" ::: "memory")
#define CP_WAIT(n)  asm volatile("cp.async.wait_group %0;" :: "n"(n) : "memory")

__device__ __forceinline__ void ldsm4(uint32_t* r, uint32_t addr) {
    asm volatile("ldmatrix.sync.aligned.m8n8.x4.shared.b16 {%0,%1,%2,%3}, [%4];"
        : "=r"(r[0]), "=r"(r[1]), "=r"(r[2]), "=r"(r[3]) : "r"(addr));
}
__device__ __forceinline__ void ldsm4t(uint32_t* r, uint32_t addr) {
    asm volatile("ldmatrix.sync.aligned.m8n8.x4.trans.shared.b16 {%0,%1,%2,%3}, [%4];"
        : "=r"(r[0]), "=r"(r[1]), "=r"(r[2]), "=r"(r[3]) : "r"(addr));
}
__device__ __forceinline__ void mma16(float* c, const uint32_t* a, const uint32_t* b) {
    asm volatile("mma.sync.aligned.m16n8k16.row.col.f32.bf16.bf16.f32 "
        "{%0,%1,%2,%3}, {%4,%5,%6,%7}, {%8,%9}, {%0,%1,%2,%3};"
        : "+f"(c[0]), "+f"(c[1]), "+f"(c[2]), "+f"(c[3])
        : "r"(a[0]), "r"(a[1]), "r"(a[2]), "r"(a[3]), "r"(b[0]), "r"(b[1]));
}

// smem byte offsets — N=64px tiles, 2 CTAs/SM
#define SH  136               // A tile stride (halves)
#define SBH 72                // B tile stride (halves)
#define OFF_A0   0            // 34816
#define OFF_A1   34816
#define OFF_B0   69632        // 18432
#define OFF_B1   88064
#define OFF_BIAS 106496       // 512 floats
#define OFF_RS   108544       // 128 floats
#define OFF_RB   109056       // 128 floats
#define OFF_RBUF 109568       // 256 floats
#define SMB      110592       // 108 KB -> 2 CTAs/SM

// =====================================================================
// bf16 mma GEMM: 256 thr (8 warps, 4m x 2n), block 128oc x 64px,
// double-buffered cp.async. 2 CTAs/SM to overlap sync/epilogue bubbles.
// =====================================================================
template<int KT, int MT, int MODE, bool RMSOUT>
__global__ void __launch_bounds__(256, 2)
tc_gemm(const bf16* __restrict__ in, const bf16* __restrict__ W,
        const float* __restrict__ bias,
        const float* __restrict__ res, const float* __restrict__ scale_ptr,
        float* __restrict__ out, bf16* __restrict__ outb,
        bf16* __restrict__ outn,
        const float* __restrict__ rs2, const float* __restrict__ rb2)
{
    constexpr int NSUB  = (MODE == 1) ? 2 : 1;
    constexpr int NS    = KT * MT * NSUB;
    constexpr int KTOT  = KT * 128;
    constexpr int OCOUT = (MODE == 1) ? 256 : MT * 128;
    constexpr int NBIAS = (MODE == 1) ? 512 : MT * 128;
    constexpr int NACC  = (MODE == 1) ? 2 : 1;

    extern __shared__ char sm[];
    float* bs   = (float*)(sm + OFF_BIAS);
    float* rsv  = (float*)(sm + OFF_RS);
    float* rbv  = (float*)(sm + OFF_RB);
    float* rbuf = (float*)(sm + OFF_RBUF);
    const uint32_t smb = smem_u32(sm);

    const int tid = threadIdx.x, lane = tid & 31, wid = tid >> 5;
    const int wm = wid & 3, wn = wid >> 2;
    const int gp = blockIdx.x * 64;
    const int b  = gp / HWC;
    const int p0 = gp - b * HWC;
    const bf16* inb = in + (size_t)b * KTOT * HWC + p0;

    for (int i = tid; i < NBIAS; i += 256) bs[i] = bias[i];
    if (RMSOUT) for (int i = tid; i < 128; i += 256) { rsv[i] = rs2[i]; rbv[i] = rb2[i]; }

    const int a_m = (lane & 7) + ((lane >> 3) & 1) * 8;
    const int a_k = (lane >> 4) * 8;
    const int b_k = (lane & 7) + ((lane >> 3) & 1) * 8;
    const int b_n = wn * 32 + (lane >> 4) * 8;

    float acc[NACC][2][4][4];

    {   // prefetch step 0
        for (int i = tid; i < 1024; i += 256) {       // B(kc=0): 128c x 64px
            int c = i >> 3, p8 = (i & 7) * 8;
            cpa16(sm + OFF_B0 + (c * SBH + p8) * 2, inb + (size_t)c * HWC + p8);
        }
        const bf16* wt = W;
        for (int i = tid; i < 2048; i += 256) {       // A(step 0)
            int o = i >> 4, k8 = (i & 15) * 8;
            cpa16(sm + OFF_A0 + (o * SH + k8) * 2, wt + (size_t)o * KTOT + k8);
        }
        CP_COMMIT();
    }

    #pragma unroll
    for (int s = 0; s < NS; ++s) {
        const int kc = (KT == 2) ? s : 0;
        __syncthreads();
        if (s + 1 < NS) {
            const int kcn = (KT == 2) ? (s + 1) : 0;
            if (kcn != kc) {
                char* bd = sm + ((kcn & 1) ? OFF_B1 : OFF_B0);
                for (int i = tid; i < 1024; i += 256) {
                    int c = i >> 3, p8 = (i & 7) * 8;
                    cpa16(bd + (c * SBH + p8) * 2, inb + (size_t)(kcn * 128 + c) * HWC + p8);
                }
            }
            const int sn = s + 1;
            const int ocb = (MODE == 1) ? ((sn & 1) * 256 + (sn >> 1) * 128)
                          : ((MODE == 0) ? sn * 128 : 0);
            const bf16* wt = W + (size_t)ocb * KTOT + kcn * 128;
            char* ad = sm + ((sn & 1) ? OFF_A1 : OFF_A0);
            for (int i = tid; i < 2048; i += 256) {
                int o = i >> 4, k8 = (i & 15) * 8;
                cpa16(ad + (o * SH + k8) * 2, wt + (size_t)o * KTOT + k8);
            }
            CP_COMMIT();
            CP_WAIT(1);
        } else {
            CP_WAIT(0);
        }
        __syncthreads();

        const int sel = (MODE == 1) ? (s & 1) : 0;
        if (MODE != 2 || s == 0) {
            #pragma unroll
            for (int mi = 0; mi < 2; ++mi)
                #pragma unroll
                for (int j = 0; j < 4; ++j)
                    #pragma unroll
                    for (int q = 0; q < 4; ++q) acc[sel][mi][j][q] = 0.f;
        }

        {   // mma over k=128
            const uint32_t Ab = smb + ((s & 1) ? OFF_A1 : OFF_A0);
            const uint32_t Bb = smb + ((kc & 1) ? OFF_B1 : OFF_B0);
            const uint32_t aaddr = Ab + ((wm * 32 + a_m) * SH + a_k) * 2;
            const uint32_t baddr = Bb + (b_k * SBH + b_n) * 2;
            #pragma unroll
            for (int k0 = 0; k0 < 128; k0 += 16) {
                uint32_t a0[4], a1[4], b0[4], b1[4];
                ldsm4 (a0, aaddr + k0 * 2);
                ldsm4 (a1, aaddr + (16 * SH + k0) * 2);
                ldsm4t(b0, baddr + k0 * SBH * 2);
                ldsm4t(b1, baddr + (k0 * SBH + 16) * 2);
                mma16(acc[sel][0][0], a0, b0 + 0);
                mma16(acc[sel][0][1], a0, b0 + 2);
                mma16(acc[sel][0][2], a0, b1 + 0);
                mma16(acc[sel][0][3], a0, b1 + 2);
                mma16(acc[sel][1][0], a1, b0 + 0);
                mma16(acc[sel][1][1], a1, b0 + 2);
                mma16(acc[sel][1][2], a1, b1 + 0);
                mma16(acc[sel][1][3], a1, b1 + 2);
            }
        }

        const int r0e = wm * 32 + (lane >> 2);
        const int c0e = wn * 32 + (lane & 3) * 2;

        if (MODE == 0 || (MODE == 1 && (s & 1))) {
            const int mt = (MODE == 1) ? (s >> 1) : s;
            __syncthreads();
            bf16* st = (bf16*)(sm + ((s & 1) ? OFF_A1 : OFF_A0));
            #pragma unroll
            for (int mi = 0; mi < 2; ++mi) {
                int o = r0e + mi * 16;
                if (MODE == 1) {
                    float bu1 = bs[mt * 128 + o],     bv1 = bs[256 + mt * 128 + o];
                    float bu2 = bs[mt * 128 + o + 8], bv2 = bs[256 + mt * 128 + o + 8];
                    #pragma unroll
                    for (int j = 0; j < 4; ++j) {
                        int c = c0e + j * 8;
                        float u0 = (acc[0][mi][j][0] + bu1) * gelu_erf(acc[1][mi][j][0] + bv1);
                        float u1 = (acc[0][mi][j][1] + bu1) * gelu_erf(acc[1][mi][j][1] + bv1);
                        float u2 = (acc[0][mi][j][2] + bu2) * gelu_erf(acc[1][mi][j][2] + bv2);
                        float u3 = (acc[0][mi][j][3] + bu2) * gelu_erf(acc[1][mi][j][3] + bv2);
                        *(__nv_bfloat162*)&st[o * SH + c] =
                            __halves2bfloat162(__float2bfloat16(u0), __float2bfloat16(u1));
                        *(__nv_bfloat162*)&st[(o + 8) * SH + c] =
                            __halves2bfloat162(__float2bfloat16(u2), __float2bfloat16(u3));
                    }
                } else {
                    float b1v = bs[mt * 128 + o], b2v = bs[mt * 128 + o + 8];
                    #pragma unroll
                    for (int j = 0; j < 4; ++j) {
                        int c = c0e + j * 8;
                        *(__nv_bfloat162*)&st[o * SH + c] =
                            __halves2bfloat162(__float2bfloat16(acc[0][mi][j][0] + b1v),
                                               __float2bfloat16(acc[0][mi][j][1] + b1v));
                        *(__nv_bfloat162*)&st[(o + 8) * SH + c] =
                            __halves2bfloat162(__float2bfloat16(acc[0][mi][j][2] + b2v),
                                               __float2bfloat16(acc[0][mi][j][3] + b2v));
                    }
                }
            }
            __syncthreads();
            for (int i = tid; i < 1024; i += 256) {
                int o = i >> 3, p8 = (i & 7) * 8;
                uint4 v = *(uint4*)&st[o * SH + p8];
                *(uint4*)(outb + (size_t)b * OCOUT * HWC
                          + (size_t)(mt * 128 + o) * HWC + p0 + p8) = v;
            }
        } else if (MODE == 2 && s == NS - 1) {
            __syncthreads();
            float* st = (float*)(sm + OFF_B0);   // fp32 stage [128][68] = 34.8KB
            #pragma unroll
            for (int mi = 0; mi < 2; ++mi) {
                int o = r0e + mi * 16;
                float b1v = bs[o], b2v = bs[o + 8];
                #pragma unroll
                for (int j = 0; j < 4; ++j) {
                    int c = c0e + j * 8;
                    st[o * 68 + c]           = acc[0][mi][j][0] + b1v;
                    st[o * 68 + c + 1]       = acc[0][mi][j][1] + b1v;
                    st[(o + 8) * 68 + c]     = acc[0][mi][j][2] + b2v;
                    st[(o + 8) * 68 + c + 1] = acc[0][mi][j][3] + b2v;
                }
            }
            __syncthreads();
            float scl = *scale_ptr;
            for (int i = tid; i < 2048; i += 256) {
                int o = i >> 4, p4 = (i & 15) * 4;
                float4 v = *(float4*)&st[o * 68 + p4];
                size_t oidx = (size_t)b * 128 * HWC + (size_t)o * HWC + p0 + p4;
                float4 rr = *(const float4*)(res + oidx);
                v.x = rr.x + scl * v.x; v.y = rr.y + scl * v.y;
                v.z = rr.z + scl * v.z; v.w = rr.w + scl * v.w;
                *(float4*)(out + oidx) = v;
                if (RMSOUT) *(float4*)&st[o * 68 + p4] = v;
            }
            if (RMSOUT) {
                __syncthreads();
                int px = tid & 63, part = tid >> 6;
                float ss = 0.f;
                #pragma unroll 8
                for (int c = part * 32; c < part * 32 + 32; ++c) {
                    float v = st[c * 68 + px]; ss += v * v;
                }
                rbuf[part * 64 + px] = ss;
                __syncthreads();
                if (tid < 64)
                    rbuf[tid] = rsqrtf((rbuf[tid] + rbuf[64 + tid] + rbuf[128 + tid]
                                      + rbuf[192 + tid]) * (1.0f / 128.0f) + 1e-6f);
                __syncthreads();
                for (int i = tid; i < 2048; i += 256) {
                    int o = i >> 4, p4 = (i & 15) * 4;
                    float sc = rsv[o], bb = rbv[o];
                    float4 v = *(float4*)&st[o * 68 + p4];
                    float n0 = rbuf[p4], n1 = rbuf[p4 + 1], n2 = rbuf[p4 + 2], n3 = rbuf[p4 + 3];
                    bf16* ob = outn + (size_t)b * 128 * HWC + (size_t)o * HWC + p0 + p4;
                    *(__nv_bfloat162*)ob =
                        __halves2bfloat162(__float2bfloat16(sc * v.x * n0 + bb),
                                           __float2bfloat16(sc * v.y * n1 + bb));
                    *(__nv_bfloat162*)(ob + 2) =
                        __halves2bfloat162(__float2bfloat16(sc * v.z * n2 + bb),
                                           __float2bfloat16(sc * v.w * n3 + bb));
                }
            }
        }
    }
}

// =====================================================================
// weight fp32 -> bf16
// =====================================================================
__global__ void wcvt_kernel(const float* p1, const float* p2, const float* p3,
                            const float* p4, const float* p5, const float* p6,
                            bf16* o)
{
    int i = blockIdx.x * 1024 + threadIdx.x * 4;
    const float* src; int base;
    if      (i < 65536)  { src = p1; base = 0; }
    else if (i < 98304)  { src = p2; base = 65536; }
    else if (i < 147456) { src = p3; base = 98304; }
    else if (i < 163840) { src = p4; base = 147456; }
    else if (i < 229376) { src = p5; base = 163840; }
    else                 { src = p6; base = 229376; }
    float4 v = *(const float4*)(src + (i - base));
    *(__nv_bfloat162*)(o + i)     = __halves2bfloat162(__float2bfloat16(v.x), __float2bfloat16(v.y));
    *(__nv_bfloat162*)(o + i + 2) = __halves2bfloat162(__float2bfloat16(v.z), __float2bfloat16(v.w));
}

// =====================================================================
// rmsnorm(x) -> bf16
// =====================================================================
__global__ void __launch_bounds__(512)
rms_prep(const float* __restrict__ x, const float* __restrict__ s,
         const float* __restrict__ bsh, bf16* __restrict__ xn)
{
    extern __shared__ float smf[];
    float* st = smf;
    float* rbuf = smf + 128 * 132;
    int tid = threadIdx.x;
    int gp = blockIdx.x * 128;
    int b = gp / HWC, p0 = gp - b * HWC;
    const float* xb = x + (size_t)b * 128 * HWC + p0;
    for (int i = tid; i < 4096; i += 512) {
        int c = i >> 5, p4 = (i & 31) * 4;
        *(float4*)&st[c * 132 + p4] = *(const float4*)(xb + (size_t)c * HWC + p4);
    }
    __syncthreads();
    int px = tid & 127, part = tid >> 7;
    float ss = 0.f;
    #pragma unroll 8
    for (int c = part * 32; c < part * 32 + 32; ++c) { float v = st[c * 132 + px]; ss += v * v; }
    rbuf[part * 128 + px] = ss;
    __syncthreads();
    if (tid < 128)
        rbuf[tid] = rsqrtf((rbuf[tid] + rbuf[128 + tid] + rbuf[256 + tid] + rbuf[384 + tid])
                           * (1.0f / 128.0f) + 1e-6f);
    __syncthreads();
    bf16* ob = xn + (size_t)b * 128 * HWC + p0;
    for (int i = tid; i < 4096; i += 512) {
        int c = i >> 5, p4 = (i & 31) * 4;
        float sc = s[c], bb = bsh[c];
        float4 v = *(float4*)&st[c * 132 + p4];
        float n0 = rbuf[p4], n1 = rbuf[p4 + 1], n2 = rbuf[p4 + 2], n3 = rbuf[p4 + 3];
        *(__nv_bfloat162*)(ob + (size_t)c * HWC + p4) =
            __halves2bfloat162(__float2bfloat16(sc * v.x * n0 + bb),
                               __float2bfloat16(sc * v.y * n1 + bb));
        *(__nv_bfloat162*)(ob + (size_t)c * HWC + p4 + 2) =
            __halves2bfloat162(__float2bfloat16(sc * v.z * n2 + bb),
                               __float2bfloat16(sc * v.w * n3 + bb));
    }
}

// =====================================================================
// Depthwise 3x3 + bias + gated GELU (unchanged — at instruction floor)
// =====================================================================
__global__ void __launch_bounds__(256)
dwgate_kernel(const bf16* __restrict__ a, const float* __restrict__ dw,
              const float* __restrict__ db, bf16* __restrict__ out)
{
    __shared__ float su[34 * 68], sv[34 * 68];
    int blk  = blockIdx.x;
    int tile = blk % 18;
    int cp   = (blk / 18) & 255;
    int b    = blk / (18 * 256);
    int ty0 = (tile / 3) * 32, tx0 = (tile % 3) * 64;
    const bf16* ua = a + ((size_t)b * 512 + cp) * HWC;
    const bf16* va = ua + (size_t)256 * HWC;

    #pragma unroll
    for (int it = 0; it < 5; ++it) {
        int i = threadIdx.x + it * 256;
        if (i < 34 * 34) {
            int ly = i / 34, px = i - ly * 34;
            int gy = ty0 + ly - 1;
            int gx = tx0 - 2 + px * 2;
            float2 uu = make_float2(0.f, 0.f), vv = make_float2(0.f, 0.f);
            if (((unsigned)gy < (unsigned)IMG) && ((unsigned)gx < (unsigned)IMG)) {
                int gi = gy * IMG + gx;
                uu = __bfloat1622float2(*(const __nv_bfloat162*)&ua[gi]);
                vv = __bfloat1622float2(*(const __nv_bfloat162*)&va[gi]);
            }
            *(float2*)&su[ly * 68 + px * 2] = uu;
            *(float2*)&sv[ly * 68 + px * 2] = vv;
        }
    }
    float wu[9], wv[9];
    #pragma unroll
    for (int i = 0; i < 9; ++i) {
        wu[i] = dw[cp * 9 + i];
        wv[i] = dw[(cp + 256) * 9 + i];
    }
    float bu = db[cp], bv = db[cp + 256];
    __syncthreads();

    int y0 = (threadIdx.x >> 4) * 2;
    int x0 = (threadIdx.x & 15) * 4;
    float U[4][8], V[4][8];
    #pragma unroll
    for (int r = 0; r < 4; ++r) {
        *(float4*)&U[r][0] = *(float4*)&su[(y0 + r) * 68 + x0];
        *(float4*)&U[r][4] = *(float4*)&su[(y0 + r) * 68 + x0 + 4];
        *(float4*)&V[r][0] = *(float4*)&sv[(y0 + r) * 68 + x0];
        *(float4*)&V[r][4] = *(float4*)&sv[(y0 + r) * 68 + x0 + 4];
    }

    bf16* ob = out + ((size_t)b * 256 + cp) * HWC;
    #pragma unroll
    for (int dy = 0; dy < 2; ++dy) {
        uint32_t pk[2];
        #pragma unroll
        for (int dp = 0; dp < 2; ++dp) {
            float r2[2];
            #pragma unroll
            for (int h = 0; h < 2; ++h) {
                int dx = dp * 2 + h;
                float u = bu, v = bv;
                #pragma unroll
                for (int i = 0; i < 3; ++i)
                    #pragma unroll
                    for (int j = 0; j < 3; ++j) {
                        u = fmaf(U[dy + i][dx + 1 + j], wu[i * 3 + j], u);
                        v = fmaf(V[dy + i][dx + 1 + j], wv[i * 3 + j], v);
                    }
                r2[h] = u * gelu_erf(v);
            }
            __nv_bfloat162 p2 = __halves2bfloat162(__float2bfloat16(r2[0]),
                                                   __float2bfloat16(r2[1]));
            pk[dp] = *(uint32_t*)&p2;
        }
        *(uint2*)&ob[(ty0 + y0 + dy) * IMG + tx0 + x0] = make_uint2(pk[0], pk[1]);
    }
}

// =====================================================================
// Attention (unchanged)
// =====================================================================
__global__ void __launch_bounds__(64)
attn2_kernel(const bf16* __restrict__ qkv, const float* __restrict__ rpe,
             bf16* __restrict__ aog)
{
    __shared__ float Ks[64 * 36], Vs[64 * 36], rpe_s[225];
    __shared__ int pix[64], lk[64];
    int w = blockIdx.x >> 2, head = blockIdx.x & 3;
    int tid = threadIdx.x;
    int b = w / NWPB, wrem = w - b * NWPB;
    int wy = wrem / NWSIDE, wx = wrem - wy * NWSIDE;
    int qy = tid >> 3, qx = tid & 7;
    {
        int gh = wy * 8 + qy + 4; if (gh >= IMG) gh -= IMG;
        int gw = wx * 8 + qx + 4; if (gw >= IMG) gw -= IMG;
        pix[tid] = gh * IMG + gw;
    }
    {
        int gh = wy * 8 + qy, gw = wx * 8 + qx;
        int lh = gh < 184 ? 0 : (gh < 188 ? 1 : 2);
        int lw = gw < 184 ? 0 : (gw < 188 ? 1 : 2);
        lk[tid] = lh * 3 + lw;
    }
    for (int i = tid; i < 225; i += 64) rpe_s[i] = rpe[i * 4 + head];
    __syncthreads();

    const bf16* qb = qkv + (size_t)b * 384 * HWC + (size_t)(head * 32) * HWC;
    const bf16* kb = qb + (size_t)128 * HWC;
    const bf16* vb = qb + (size_t)256 * HWC;
    int myp = pix[tid];
    float q[32];
    #pragma unroll
    for (int d = 0; d < 32; ++d) {
        q[d] = __bfloat162float(qb[(size_t)d * HWC + myp]) * 0.17677669529663687f;
        Ks[tid * 36 + d] = __bfloat162float(kb[(size_t)d * HWC + myp]);
        Vs[tid * 36 + d] = __bfloat162float(vb[(size_t)d * HWC + myp]);
    }
    int lab = lk[tid];
    __syncthreads();

    float sc[64];
    float mx = -1e30f;
    #pragma unroll
    for (int kk = 0; kk < 64; ++kk) {
        const float4* kp = (const float4*)(Ks + kk * 36);
        float dot = 0.f;
        #pragma unroll
        for (int d4 = 0; d4 < 8; ++d4) {
            float4 kv = kp[d4];
            dot = fmaf(q[d4 * 4 + 0], kv.x, dot);
            dot = fmaf(q[d4 * 4 + 1], kv.y, dot);
            dot = fmaf(q[d4 * 4 + 2], kv.z, dot);
            dot = fmaf(q[d4 * 4 + 3], kv.w, dot);
        }
        int ky = kk >> 3, kx = kk & 7;
        dot += rpe_s[(qy - ky + 7) * 15 + (qx - kx + 7)];
        if (lab != lk[kk]) dot = -1e30f;
        sc[kk] = dot;
        mx = fmaxf(mx, dot);
    }
    float sum = 0.f;
    #pragma unroll
    for (int kk = 0; kk < 64; ++kk) {
        float e = __expf(sc[kk] - mx);
        sc[kk] = e; sum += e;
    }
    float inv = 1.0f / sum;
    float acc[32];
    #pragma unroll
    for (int d = 0; d < 32; ++d) acc[d] = 0.f;
    #pragma unroll
    for (int kk = 0; kk < 64; ++kk) {
        float p = sc[kk];
        const float4* vp = (const float4*)(Vs + kk * 36);
        #pragma unroll
        for (int d4 = 0; d4 < 8; ++d4) {
            float4 vv = vp[d4];
            acc[d4 * 4 + 0] = fmaf(p, vv.x, acc[d4 * 4 + 0]);
            acc[d4 * 4 + 1] = fmaf(p, vv.y, acc[d4 * 4 + 1]);
            acc[d4 * 4 + 2] = fmaf(p, vv.z, acc[d4 * 4 + 2]);
            acc[d4 * 4 + 3] = fmaf(p, vv.w, acc[d4 * 4 + 3]);
        }
    }
    size_t cb = (size_t)b * 128 * HWC + (size_t)(head * 32) * HWC;
    #pragma unroll
    for (int d = 0; d < 32; ++d)
        aog[cb + (size_t)d * HWC + myp] = __float2bfloat16(acc[d] * inv);
}

// =====================================================================
extern "C" void kernel_launch(void* const* d_in, const int* in_sizes, int n_in,
                              void* d_out, int out_size)
{
    const float* x      = (const float*)d_in[0];
    const float* cg_s   = (const float*)d_in[1];
    const float* cg_b   = (const float*)d_in[2];
    const float* pw1_w  = (const float*)d_in[3];
    const float* pw1_b  = (const float*)d_in[4];
    const float* dw_w   = (const float*)d_in[5];
    const float* dw_b   = (const float*)d_in[6];
    const float* pw2_w  = (const float*)d_in[7];
    const float* pw2_b  = (const float*)d_in[8];
    const float* beta   = (const float*)d_in[9];
    const float* at_s   = (const float*)d_in[10];
    const float* at_b   = (const float*)d_in[11];
    const float* qkv_w  = (const float*)d_in[12];
    const float* qkv_b  = (const float*)d_in[13];
    const float* rpe    = (const float*)d_in[14];
    const float* proj_w = (const float*)d_in[15];
    const float* proj_b = (const float*)d_in[16];
    const float* alpha  = (const float*)d_in[17];
    const float* ff_s   = (const float*)d_in[18];
    const float* ff_b   = (const float*)d_in[19];
    const float* fc1_w  = (const float*)d_in[20];
    const float* fc1_b  = (const float*)d_in[21];
    const float* fc2_w  = (const float*)d_in[22];
    const float* fc2_b  = (const float*)d_in[23];
    const float* gamma  = (const float*)d_in[24];
    float* out = (float*)d_out;

    bf16 *wbf, *xn, *a512, *g256, *qkvb, *aob, *x1n, *x2n;
    float *x1, *x2;
    cudaGetSymbolAddress((void**)&wbf,  g_wbf);
    cudaGetSymbolAddress((void**)&xn,   g_xn);
    cudaGetSymbolAddress((void**)&a512, g_a512);
    cudaGetSymbolAddress((void**)&g256, g_g256);
    cudaGetSymbolAddress((void**)&qkvb, g_qkv);
    cudaGetSymbolAddress((void**)&aob,  g_ao);
    cudaGetSymbolAddress((void**)&x1n,  g_x1n);
    cudaGetSymbolAddress((void**)&x2n,  g_x2n);
    cudaGetSymbolAddress((void**)&x1,   g_x1);
    cudaGetSymbolAddress((void**)&x2,   g_x2);

    cudaFuncSetAttribute(tc_gemm<1, 4, 0, false>, cudaFuncAttributeMaxDynamicSharedMemorySize, SMB);
    cudaFuncSetAttribute(tc_gemm<1, 3, 0, false>, cudaFuncAttributeMaxDynamicSharedMemorySize, SMB);
    cudaFuncSetAttribute(tc_gemm<2, 1, 2, true >, cudaFuncAttributeMaxDynamicSharedMemorySize, SMB);
    cudaFuncSetAttribute(tc_gemm<1, 1, 2, true >, cudaFuncAttributeMaxDynamicSharedMemorySize, SMB);
    cudaFuncSetAttribute(tc_gemm<1, 2, 1, false>, cudaFuncAttributeMaxDynamicSharedMemorySize, SMB);
    cudaFuncSetAttribute(tc_gemm<2, 1, 2, false>, cudaFuncAttributeMaxDynamicSharedMemorySize, SMB);
    cudaFuncSetAttribute(rms_prep, cudaFuncAttributeMaxDynamicSharedMemorySize, 69632);

    const int NPB = 1152;   // (2*HWC)/64

    // ---- prep ----
    wcvt_kernel<<<256, 256>>>(pw1_w, pw2_w, qkv_w, proj_w, fc1_w, fc2_w, wbf);
    rms_prep<<<576, 512, 69632>>>(x, cg_s, cg_b, xn);

    // ---- conv gated block ----
    tc_gemm<1, 4, 0, false><<<NPB, 256, SMB>>>(
        xn, wbf + 0, pw1_b, nullptr, nullptr, nullptr, a512, nullptr, nullptr, nullptr);
    dwgate_kernel<<<2 * 256 * 18, 256>>>(a512, dw_w, dw_b, g256);
    tc_gemm<2, 1, 2, true><<<NPB, 256, SMB>>>(
        g256, wbf + 65536, pw2_b, x, beta, x1, nullptr, x1n, at_s, at_b);

    // ---- window attention ----
    tc_gemm<1, 3, 0, false><<<NPB, 256, SMB>>>(
        x1n, wbf + 98304, qkv_b, nullptr, nullptr, nullptr, qkvb, nullptr, nullptr, nullptr);
    attn2_kernel<<<NWTOT * 4, 64>>>(qkvb, rpe, aob);
    tc_gemm<1, 1, 2, true><<<NPB, 256, SMB>>>(
        aob, wbf + 147456, proj_b, x1, alpha, x2, nullptr, x2n, ff_s, ff_b);

    // ---- gated FFN ----
    tc_gemm<1, 2, 1, false><<<NPB, 256, SMB>>>(
        x2n, wbf + 163840, fc1_b, nullptr, nullptr, nullptr, g256, nullptr, nullptr, nullptr);
    tc_gemm<2, 1, 2, false><<<NPB, 256, SMB>>>(
        g256, wbf + 229376, fc2_b, x2, gamma, out, nullptr, nullptr, nullptr, nullptr);
}

// round 10
// speedup vs baseline: 4.4229x; 1.0082x over previous
#include <cuda_runtime.h>
#include <cuda_bf16.h>
#include <math.h>
#include <stdint.h>

#define IMG 192
#define HWC (192*192)
#define NWSIDE 24
#define NWPB 576
#define NWTOT 1152
typedef __nv_bfloat16 bf16;

// ---------------- scratch (device globals) ----------------
static __device__ bf16  g_wbf [262144];
static __device__ bf16  g_a512[(size_t)2*512*HWC];
static __device__ bf16  g_g256[(size_t)2*256*HWC];
static __device__ bf16  g_qkv [(size_t)2*384*HWC];
static __device__ bf16  g_ao  [(size_t)2*128*HWC];
static __device__ bf16  g_x1n [(size_t)2*128*HWC];
static __device__ bf16  g_x2n [(size_t)2*128*HWC];
static __device__ float g_x1  [(size_t)2*128*HWC];
static __device__ float g_x2  [(size_t)2*128*HWC];

__device__ __forceinline__ float gelu_erf(float v) {
    return 0.5f * v * (1.0f + erff(v * 0.70710678118654752f));
}
__device__ __forceinline__ uint32_t smem_u32(const void* p) {
    uint32_t a;
    asm("{ .reg .u64 t; cvta.to.shared.u64 t, %1; cvt.u32.u64 %0, t; }" : "=r"(a) : "l"(p));
    return a;
}
__device__ __forceinline__ void cpa16(void* dst, const void* src) {
    uint32_t d = smem_u32(dst);
    asm volatile("cp.async.cg.shared.global [%0], [%1], 16;" :: "r"(d), "l"(src) : "memory");
}
#define CP_COMMIT() asm volatile("cp.async.commit_group;" ::: "memory")
#define CP_WAIT(n)  asm volatile("cp.async.wait_group %0;" :: "n"(n) : "memory")

__device__ __forceinline__ void ldsm4(uint32_t* r, uint32_t addr) {
    asm volatile("ldmatrix.sync.aligned.m8n8.x4.shared.b16 {%0,%1,%2,%3}, [%4];"
        : "=r"(r[0]), "=r"(r[1]), "=r"(r[2]), "=r"(r[3]) : "r"(addr));
}
__device__ __forceinline__ void ldsm4t(uint32_t* r, uint32_t addr) {
    asm volatile("ldmatrix.sync.aligned.m8n8.x4.trans.shared.b16 {%0,%1,%2,%3}, [%4];"
        : "=r"(r[0]), "=r"(r[1]), "=r"(r[2]), "=r"(r[3]) : "r"(addr));
}
__device__ __forceinline__ void mma16(float* c, const uint32_t* a, const uint32_t* b) {
    asm volatile("mma.sync.aligned.m16n8k16.row.col.f32.bf16.bf16.f32 "
        "{%0,%1,%2,%3}, {%4,%5,%6,%7}, {%8,%9}, {%0,%1,%2,%3};"
        : "+f"(c[0]), "+f"(c[1]), "+f"(c[2]), "+f"(c[3])
        : "r"(a[0]), "r"(a[1]), "r"(a[2]), "r"(a[3]), "r"(b[0]), "r"(b[1]));
}

// smem byte offsets — N=64px tiles, 2 CTAs/SM
#define SH  136               // A tile stride (halves)
#define SBH 72                // B tile stride (halves)
#define OFF_A0   0            // 34816
#define OFF_A1   34816        // also fp32 RMSIN staging [128][68] = 34816 B
#define OFF_B0   69632        // 18432
#define OFF_B1   88064
#define OFF_BIAS 106496       // 512 floats
#define OFF_RS   108544       // 128 floats
#define OFF_RB   109056       // 128 floats
#define OFF_RBUF 109568       // 256 floats
#define SMB      110592       // 108 KB -> 2 CTAs/SM

// =====================================================================
// bf16 mma GEMM: 256 thr (8 warps, 4m x 2n), block 128oc x 64px,
// double-buffered cp.async, 2 CTAs/SM.
// RMSIN: input comes from fp32 `inf` with rmsnorm(rs2,rb2) prologue
// (staged in A1, normalized bf16 written to B0).
// =====================================================================
template<int KT, int MT, int MODE, bool RMSOUT, bool RMSIN>
__global__ void __launch_bounds__(256, 2)
tc_gemm(const bf16* __restrict__ in, const bf16* __restrict__ W,
        const float* __restrict__ bias,
        const float* __restrict__ res, const float* __restrict__ scale_ptr,
        float* __restrict__ out, bf16* __restrict__ outb,
        bf16* __restrict__ outn,
        const float* __restrict__ rs2, const float* __restrict__ rb2,
        const float* __restrict__ inf)
{
    constexpr int NSUB  = (MODE == 1) ? 2 : 1;
    constexpr int NS    = KT * MT * NSUB;
    constexpr int KTOT  = KT * 128;
    constexpr int OCOUT = (MODE == 1) ? 256 : MT * 128;
    constexpr int NBIAS = (MODE == 1) ? 512 : MT * 128;
    constexpr int NACC  = (MODE == 1) ? 2 : 1;

    extern __shared__ char sm[];
    float* bs   = (float*)(sm + OFF_BIAS);
    float* rsv  = (float*)(sm + OFF_RS);
    float* rbv  = (float*)(sm + OFF_RB);
    float* rbuf = (float*)(sm + OFF_RBUF);
    const uint32_t smb = smem_u32(sm);

    const int tid = threadIdx.x, lane = tid & 31, wid = tid >> 5;
    const int wm = wid & 3, wn = wid >> 2;
    const int gp = blockIdx.x * 64;
    const int b  = gp / HWC;
    const int p0 = gp - b * HWC;
    const bf16* inb = RMSIN ? nullptr : (in + (size_t)b * KTOT * HWC + p0);

    for (int i = tid; i < NBIAS; i += 256) bs[i] = bias[i];
    if (RMSOUT) for (int i = tid; i < 128; i += 256) { rsv[i] = rs2[i]; rbv[i] = rb2[i]; }

    const int a_m = (lane & 7) + ((lane >> 3) & 1) * 8;
    const int a_k = (lane >> 4) * 8;
    const int b_k = (lane & 7) + ((lane >> 3) & 1) * 8;
    const int b_n = wn * 32 + (lane >> 4) * 8;

    float acc[NACC][2][4][4];

    if (RMSIN) {
        // ---- fused RMSNorm prologue: fp32 x -> staged -> bf16 B0 ----
        float* stg = (float*)(sm + OFF_A1);           // [128][68]
        const float* xf = inf + (size_t)b * 128 * HWC + p0;
        for (int i = tid; i < 2048; i += 256) {
            int c = i >> 4, p4 = (i & 15) * 4;
            cpa16(stg + c * 68 + p4, xf + (size_t)c * HWC + p4);
        }
        CP_COMMIT();
        const bf16* wt = W;
        for (int i = tid; i < 2048; i += 256) {       // A(step 0)
            int o = i >> 4, k8 = (i & 15) * 8;
            cpa16(sm + OFF_A0 + (o * SH + k8) * 2, wt + (size_t)o * KTOT + k8);
        }
        CP_COMMIT();
        CP_WAIT(1);                                   // x staged; A still in flight
        __syncthreads();
        int px = tid & 63, part = tid >> 6;
        float ss = 0.f;
        #pragma unroll 8
        for (int c = part * 32; c < part * 32 + 32; ++c) {
            float v = stg[c * 68 + px]; ss += v * v;
        }
        rbuf[part * 64 + px] = ss;
        __syncthreads();
        if (tid < 64)
            rbuf[tid] = rsqrtf((rbuf[tid] + rbuf[64 + tid] + rbuf[128 + tid]
                              + rbuf[192 + tid]) * (1.0f / 128.0f) + 1e-6f);
        __syncthreads();
        bf16* B0h = (bf16*)(sm + OFF_B0);
        for (int i = tid; i < 4096; i += 256) {
            int c = i >> 5, p2 = (i & 31) * 2;
            float sc = rs2[c], bb = rb2[c];
            float v0 = sc * stg[c * 68 + p2]     * rbuf[p2]     + bb;
            float v1 = sc * stg[c * 68 + p2 + 1] * rbuf[p2 + 1] + bb;
            *(__nv_bfloat162*)&B0h[c * SBH + p2] =
                __halves2bfloat162(__float2bfloat16(v0), __float2bfloat16(v1));
        }
    } else {
        // ---- prefetch step 0 ----
        for (int i = tid; i < 1024; i += 256) {       // B(kc=0): 128c x 64px
            int c = i >> 3, p8 = (i & 7) * 8;
            cpa16(sm + OFF_B0 + (c * SBH + p8) * 2, inb + (size_t)c * HWC + p8);
        }
        const bf16* wt = W;
        for (int i = tid; i < 2048; i += 256) {       // A(step 0)
            int o = i >> 4, k8 = (i & 15) * 8;
            cpa16(sm + OFF_A0 + (o * SH + k8) * 2, wt + (size_t)o * KTOT + k8);
        }
        CP_COMMIT();
    }

    #pragma unroll
    for (int s = 0; s < NS; ++s) {
        const int kc = (KT == 2) ? s : 0;
        __syncthreads();
        if (s + 1 < NS) {
            const int kcn = (KT == 2) ? (s + 1) : 0;
            if (kcn != kc) {
                char* bd = sm + ((kcn & 1) ? OFF_B1 : OFF_B0);
                for (int i = tid; i < 1024; i += 256) {
                    int c = i >> 3, p8 = (i & 7) * 8;
                    cpa16(bd + (c * SBH + p8) * 2, inb + (size_t)(kcn * 128 + c) * HWC + p8);
                }
            }
            const int sn = s + 1;
            const int ocb = (MODE == 1) ? ((sn & 1) * 256 + (sn >> 1) * 128)
                          : ((MODE == 0) ? sn * 128 : 0);
            const bf16* wt = W + (size_t)ocb * KTOT + kcn * 128;
            char* ad = sm + ((sn & 1) ? OFF_A1 : OFF_A0);
            for (int i = tid; i < 2048; i += 256) {
                int o = i >> 4, k8 = (i & 15) * 8;
                cpa16(ad + (o * SH + k8) * 2, wt + (size_t)o * KTOT + k8);
            }
            CP_COMMIT();
            CP_WAIT(1);
        } else {
            CP_WAIT(0);
        }
        __syncthreads();

        const int sel = (MODE == 1) ? (s & 1) : 0;
        if (MODE != 2 || s == 0) {
            #pragma unroll
            for (int mi = 0; mi < 2; ++mi)
                #pragma unroll
                for (int j = 0; j < 4; ++j)
                    #pragma unroll
                    for (int q = 0; q < 4; ++q) acc[sel][mi][j][q] = 0.f;
        }

        {   // mma over k=128
            const uint32_t Ab = smb + ((s & 1) ? OFF_A1 : OFF_A0);
            const uint32_t Bb = smb + ((kc & 1) ? OFF_B1 : OFF_B0);
            const uint32_t aaddr = Ab + ((wm * 32 + a_m) * SH + a_k) * 2;
            const uint32_t baddr = Bb + (b_k * SBH + b_n) * 2;
            #pragma unroll
            for (int k0 = 0; k0 < 128; k0 += 16) {
                uint32_t a0[4], a1[4], b0[4], b1[4];
                ldsm4 (a0, aaddr + k0 * 2);
                ldsm4 (a1, aaddr + (16 * SH + k0) * 2);
                ldsm4t(b0, baddr + k0 * SBH * 2);
                ldsm4t(b1, baddr + (k0 * SBH + 16) * 2);
                mma16(acc[sel][0][0], a0, b0 + 0);
                mma16(acc[sel][0][1], a0, b0 + 2);
                mma16(acc[sel][0][2], a0, b1 + 0);
                mma16(acc[sel][0][3], a0, b1 + 2);
                mma16(acc[sel][1][0], a1, b0 + 0);
                mma16(acc[sel][1][1], a1, b0 + 2);
                mma16(acc[sel][1][2], a1, b1 + 0);
                mma16(acc[sel][1][3], a1, b1 + 2);
            }
        }

        const int r0e = wm * 32 + (lane >> 2);
        const int c0e = wn * 32 + (lane & 3) * 2;

        if (MODE == 0 || (MODE == 1 && (s & 1))) {
            const int mt = (MODE == 1) ? (s >> 1) : s;
            __syncthreads();
            bf16* st = (bf16*)(sm + ((s & 1) ? OFF_A1 : OFF_A0));
            #pragma unroll
            for (int mi = 0; mi < 2; ++mi) {
                int o = r0e + mi * 16;
                if (MODE == 1) {
                    float bu1 = bs[mt * 128 + o],     bv1 = bs[256 + mt * 128 + o];
                    float bu2 = bs[mt * 128 + o + 8], bv2 = bs[256 + mt * 128 + o + 8];
                    #pragma unroll
                    for (int j = 0; j < 4; ++j) {
                        int c = c0e + j * 8;
                        float u0 = (acc[0][mi][j][0] + bu1) * gelu_erf(acc[1][mi][j][0] + bv1);
                        float u1 = (acc[0][mi][j][1] + bu1) * gelu_erf(acc[1][mi][j][1] + bv1);
                        float u2 = (acc[0][mi][j][2] + bu2) * gelu_erf(acc[1][mi][j][2] + bv2);
                        float u3 = (acc[0][mi][j][3] + bu2) * gelu_erf(acc[1][mi][j][3] + bv2);
                        *(__nv_bfloat162*)&st[o * SH + c] =
                            __halves2bfloat162(__float2bfloat16(u0), __float2bfloat16(u1));
                        *(__nv_bfloat162*)&st[(o + 8) * SH + c] =
                            __halves2bfloat162(__float2bfloat16(u2), __float2bfloat16(u3));
                    }
                } else {
                    float b1v = bs[mt * 128 + o], b2v = bs[mt * 128 + o + 8];
                    #pragma unroll
                    for (int j = 0; j < 4; ++j) {
                        int c = c0e + j * 8;
                        *(__nv_bfloat162*)&st[o * SH + c] =
                            __halves2bfloat162(__float2bfloat16(acc[0][mi][j][0] + b1v),
                                               __float2bfloat16(acc[0][mi][j][1] + b1v));
                        *(__nv_bfloat162*)&st[(o + 8) * SH + c] =
                            __halves2bfloat162(__float2bfloat16(acc[0][mi][j][2] + b2v),
                                               __float2bfloat16(acc[0][mi][j][3] + b2v));
                    }
                }
            }
            __syncthreads();
            for (int i = tid; i < 1024; i += 256) {
                int o = i >> 3, p8 = (i & 7) * 8;
                uint4 v = *(uint4*)&st[o * SH + p8];
                *(uint4*)(outb + (size_t)b * OCOUT * HWC
                          + (size_t)(mt * 128 + o) * HWC + p0 + p8) = v;
            }
        } else if (MODE == 2 && s == NS - 1) {
            __syncthreads();
            float* st = (float*)(sm + OFF_B0);   // fp32 stage [128][68]
            #pragma unroll
            for (int mi = 0; mi < 2; ++mi) {
                int o = r0e + mi * 16;
                float b1v = bs[o], b2v = bs[o + 8];
                #pragma unroll
                for (int j = 0; j < 4; ++j) {
                    int c = c0e + j * 8;
                    st[o * 68 + c]           = acc[0][mi][j][0] + b1v;
                    st[o * 68 + c + 1]       = acc[0][mi][j][1] + b1v;
                    st[(o + 8) * 68 + c]     = acc[0][mi][j][2] + b2v;
                    st[(o + 8) * 68 + c + 1] = acc[0][mi][j][3] + b2v;
                }
            }
            __syncthreads();
            float scl = *scale_ptr;
            for (int i = tid; i < 2048; i += 256) {
                int o = i >> 4, p4 = (i & 15) * 4;
                float4 v = *(float4*)&st[o * 68 + p4];
                size_t oidx = (size_t)b * 128 * HWC + (size_t)o * HWC + p0 + p4;
                float4 rr = *(const float4*)(res + oidx);
                v.x = rr.x + scl * v.x; v.y = rr.y + scl * v.y;
                v.z = rr.z + scl * v.z; v.w = rr.w + scl * v.w;
                *(float4*)(out + oidx) = v;
                if (RMSOUT) *(float4*)&st[o * 68 + p4] = v;
            }
            if (RMSOUT) {
                __syncthreads();
                int px = tid & 63, part = tid >> 6;
                float ss = 0.f;
                #pragma unroll 8
                for (int c = part * 32; c < part * 32 + 32; ++c) {
                    float v = st[c * 68 + px]; ss += v * v;
                }
                rbuf[part * 64 + px] = ss;
                __syncthreads();
                if (tid < 64)
                    rbuf[tid] = rsqrtf((rbuf[tid] + rbuf[64 + tid] + rbuf[128 + tid]
                                      + rbuf[192 + tid]) * (1.0f / 128.0f) + 1e-6f);
                __syncthreads();
                for (int i = tid; i < 2048; i += 256) {
                    int o = i >> 4, p4 = (i & 15) * 4;
                    float sc = rsv[o], bb = rbv[o];
                    float4 v = *(float4*)&st[o * 68 + p4];
                    float n0 = rbuf[p4], n1 = rbuf[p4 + 1], n2 = rbuf[p4 + 2], n3 = rbuf[p4 + 3];
                    bf16* ob = outn + (size_t)b * 128 * HWC + (size_t)o * HWC + p0 + p4;
                    *(__nv_bfloat162*)ob =
                        __halves2bfloat162(__float2bfloat16(sc * v.x * n0 + bb),
                                           __float2bfloat16(sc * v.y * n1 + bb));
                    *(__nv_bfloat162*)(ob + 2) =
                        __halves2bfloat162(__float2bfloat16(sc * v.z * n2 + bb),
                                           __float2bfloat16(sc * v.w * n3 + bb));
                }
            }
        }
    }
}

// =====================================================================
// weight fp32 -> bf16
// =====================================================================
__global__ void wcvt_kernel(const float* p1, const float* p2, const float* p3,
                            const float* p4, const float* p5, const float* p6,
                            bf16* o)
{
    int i = blockIdx.x * 1024 + threadIdx.x * 4;
    const float* src; int base;
    if      (i < 65536)  { src = p1; base = 0; }
    else if (i < 98304)  { src = p2; base = 65536; }
    else if (i < 147456) { src = p3; base = 98304; }
    else if (i < 163840) { src = p4; base = 147456; }
    else if (i < 229376) { src = p5; base = 163840; }
    else                 { src = p6; base = 229376; }
    float4 v = *(const float4*)(src + (i - base));
    *(__nv_bfloat162*)(o + i)     = __halves2bfloat162(__float2bfloat16(v.x), __float2bfloat16(v.y));
    *(__nv_bfloat162*)(o + i + 2) = __halves2bfloat162(__float2bfloat16(v.z), __float2bfloat16(v.w));
}

// =====================================================================
// Depthwise 3x3 + bias + gated GELU (at instruction floor — unchanged)
// =====================================================================
__global__ void __launch_bounds__(256)
dwgate_kernel(const bf16* __restrict__ a, const float* __restrict__ dw,
              const float* __restrict__ db, bf16* __restrict__ out)
{
    __shared__ float su[34 * 68], sv[34 * 68];
    int blk  = blockIdx.x;
    int tile = blk % 18;
    int cp   = (blk / 18) & 255;
    int b    = blk / (18 * 256);
    int ty0 = (tile / 3) * 32, tx0 = (tile % 3) * 64;
    const bf16* ua = a + ((size_t)b * 512 + cp) * HWC;
    const bf16* va = ua + (size_t)256 * HWC;

    #pragma unroll
    for (int it = 0; it < 5; ++it) {
        int i = threadIdx.x + it * 256;
        if (i < 34 * 34) {
            int ly = i / 34, px = i - ly * 34;
            int gy = ty0 + ly - 1;
            int gx = tx0 - 2 + px * 2;
            float2 uu = make_float2(0.f, 0.f), vv = make_float2(0.f, 0.f);
            if (((unsigned)gy < (unsigned)IMG) && ((unsigned)gx < (unsigned)IMG)) {
                int gi = gy * IMG + gx;
                uu = __bfloat1622float2(*(const __nv_bfloat162*)&ua[gi]);
                vv = __bfloat1622float2(*(const __nv_bfloat162*)&va[gi]);
            }
            *(float2*)&su[ly * 68 + px * 2] = uu;
            *(float2*)&sv[ly * 68 + px * 2] = vv;
        }
    }
    float wu[9], wv[9];
    #pragma unroll
    for (int i = 0; i < 9; ++i) {
        wu[i] = dw[cp * 9 + i];
        wv[i] = dw[(cp + 256) * 9 + i];
    }
    float bu = db[cp], bv = db[cp + 256];
    __syncthreads();

    int y0 = (threadIdx.x >> 4) * 2;
    int x0 = (threadIdx.x & 15) * 4;
    float U[4][8], V[4][8];
    #pragma unroll
    for (int r = 0; r < 4; ++r) {
        *(float4*)&U[r][0] = *(float4*)&su[(y0 + r) * 68 + x0];
        *(float4*)&U[r][4] = *(float4*)&su[(y0 + r) * 68 + x0 + 4];
        *(float4*)&V[r][0] = *(float4*)&sv[(y0 + r) * 68 + x0];
        *(float4*)&V[r][4] = *(float4*)&sv[(y0 + r) * 68 + x0 + 4];
    }

    bf16* ob = out + ((size_t)b * 256 + cp) * HWC;
    #pragma unroll
    for (int dy = 0; dy < 2; ++dy) {
        uint32_t pk[2];
        #pragma unroll
        for (int dp = 0; dp < 2; ++dp) {
            float r2[2];
            #pragma unroll
            for (int h = 0; h < 2; ++h) {
                int dx = dp * 2 + h;
                float u = bu, v = bv;
                #pragma unroll
                for (int i = 0; i < 3; ++i)
                    #pragma unroll
                    for (int j = 0; j < 3; ++j) {
                        u = fmaf(U[dy + i][dx + 1 + j], wu[i * 3 + j], u);
                        v = fmaf(V[dy + i][dx + 1 + j], wv[i * 3 + j], v);
                    }
                r2[h] = u * gelu_erf(v);
            }
            __nv_bfloat162 p2 = __halves2bfloat162(__float2bfloat16(r2[0]),
                                                   __float2bfloat16(r2[1]));
            pk[dp] = *(uint32_t*)&p2;
        }
        *(uint2*)&ob[(ty0 + y0 + dy) * IMG + tx0 + x0] = make_uint2(pk[0], pk[1]);
    }
}

// =====================================================================
// Attention (unchanged)
// =====================================================================
__global__ void __launch_bounds__(64)
attn2_kernel(const bf16* __restrict__ qkv, const float* __restrict__ rpe,
             bf16* __restrict__ aog)
{
    __shared__ float Ks[64 * 36], Vs[64 * 36], rpe_s[225];
    __shared__ int pix[64], lk[64];
    int w = blockIdx.x >> 2, head = blockIdx.x & 3;
    int tid = threadIdx.x;
    int b = w / NWPB, wrem = w - b * NWPB;
    int wy = wrem / NWSIDE, wx = wrem - wy * NWSIDE;
    int qy = tid >> 3, qx = tid & 7;
    {
        int gh = wy * 8 + qy + 4; if (gh >= IMG) gh -= IMG;
        int gw = wx * 8 + qx + 4; if (gw >= IMG) gw -= IMG;
        pix[tid] = gh * IMG + gw;
    }
    {
        int gh = wy * 8 + qy, gw = wx * 8 + qx;
        int lh = gh < 184 ? 0 : (gh < 188 ? 1 : 2);
        int lw = gw < 184 ? 0 : (gw < 188 ? 1 : 2);
        lk[tid] = lh * 3 + lw;
    }
    for (int i = tid; i < 225; i += 64) rpe_s[i] = rpe[i * 4 + head];
    __syncthreads();

    const bf16* qb = qkv + (size_t)b * 384 * HWC + (size_t)(head * 32) * HWC;
    const bf16* kb = qb + (size_t)128 * HWC;
    const bf16* vb = qb + (size_t)256 * HWC;
    int myp = pix[tid];
    float q[32];
    #pragma unroll
    for (int d = 0; d < 32; ++d) {
        q[d] = __bfloat162float(qb[(size_t)d * HWC + myp]) * 0.17677669529663687f;
        Ks[tid * 36 + d] = __bfloat162float(kb[(size_t)d * HWC + myp]);
        Vs[tid * 36 + d] = __bfloat162float(vb[(size_t)d * HWC + myp]);
    }
    int lab = lk[tid];
    __syncthreads();

    float sc[64];
    float mx = -1e30f;
    #pragma unroll
    for (int kk = 0; kk < 64; ++kk) {
        const float4* kp = (const float4*)(Ks + kk * 36);
        float dot = 0.f;
        #pragma unroll
        for (int d4 = 0; d4 < 8; ++d4) {
            float4 kv = kp[d4];
            dot = fmaf(q[d4 * 4 + 0], kv.x, dot);
            dot = fmaf(q[d4 * 4 + 1], kv.y, dot);
            dot = fmaf(q[d4 * 4 + 2], kv.z, dot);
            dot = fmaf(q[d4 * 4 + 3], kv.w, dot);
        }
        int ky = kk >> 3, kx = kk & 7;
        dot += rpe_s[(qy - ky + 7) * 15 + (qx - kx + 7)];
        if (lab != lk[kk]) dot = -1e30f;
        sc[kk] = dot;
        mx = fmaxf(mx, dot);
    }
    float sum = 0.f;
    #pragma unroll
    for (int kk = 0; kk < 64; ++kk) {
        float e = __expf(sc[kk] - mx);
        sc[kk] = e; sum += e;
    }
    float inv = 1.0f / sum;
    float acc[32];
    #pragma unroll
    for (int d = 0; d < 32; ++d) acc[d] = 0.f;
    #pragma unroll
    for (int kk = 0; kk < 64; ++kk) {
        float p = sc[kk];
        const float4* vp = (const float4*)(Vs + kk * 36);
        #pragma unroll
        for (int d4 = 0; d4 < 8; ++d4) {
            float4 vv = vp[d4];
            acc[d4 * 4 + 0] = fmaf(p, vv.x, acc[d4 * 4 + 0]);
            acc[d4 * 4 + 1] = fmaf(p, vv.y, acc[d4 * 4 + 1]);
            acc[d4 * 4 + 2] = fmaf(p, vv.z, acc[d4 * 4 + 2]);
            acc[d4 * 4 + 3] = fmaf(p, vv.w, acc[d4 * 4 + 3]);
        }
    }
    size_t cb = (size_t)b * 128 * HWC + (size_t)(head * 32) * HWC;
    #pragma unroll
    for (int d = 0; d < 32; ++d)
        aog[cb + (size_t)d * HWC + myp] = __float2bfloat16(acc[d] * inv);
}

// =====================================================================
extern "C" void kernel_launch(void* const* d_in, const int* in_sizes, int n_in,
                              void* d_out, int out_size)
{
    const float* x      = (const float*)d_in[0];
    const float* cg_s   = (const float*)d_in[1];
    const float* cg_b   = (const float*)d_in[2];
    const float* pw1_w  = (const float*)d_in[3];
    const float* pw1_b  = (const float*)d_in[4];
    const float* dw_w   = (const float*)d_in[5];
    const float* dw_b   = (const float*)d_in[6];
    const float* pw2_w  = (const float*)d_in[7];
    const float* pw2_b  = (const float*)d_in[8];
    const float* beta   = (const float*)d_in[9];
    const float* at_s   = (const float*)d_in[10];
    const float* at_b   = (const float*)d_in[11];
    const float* qkv_w  = (const float*)d_in[12];
    const float* qkv_b  = (const float*)d_in[13];
    const float* rpe    = (const float*)d_in[14];
    const float* proj_w = (const float*)d_in[15];
    const float* proj_b = (const float*)d_in[16];
    const float* alpha  = (const float*)d_in[17];
    const float* ff_s   = (const float*)d_in[18];
    const float* ff_b   = (const float*)d_in[19];
    const float* fc1_w  = (const float*)d_in[20];
    const float* fc1_b  = (const float*)d_in[21];
    const float* fc2_w  = (const float*)d_in[22];
    const float* fc2_b  = (const float*)d_in[23];
    const float* gamma  = (const float*)d_in[24];
    float* out = (float*)d_out;

    bf16 *wbf, *a512, *g256, *qkvb, *aob, *x1n, *x2n;
    float *x1, *x2;
    cudaGetSymbolAddress((void**)&wbf,  g_wbf);
    cudaGetSymbolAddress((void**)&a512, g_a512);
    cudaGetSymbolAddress((void**)&g256, g_g256);
    cudaGetSymbolAddress((void**)&qkvb, g_qkv);
    cudaGetSymbolAddress((void**)&aob,  g_ao);
    cudaGetSymbolAddress((void**)&x1n,  g_x1n);
    cudaGetSymbolAddress((void**)&x2n,  g_x2n);
    cudaGetSymbolAddress((void**)&x1,   g_x1);
    cudaGetSymbolAddress((void**)&x2,   g_x2);

    cudaFuncSetAttribute(tc_gemm<1, 4, 0, false, true >, cudaFuncAttributeMaxDynamicSharedMemorySize, SMB);
    cudaFuncSetAttribute(tc_gemm<1, 3, 0, false, false>, cudaFuncAttributeMaxDynamicSharedMemorySize, SMB);
    cudaFuncSetAttribute(tc_gemm<2, 1, 2, true , false>, cudaFuncAttributeMaxDynamicSharedMemorySize, SMB);
    cudaFuncSetAttribute(tc_gemm<1, 1, 2, true , false>, cudaFuncAttributeMaxDynamicSharedMemorySize, SMB);
    cudaFuncSetAttribute(tc_gemm<1, 2, 1, false, false>, cudaFuncAttributeMaxDynamicSharedMemorySize, SMB);
    cudaFuncSetAttribute(tc_gemm<2, 1, 2, false, false>, cudaFuncAttributeMaxDynamicSharedMemorySize, SMB);

    const int NPB = 1152;   // (2*HWC)/64

    // ---- prep ----
    wcvt_kernel<<<256, 256>>>(pw1_w, pw2_w, qkv_w, proj_w, fc1_w, fc2_w, wbf);

    // ---- conv gated block (RMS fused into pw1) ----
    tc_gemm<1, 4, 0, false, true><<<NPB, 256, SMB>>>(
        nullptr, wbf + 0, pw1_b, nullptr, nullptr, nullptr, a512, nullptr,
        cg_s, cg_b, x);
    dwgate_kernel<<<2 * 256 * 18, 256>>>(a512, dw_w, dw_b, g256);
    tc_gemm<2, 1, 2, true, false><<<NPB, 256, SMB>>>(
        g256, wbf + 65536, pw2_b, x, beta, x1, nullptr, x1n, at_s, at_b, nullptr);

    // ---- window attention ----
    tc_gemm<1, 3, 0, false, false><<<NPB, 256, SMB>>>(
        x1n, wbf + 98304, qkv_b, nullptr, nullptr, nullptr, qkvb, nullptr,
        nullptr, nullptr, nullptr);
    attn2_kernel<<<NWTOT * 4, 64>>>(qkvb, rpe, aob);
    tc_gemm<1, 1, 2, true, false><<<NPB, 256, SMB>>>(
        aob, wbf + 147456, proj_b, x1, alpha, x2, nullptr, x2n, ff_s, ff_b, nullptr);

    // ---- gated FFN ----
    tc_gemm<1, 2, 1, false, false><<<NPB, 256, SMB>>>(
        x2n, wbf + 163840, fc1_b, nullptr, nullptr, nullptr, g256, nullptr,
        nullptr, nullptr, nullptr);
    tc_gemm<2, 1, 2, false, false><<<NPB, 256, SMB>>>(
        g256, wbf + 229376, fc2_b, x2, gamma, out, nullptr, nullptr,
        nullptr, nullptr, nullptr);
}